// round 2
// baseline (speedup 1.0000x reference)
#include <cuda_runtime.h>
#include <cuda_bf16.h>
#include <math.h>

#define NN 512
#define BB 64
#define NZ 128            // B*2 branch instances
#define H1 128
#define H2 64
#define H3 32
#define OUTD 8
#define CLS 16
#define PDIM 72           // OUT*OUT + OUT
#define CDIM 48           // H3 + CLS

// ---------------- scratch (single static device buffer, no allocs) ----------
// layout (floats):
//   d   : NZ*NN                       = 65,536
//   H1b : NZ*NN*H1                    = 8,388,608
//   H2b : NZ*NN*H2                    = 4,194,304
//   H3b : NZ*NN*H3                    = 2,097,152
//   H4b : NZ*NN*OUTD                  = 524,288
//   Zb  : NZ*NN*H2 (max of Z2/Z3/Z4)  = 4,194,304
//   WBb : NZ*PDIM                     = 9,216
//   CCb : BB*2*NN*OUTD                = 524,288
static const size_t OFF_D   = 0;
static const size_t OFF_H1  = OFF_D   + (size_t)NZ*NN;
static const size_t OFF_H2  = OFF_H1  + (size_t)NZ*NN*H1;
static const size_t OFF_H3  = OFF_H2  + (size_t)NZ*NN*H2;
static const size_t OFF_H4  = OFF_H3  + (size_t)NZ*NN*H3;
static const size_t OFF_Z   = OFF_H4  + (size_t)NZ*NN*OUTD;
static const size_t OFF_WB  = OFF_Z   + (size_t)NZ*NN*H2;
static const size_t OFF_CC  = OFF_WB  + (size_t)NZ*PDIM;
static const size_t TOTAL_SCRATCH = OFF_CC + (size_t)BB*2*NN*OUTD;

__device__ float g_scratch[TOTAL_SCRATCH];

// ---------------- kernel 1: row-sum normalization factors -------------------
// d[z, i] = rsqrt(1 + sum_j adj[b2, i, j]),  z = s*64 + b, b2 = b*2 + s
__global__ void rowsum_kernel(const float* __restrict__ adj, float* __restrict__ dout) {
    int gw   = (blockIdx.x * blockDim.x + threadIdx.x) >> 5;  // global warp = row id
    int lane = threadIdx.x & 31;
    int b2  = gw >> 9;          // 0..127  (b*2+s)
    int row = gw & 511;
    const float* r = adj + (size_t)b2 * NN * NN + (size_t)row * NN;
    float ssum = 0.f;
    #pragma unroll
    for (int k = lane; k < NN; k += 32) ssum += r[k];
    #pragma unroll
    for (int o = 16; o; o >>= 1) ssum += __shfl_xor_sync(0xffffffffu, ssum, o);
    if (lane == 0) {
        int s = b2 & 1, b = b2 >> 1;
        dout[(size_t)(s * BB + b) * NN + row] = rsqrtf(ssum + 1.0f);
    }
}

// ---------------- generic register-tiled SGEMM (plain): C = A @ W -----------
template<int BM, int BN, int BK, int TM, int TN>
__global__ void gemm_plain_kernel(const float* __restrict__ A,
                                  const float* __restrict__ W,
                                  float* __restrict__ C,
                                  int K, int Ncols) {
    __shared__ float As[BK][BM + 1];
    __shared__ float Bs[BK][BN + 1];
    const int NT  = (BM / TM) * (BN / TN);
    const int tx  = threadIdx.x, ty = threadIdx.y;
    const int tid = ty * (BN / TN) + tx;
    const int m0  = blockIdx.x * BM;
    const int n0  = blockIdx.y * BN;
    float acc[TM][TN] = {};
    for (int k0 = 0; k0 < K; k0 += BK) {
        #pragma unroll
        for (int idx = tid; idx < BM * BK; idx += NT) {
            int k = idx % BK, m = idx / BK;
            As[k][m] = A[(size_t)(m0 + m) * K + k0 + k];
        }
        #pragma unroll
        for (int idx = tid; idx < BK * BN; idx += NT) {
            int n = idx % BN, k = idx / BN;
            Bs[k][n] = W[(size_t)(k0 + k) * Ncols + n0 + n];
        }
        __syncthreads();
        #pragma unroll
        for (int kk = 0; kk < BK; kk++) {
            float a[TM], b[TN];
            #pragma unroll
            for (int m = 0; m < TM; m++) a[m] = As[kk][ty * TM + m];
            #pragma unroll
            for (int n = 0; n < TN; n++) b[n] = Bs[kk][tx * TN + n];
            #pragma unroll
            for (int m = 0; m < TM; m++)
                #pragma unroll
                for (int n = 0; n < TN; n++) acc[m][n] += a[m] * b[n];
        }
        __syncthreads();
    }
    #pragma unroll
    for (int m = 0; m < TM; m++) {
        int i = m0 + ty * TM + m;
        #pragma unroll
        for (int n = 0; n < TN; n++) {
            int c = n0 + tx * TN + n;
            C[(size_t)i * Ncols + c] = acc[m][n];
        }
    }
}

// ---------------- GCN layer: H = act(d_i*(adj@(d∘Z)) + d_i^2*Z_i + bias) ----
// adjbase pre-offset by s (per-block stride 2*N*N); Zbase/dbase/Hbase pre-offset by s.
template<int BM, int BN, int BK, int TM, int TN, bool ACT, bool ZSHARED>
__global__ void gcn_layer_kernel(const float* __restrict__ adjbase,
                                 const float* __restrict__ Zbase,
                                 const float* __restrict__ dbase,
                                 const float* __restrict__ bias,
                                 float* __restrict__ Hbase,
                                 int Ncols) {
    const int b = blockIdx.z;
    const float* A  = adjbase + (size_t)b * (2 * NN * NN);
    const float* Zb = ZSHARED ? Zbase : Zbase + (size_t)b * NN * Ncols;
    const float* dz = dbase + (size_t)b * NN;
    float* Hout     = Hbase + (size_t)b * NN * Ncols;

    __shared__ float As[BK][BM + 1];
    __shared__ float Bs[BK][BN + 1];
    const int NT  = (BM / TM) * (BN / TN);
    const int tx  = threadIdx.x, ty = threadIdx.y;
    const int tid = ty * (BN / TN) + tx;
    const int m0  = blockIdx.x * BM;
    const int n0  = blockIdx.y * BN;
    float acc[TM][TN] = {};
    for (int k0 = 0; k0 < NN; k0 += BK) {
        #pragma unroll
        for (int idx = tid; idx < BM * BK; idx += NT) {
            int k = idx % BK, m = idx / BK;
            As[k][m] = A[(size_t)(m0 + m) * NN + k0 + k];
        }
        #pragma unroll
        for (int idx = tid; idx < BK * BN; idx += NT) {
            int n = idx % BN, k = idx / BN;
            Bs[k][n] = Zb[(size_t)(k0 + k) * Ncols + n0 + n] * dz[k0 + k];
        }
        __syncthreads();
        #pragma unroll
        for (int kk = 0; kk < BK; kk++) {
            float a[TM], bf[TN];
            #pragma unroll
            for (int m = 0; m < TM; m++) a[m] = As[kk][ty * TM + m];
            #pragma unroll
            for (int n = 0; n < TN; n++) bf[n] = Bs[kk][tx * TN + n];
            #pragma unroll
            for (int m = 0; m < TM; m++)
                #pragma unroll
                for (int n = 0; n < TN; n++) acc[m][n] += a[m] * bf[n];
        }
        __syncthreads();
    }
    #pragma unroll
    for (int m = 0; m < TM; m++) {
        int i = m0 + ty * TM + m;
        float di = dz[i];
        #pragma unroll
        for (int n = 0; n < TN; n++) {
            int c = n0 + tx * TN + n;
            float zv = Zb[(size_t)i * Ncols + c];
            float v = di * acc[m][n] + di * di * zv + bias[c];
            if (ACT) v = (v >= 0.f) ? v : 0.2f * v;
            Hout[(size_t)i * Ncols + c] = v;
        }
    }
}

// ---------------- dynamic head params: per z compute w(8x8)+b(8) ------------
__global__ void dcl_params_kernel(const int* __restrict__ task,
                                  const float* __restrict__ wc,
                                  const float* __restrict__ H3b,
                                  float* __restrict__ wb) {
    int z = blockIdx.x;             // z = s*64 + b
    int b = z & 63;
    const float* conv3 = H3b + (size_t)z * NN * H3;
    __shared__ float partial[256];
    __shared__ float xc[CDIM];
    int tid = threadIdx.x;
    int col = tid & 31, g = tid >> 5;
    float p = 0.f;
    for (int r = g; r < NN; r += 8) p += conv3[(size_t)r * H3 + col];
    partial[tid] = p;
    __syncthreads();
    if (tid < H3) {
        float sum = 0.f;
        #pragma unroll
        for (int gg = 0; gg < 8; gg++) sum += partial[gg * 32 + tid];
        xc[tid] = sum * (1.0f / (float)NN);
    }
    if (tid >= H3 && tid < CDIM) {
        xc[tid] = (task[b] == tid - H3) ? 1.f : 0.f;
    }
    __syncthreads();
    if (tid < PDIM) {
        float acc = 0.f;
        #pragma unroll
        for (int c = 0; c < CDIM; c++) acc += wc[tid * CDIM + c] * xc[c];
        wb[(size_t)z * PDIM + tid] = acc;
    }
}

// ---------------- cc kernel: logits + interleave scatter --------------------
__global__ void cc_kernel(const float* __restrict__ H4b,
                          const float* __restrict__ wb,
                          float* __restrict__ cc) {
    int z = blockIdx.x;            // z = q*64 + b  (q = branch)
    int q = z >> 6, b = z & 63;
    __shared__ float flat[NN * OUTD];   // conv4[b,q] flattened (4096)
    __shared__ float wm[64];
    __shared__ float bv[8];
    int tid = threadIdx.x;
    const float4* src4 = (const float4*)(H4b + (size_t)z * NN * OUTD);
    float4* dst4 = (float4*)flat;
    for (int i = tid; i < NN * OUTD / 4; i += 256) dst4[i] = src4[i];
    if (tid < 64) wm[tid] = wb[(size_t)z * PDIM + tid];
    if (tid < 8)  bv[tid] = wb[(size_t)z * PDIM + 64 + tid];
    __syncthreads();
    for (int f = tid; f < NN * OUTD; f += 256) {
        int r = f >> 9, c = f & 511;         // logits[r, c]
        float v = bv[r];
        #pragma unroll
        for (int i = 0; i < 8; i++) v += wm[r * 8 + i] * flat[i * NN + c];
        int n = f >> 3, o = f & 7;           // L[n, o]
        int scc = n >> 8;
        int n2 = ((n & 255) << 1) | q;
        cc[(((size_t)(b * 2 + scc) * NN + n2) << 3) + o] = v;
    }
}

// ---------------- final: out = softplus(-(cc @ cc^T)) -----------------------
__global__ void final_kernel(const float* __restrict__ cc, float* __restrict__ out) {
    int zz = blockIdx.z;           // b*2 + scc
    __shared__ float Msm[NN * OUTD];
    int tid = threadIdx.y * 16 + threadIdx.x;
    const float4* src = (const float4*)(cc + (size_t)zz * NN * OUTD);
    float4* dst = (float4*)Msm;
    for (int i = tid; i < NN * OUTD / 4; i += 256) dst[i] = src[i];
    __syncthreads();
    int i0 = blockIdx.y * 64 + threadIdx.y * 4;
    int j0 = blockIdx.x * 64 + threadIdx.x * 4;
    float ai[4][8], aj[4][8];
    #pragma unroll
    for (int m = 0; m < 4; m++)
        #pragma unroll
        for (int o = 0; o < 8; o++) ai[m][o] = Msm[(i0 + m) * 8 + o];
    #pragma unroll
    for (int n = 0; n < 4; n++)
        #pragma unroll
        for (int o = 0; o < 8; o++) aj[n][o] = Msm[(j0 + n) * 8 + o];
    float* ob = out + (size_t)zz * NN * NN;
    #pragma unroll
    for (int m = 0; m < 4; m++) {
        float r[4];
        #pragma unroll
        for (int n = 0; n < 4; n++) {
            float x = 0.f;
            #pragma unroll
            for (int o = 0; o < 8; o++) x += ai[m][o] * aj[n][o];
            // softplus(-x) = -log_sigmoid(x)
            r[n] = log1pf(expf(-fabsf(x))) + fmaxf(-x, 0.f);
        }
        *(float4*)(ob + (size_t)(i0 + m) * NN + j0) = make_float4(r[0], r[1], r[2], r[3]);
    }
}

// ---------------- host orchestration ----------------------------------------
extern "C" void kernel_launch(void* const* d_in, const int* in_sizes, int n_in,
                              void* d_out, int out_size) {
    const float* adj  = (const float*)d_in[0];
    const int*   task = (const int*)d_in[1];
    const float* w[2][4];
    const float* bia[2][4];
    int idx = 2;
    for (int s = 0; s < 2; s++)
        for (int l = 0; l < 4; l++) {
            w[s][l]   = (const float*)d_in[idx++];
            bia[s][l] = (const float*)d_in[idx++];
        }
    const float* wc = (const float*)d_in[18];
    float* out = (float*)d_out;

    float* base = nullptr;
    cudaGetSymbolAddress((void**)&base, g_scratch);
    float* p_d  = base + OFF_D;
    float* p_H1 = base + OFF_H1;
    float* p_H2 = base + OFF_H2;
    float* p_H3 = base + OFF_H3;
    float* p_H4 = base + OFF_H4;
    float* p_Z  = base + OFF_Z;
    float* p_WB = base + OFF_WB;
    float* p_CC = base + OFF_CC;

    const size_t DH  = (size_t)BB * NN;          // per-s stride of d
    const size_t S1  = (size_t)BB * NN * H1;     // per-s stride of H1
    const size_t S2  = (size_t)BB * NN * H2;
    const size_t S3  = (size_t)BB * NN * H3;
    const size_t S4  = (size_t)BB * NN * OUTD;

    // 1) degree factors
    rowsum_kernel<<<NZ * NN / 8, 256>>>(adj, p_d);

    // 2) layer 1 (Z = W1, shared across batch)
    for (int s = 0; s < 2; s++) {
        gcn_layer_kernel<64, 64, 32, 4, 4, true, true>
            <<<dim3(8, 2, BB), dim3(16, 16)>>>(
                adj + (size_t)s * NN * NN, w[s][0], p_d + s * DH,
                bia[s][0], p_H1 + s * S1, H1);
    }
    // 3) layer 2
    for (int s = 0; s < 2; s++)
        gemm_plain_kernel<64, 64, 32, 4, 4>
            <<<dim3(BB * NN / 64, 1), dim3(16, 16)>>>(
                p_H1 + s * S1, w[s][1], p_Z + s * S2, H1, H2);
    for (int s = 0; s < 2; s++)
        gcn_layer_kernel<64, 64, 32, 4, 4, true, false>
            <<<dim3(8, 1, BB), dim3(16, 16)>>>(
                adj + (size_t)s * NN * NN, p_Z + s * S2, p_d + s * DH,
                bia[s][1], p_H2 + s * S2, H2);
    // 4) layer 3
    for (int s = 0; s < 2; s++)
        gemm_plain_kernel<64, 32, 32, 4, 4>
            <<<dim3(BB * NN / 64, 1), dim3(8, 16)>>>(
                p_H2 + s * S2, w[s][2], p_Z + s * S3, H2, H3);
    for (int s = 0; s < 2; s++)
        gcn_layer_kernel<64, 32, 32, 4, 4, true, false>
            <<<dim3(8, 1, BB), dim3(8, 16)>>>(
                adj + (size_t)s * NN * NN, p_Z + s * S3, p_d + s * DH,
                bia[s][2], p_H3 + s * S3, H3);
    // 5) layer 4 (no activation) -> conv4
    for (int s = 0; s < 2; s++)
        gemm_plain_kernel<64, 8, 32, 4, 2>
            <<<dim3(BB * NN / 64, 1), dim3(4, 16)>>>(
                p_H3 + s * S3, w[s][3], p_Z + s * S4, H3, OUTD);
    for (int s = 0; s < 2; s++)
        gcn_layer_kernel<64, 8, 32, 4, 2, false, false>
            <<<dim3(8, 1, BB), dim3(4, 16)>>>(
                adj + (size_t)s * NN * NN, p_Z + s * S4, p_d + s * DH,
                bia[s][3], p_H4 + s * S4, OUTD);

    // 6) dynamic head params (uses conv3 = H3)
    dcl_params_kernel<<<NZ, 256>>>(task, wc, p_H3, p_WB);

    // 7) logits + interleave into cc
    cc_kernel<<<NZ, 256>>>(p_H4, p_WB, p_CC);

    // 8) final gram + softplus
    final_kernel<<<dim3(8, 8, NZ), dim3(16, 16)>>>(p_CC, out);

    (void)in_sizes; (void)n_in; (void)out_size;
}

// round 3
// speedup vs baseline: 2.1452x; 2.1452x over previous
#include <cuda_runtime.h>
#include <cuda_bf16.h>
#include <math.h>
#include <stdint.h>

#define NN 512
#define BB 64
#define NZ 128            // B*2 branch instances
#define H1 128
#define H2 64
#define H3 32
#define OUTD 8
#define CLS 16
#define PDIM 72           // OUT*OUT + OUT
#define CDIM 48           // H3 + CLS

// ---------------- scratch (single static device buffer, no allocs) ----------
static const size_t OFF_D   = 0;
static const size_t OFF_H1  = OFF_D   + (size_t)NZ*NN;
static const size_t OFF_H2  = OFF_H1  + (size_t)NZ*NN*H1;
static const size_t OFF_H3  = OFF_H2  + (size_t)NZ*NN*H2;
static const size_t OFF_H4  = OFF_H3  + (size_t)NZ*NN*H3;
static const size_t OFF_Z   = OFF_H4  + (size_t)NZ*NN*OUTD;
static const size_t OFF_WB  = OFF_Z   + (size_t)NZ*NN*H2;
static const size_t OFF_CC  = OFF_WB  + (size_t)NZ*PDIM;
static const size_t TOTAL_SCRATCH = OFF_CC + (size_t)BB*2*NN*OUTD;

__device__ float g_scratch[TOTAL_SCRATCH];

// ---------------- kernel 1: row-sum normalization factors -------------------
__global__ void rowsum_kernel(const float* __restrict__ adj, float* __restrict__ dout) {
    int gw   = (blockIdx.x * blockDim.x + threadIdx.x) >> 5;
    int lane = threadIdx.x & 31;
    int b2  = gw >> 9;
    int row = gw & 511;
    const float* r = adj + (size_t)b2 * NN * NN + (size_t)row * NN;
    float ssum = 0.f;
    #pragma unroll
    for (int k = lane; k < NN; k += 32) ssum += r[k];
    #pragma unroll
    for (int o = 16; o; o >>= 1) ssum += __shfl_xor_sync(0xffffffffu, ssum, o);
    if (lane == 0) {
        int s = b2 & 1, b = b2 >> 1;
        dout[(size_t)(s * BB + b) * NN + row] = rsqrtf(ssum + 1.0f);
    }
}

// ---------------- tf32 split helpers -----------------------------------------
__device__ __forceinline__ void split_tf32(float v, float& hi, float& lo) {
    uint32_t u;
    asm("cvt.rna.tf32.f32 %0, %1;" : "=r"(u) : "f"(v));
    hi = __uint_as_float(u);
    float r = v - hi;
    uint32_t u2;
    asm("cvt.rna.tf32.f32 %0, %1;" : "=r"(u2) : "f"(r));
    lo = __uint_as_float(u2);
}
__device__ __forceinline__ void split4(float4 v, float4& h, float4& l) {
    split_tf32(v.x, h.x, l.x);
    split_tf32(v.y, h.y, l.y);
    split_tf32(v.z, h.z, l.z);
    split_tf32(v.w, h.w, l.w);
}
__device__ __forceinline__ void mma_tf32(float c[4],
    uint32_t a0, uint32_t a1, uint32_t a2, uint32_t a3,
    uint32_t b0, uint32_t b1) {
    asm volatile(
        "mma.sync.aligned.m16n8k8.row.col.f32.tf32.tf32.f32 "
        "{%0,%1,%2,%3}, {%4,%5,%6,%7}, {%8,%9}, {%0,%1,%2,%3};"
        : "+f"(c[0]), "+f"(c[1]), "+f"(c[2]), "+f"(c[3])
        : "r"(a0), "r"(a1), "r"(a2), "r"(a3), "r"(b0), "r"(b1));
}

// ---------------- unified split-TF32 MMA GEMM --------------------------------
// GCN=true : per-instance z: C = epi(adj_z @ (d∘Z_z)), epilogue adds d_i^2*Z + bias (+leaky)
// GCN=false: flat C = A @ W
template<int BM, int BN, int BK, int WGM, int WGN, bool GCN, bool ACT, bool ZSHARED>
__global__ void __launch_bounds__(WGM*WGN*32)
mma_gemm_kernel(const float* __restrict__ Abase,
                const float* __restrict__ Bbase,
                const float* __restrict__ dbase,
                const float* __restrict__ bias,
                float* __restrict__ Cbase,
                int K, int Ncols)
{
    constexpr int WM = BM / WGM, WN = BN / WGN;
    constexpr int MT = WM / 16, NT = WN / 8;
    constexpr int NTHREADS = WGM * WGN * 32;
    constexpr int BKP = BK + 4;     // A smem stride (bank-safe: (4g+tig) distinct)
    constexpr int BNP = BN + 8;     // B smem stride (bank-safe: (8tig+g) distinct)

    __shared__ float Ah[BM][BKP], Al[BM][BKP];
    __shared__ float Bh[BK][BNP], Bl[BK][BNP];

    const int z  = blockIdx.z;
    const int m0 = blockIdx.x * BM;
    const int n0 = blockIdx.y * BN;

    const float* A; const float* B; float* C; const float* dz = nullptr;
    int lda;
    if (GCN) {
        A   = Abase + (size_t)z * (2 * NN * NN);
        lda = NN;
        B   = ZSHARED ? Bbase : Bbase + (size_t)z * NN * Ncols;
        C   = Cbase + (size_t)z * NN * Ncols;
        dz  = dbase + (size_t)z * NN;
    } else {
        A = Abase; lda = K; B = Bbase; C = Cbase;
    }

    const int tid  = threadIdx.x;
    const int w    = tid >> 5, lane = tid & 31;
    const int g    = lane >> 2, tig = lane & 3;
    const int wm   = (w / WGN) * WM;
    const int wn   = (w % WGN) * WN;

    float acc[MT][NT][4] = {};

    constexpr int A_TOT = BM * BK / 4;   // float4 count
    constexpr int B_TOT = BK * BN / 4;

    for (int k0 = 0; k0 < K; k0 += BK) {
        #pragma unroll
        for (int idx = tid; idx < A_TOT; idx += NTHREADS) {
            int r  = idx / (BK / 4);
            int c4 = (idx % (BK / 4)) * 4;
            float4 v = *(const float4*)&A[(size_t)(m0 + r) * lda + k0 + c4];
            float4 h, l; split4(v, h, l);
            *(float4*)&Ah[r][c4] = h;
            *(float4*)&Al[r][c4] = l;
        }
        #pragma unroll
        for (int idx = tid; idx < B_TOT; idx += NTHREADS) {
            int r  = idx / (BN / 4);
            int c4 = (idx % (BN / 4)) * 4;
            float4 v = *(const float4*)&B[(size_t)(k0 + r) * Ncols + n0 + c4];
            if (GCN) { float dk = dz[k0 + r]; v.x *= dk; v.y *= dk; v.z *= dk; v.w *= dk; }
            float4 h, l; split4(v, h, l);
            *(float4*)&Bh[r][c4] = h;
            *(float4*)&Bl[r][c4] = l;
        }
        __syncthreads();

        #pragma unroll
        for (int kk = 0; kk < BK; kk += 8) {
            uint32_t ah[MT][4], al[MT][4], bh[NT][2], bl[NT][2];
            #pragma unroll
            for (int mt = 0; mt < MT; mt++) {
                int rb = wm + mt * 16;
                ah[mt][0] = __float_as_uint(Ah[rb + g    ][kk + tig    ]);
                ah[mt][1] = __float_as_uint(Ah[rb + g + 8][kk + tig    ]);
                ah[mt][2] = __float_as_uint(Ah[rb + g    ][kk + tig + 4]);
                ah[mt][3] = __float_as_uint(Ah[rb + g + 8][kk + tig + 4]);
                al[mt][0] = __float_as_uint(Al[rb + g    ][kk + tig    ]);
                al[mt][1] = __float_as_uint(Al[rb + g + 8][kk + tig    ]);
                al[mt][2] = __float_as_uint(Al[rb + g    ][kk + tig + 4]);
                al[mt][3] = __float_as_uint(Al[rb + g + 8][kk + tig + 4]);
            }
            #pragma unroll
            for (int nt = 0; nt < NT; nt++) {
                int cb = wn + nt * 8 + g;
                bh[nt][0] = __float_as_uint(Bh[kk + tig    ][cb]);
                bh[nt][1] = __float_as_uint(Bh[kk + tig + 4][cb]);
                bl[nt][0] = __float_as_uint(Bl[kk + tig    ][cb]);
                bl[nt][1] = __float_as_uint(Bl[kk + tig + 4][cb]);
            }
            #pragma unroll
            for (int mt = 0; mt < MT; mt++)
                #pragma unroll
                for (int nt = 0; nt < NT; nt++) {
                    mma_tf32(acc[mt][nt], ah[mt][0], ah[mt][1], ah[mt][2], ah[mt][3],
                             bh[nt][0], bh[nt][1]);                       // hi*hi
                    mma_tf32(acc[mt][nt], ah[mt][0], ah[mt][1], ah[mt][2], ah[mt][3],
                             bl[nt][0], bl[nt][1]);                       // hi*lo
                    mma_tf32(acc[mt][nt], al[mt][0], al[mt][1], al[mt][2], al[mt][3],
                             bh[nt][0], bh[nt][1]);                       // lo*hi
                }
        }
        __syncthreads();
    }

    // epilogue
    #pragma unroll
    for (int mt = 0; mt < MT; mt++) {
        int r0 = m0 + wm + mt * 16 + g;
        int r1 = r0 + 8;
        float d0 = 0.f, d1 = 0.f;
        if (GCN) { d0 = dz[r0]; d1 = dz[r1]; }
        #pragma unroll
        for (int nt = 0; nt < NT; nt++) {
            int c = n0 + wn + nt * 8 + tig * 2;
            float v00 = acc[mt][nt][0], v01 = acc[mt][nt][1];
            float v10 = acc[mt][nt][2], v11 = acc[mt][nt][3];
            if (GCN) {
                float2 z0 = *(const float2*)&B[(size_t)r0 * Ncols + c];
                float2 z1 = *(const float2*)&B[(size_t)r1 * Ncols + c];
                float bc0 = bias[c], bc1 = bias[c + 1];
                v00 = d0 * v00 + d0 * d0 * z0.x + bc0;
                v01 = d0 * v01 + d0 * d0 * z0.y + bc1;
                v10 = d1 * v10 + d1 * d1 * z1.x + bc0;
                v11 = d1 * v11 + d1 * d1 * z1.y + bc1;
                if (ACT) {
                    v00 = (v00 >= 0.f) ? v00 : 0.2f * v00;
                    v01 = (v01 >= 0.f) ? v01 : 0.2f * v01;
                    v10 = (v10 >= 0.f) ? v10 : 0.2f * v10;
                    v11 = (v11 >= 0.f) ? v11 : 0.2f * v11;
                }
            }
            *(float2*)&C[(size_t)r0 * Ncols + c] = make_float2(v00, v01);
            *(float2*)&C[(size_t)r1 * Ncols + c] = make_float2(v10, v11);
        }
    }
}

// ---------------- fp32 kernels kept for layer 4 (N=8) ------------------------
template<int BM, int BN, int BK, int TM, int TN>
__global__ void gemm_plain_kernel(const float* __restrict__ A,
                                  const float* __restrict__ W,
                                  float* __restrict__ C,
                                  int K, int Ncols) {
    __shared__ float As[BK][BM + 1];
    __shared__ float Bs[BK][BN + 1];
    const int NT  = (BM / TM) * (BN / TN);
    const int tx  = threadIdx.x, ty = threadIdx.y;
    const int tid = ty * (BN / TN) + tx;
    const int m0  = blockIdx.x * BM;
    const int n0  = blockIdx.y * BN;
    float acc[TM][TN] = {};
    for (int k0 = 0; k0 < K; k0 += BK) {
        #pragma unroll
        for (int idx = tid; idx < BM * BK; idx += NT) {
            int k = idx % BK, m = idx / BK;
            As[k][m] = A[(size_t)(m0 + m) * K + k0 + k];
        }
        #pragma unroll
        for (int idx = tid; idx < BK * BN; idx += NT) {
            int n = idx % BN, k = idx / BN;
            Bs[k][n] = W[(size_t)(k0 + k) * Ncols + n0 + n];
        }
        __syncthreads();
        #pragma unroll
        for (int kk = 0; kk < BK; kk++) {
            float a[TM], b[TN];
            #pragma unroll
            for (int m = 0; m < TM; m++) a[m] = As[kk][ty * TM + m];
            #pragma unroll
            for (int n = 0; n < TN; n++) b[n] = Bs[kk][tx * TN + n];
            #pragma unroll
            for (int m = 0; m < TM; m++)
                #pragma unroll
                for (int n = 0; n < TN; n++) acc[m][n] += a[m] * b[n];
        }
        __syncthreads();
    }
    #pragma unroll
    for (int m = 0; m < TM; m++) {
        int i = m0 + ty * TM + m;
        #pragma unroll
        for (int n = 0; n < TN; n++) {
            int c = n0 + tx * TN + n;
            C[(size_t)i * Ncols + c] = acc[m][n];
        }
    }
}

template<int BM, int BN, int BK, int TM, int TN, bool ACT, bool ZSHARED>
__global__ void gcn_layer_kernel(const float* __restrict__ adjbase,
                                 const float* __restrict__ Zbase,
                                 const float* __restrict__ dbase,
                                 const float* __restrict__ bias,
                                 float* __restrict__ Hbase,
                                 int Ncols) {
    const int b = blockIdx.z;
    const float* A  = adjbase + (size_t)b * (2 * NN * NN);
    const float* Zb = ZSHARED ? Zbase : Zbase + (size_t)b * NN * Ncols;
    const float* dz = dbase + (size_t)b * NN;
    float* Hout     = Hbase + (size_t)b * NN * Ncols;

    __shared__ float As[BK][BM + 1];
    __shared__ float Bs[BK][BN + 1];
    const int NT  = (BM / TM) * (BN / TN);
    const int tx  = threadIdx.x, ty = threadIdx.y;
    const int tid = ty * (BN / TN) + tx;
    const int m0  = blockIdx.x * BM;
    const int n0  = blockIdx.y * BN;
    float acc[TM][TN] = {};
    for (int k0 = 0; k0 < NN; k0 += BK) {
        #pragma unroll
        for (int idx = tid; idx < BM * BK; idx += NT) {
            int k = idx % BK, m = idx / BK;
            As[k][m] = A[(size_t)(m0 + m) * NN + k0 + k];
        }
        #pragma unroll
        for (int idx = tid; idx < BK * BN; idx += NT) {
            int n = idx % BN, k = idx / BN;
            Bs[k][n] = Zb[(size_t)(k0 + k) * Ncols + n0 + n] * dz[k0 + k];
        }
        __syncthreads();
        #pragma unroll
        for (int kk = 0; kk < BK; kk++) {
            float a[TM], bf[TN];
            #pragma unroll
            for (int m = 0; m < TM; m++) a[m] = As[kk][ty * TM + m];
            #pragma unroll
            for (int n = 0; n < TN; n++) bf[n] = Bs[kk][tx * TN + n];
            #pragma unroll
            for (int m = 0; m < TM; m++)
                #pragma unroll
                for (int n = 0; n < TN; n++) acc[m][n] += a[m] * bf[n];
        }
        __syncthreads();
    }
    #pragma unroll
    for (int m = 0; m < TM; m++) {
        int i = m0 + ty * TM + m;
        float di = dz[i];
        #pragma unroll
        for (int n = 0; n < TN; n++) {
            int c = n0 + tx * TN + n;
            float zv = Zb[(size_t)i * Ncols + c];
            float v = di * acc[m][n] + di * di * zv + bias[c];
            if (ACT) v = (v >= 0.f) ? v : 0.2f * v;
            Hout[(size_t)i * Ncols + c] = v;
        }
    }
}

// ---------------- dynamic head params ---------------------------------------
__global__ void dcl_params_kernel(const int* __restrict__ task,
                                  const float* __restrict__ wc,
                                  const float* __restrict__ H3b,
                                  float* __restrict__ wb) {
    int z = blockIdx.x;
    int b = z & 63;
    const float* conv3 = H3b + (size_t)z * NN * H3;
    __shared__ float partial[256];
    __shared__ float xc[CDIM];
    int tid = threadIdx.x;
    int col = tid & 31, g = tid >> 5;
    float p = 0.f;
    for (int r = g; r < NN; r += 8) p += conv3[(size_t)r * H3 + col];
    partial[tid] = p;
    __syncthreads();
    if (tid < H3) {
        float sum = 0.f;
        #pragma unroll
        for (int gg = 0; gg < 8; gg++) sum += partial[gg * 32 + tid];
        xc[tid] = sum * (1.0f / (float)NN);
    }
    if (tid >= H3 && tid < CDIM) {
        xc[tid] = (task[b] == tid - H3) ? 1.f : 0.f;
    }
    __syncthreads();
    if (tid < PDIM) {
        float acc = 0.f;
        #pragma unroll
        for (int c = 0; c < CDIM; c++) acc += wc[tid * CDIM + c] * xc[c];
        wb[(size_t)z * PDIM + tid] = acc;
    }
}

// ---------------- cc kernel: logits + interleave scatter --------------------
__global__ void cc_kernel(const float* __restrict__ H4b,
                          const float* __restrict__ wb,
                          float* __restrict__ cc) {
    int z = blockIdx.x;
    int q = z >> 6, b = z & 63;
    __shared__ float flat[NN * OUTD];
    __shared__ float wm[64];
    __shared__ float bv[8];
    int tid = threadIdx.x;
    const float4* src4 = (const float4*)(H4b + (size_t)z * NN * OUTD);
    float4* dst4 = (float4*)flat;
    for (int i = tid; i < NN * OUTD / 4; i += 256) dst4[i] = src4[i];
    if (tid < 64) wm[tid] = wb[(size_t)z * PDIM + tid];
    if (tid < 8)  bv[tid] = wb[(size_t)z * PDIM + 64 + tid];
    __syncthreads();
    for (int f = tid; f < NN * OUTD; f += 256) {
        int r = f >> 9, c = f & 511;
        float v = bv[r];
        #pragma unroll
        for (int i = 0; i < 8; i++) v += wm[r * 8 + i] * flat[i * NN + c];
        int n = f >> 3, o = f & 7;
        int scc = n >> 8;
        int n2 = ((n & 255) << 1) | q;
        cc[(((size_t)(b * 2 + scc) * NN + n2) << 3) + o] = v;
    }
}

// ---------------- final: out = softplus(-(cc @ cc^T)) -----------------------
__global__ void final_kernel(const float* __restrict__ cc, float* __restrict__ out) {
    int zz = blockIdx.z;
    __shared__ float Msm[NN * OUTD];
    int tid = threadIdx.y * 16 + threadIdx.x;
    const float4* src = (const float4*)(cc + (size_t)zz * NN * OUTD);
    float4* dst = (float4*)Msm;
    for (int i = tid; i < NN * OUTD / 4; i += 256) dst[i] = src[i];
    __syncthreads();
    int i0 = blockIdx.y * 64 + threadIdx.y * 4;
    int j0 = blockIdx.x * 64 + threadIdx.x * 4;
    float ai[4][8], aj[4][8];
    #pragma unroll
    for (int m = 0; m < 4; m++)
        #pragma unroll
        for (int o = 0; o < 8; o++) ai[m][o] = Msm[(i0 + m) * 8 + o];
    #pragma unroll
    for (int n = 0; n < 4; n++)
        #pragma unroll
        for (int o = 0; o < 8; o++) aj[n][o] = Msm[(j0 + n) * 8 + o];
    float* ob = out + (size_t)zz * NN * NN;
    #pragma unroll
    for (int m = 0; m < 4; m++) {
        float r[4];
        #pragma unroll
        for (int n = 0; n < 4; n++) {
            float x = 0.f;
            #pragma unroll
            for (int o = 0; o < 8; o++) x += ai[m][o] * aj[n][o];
            r[n] = log1pf(expf(-fabsf(x))) + fmaxf(-x, 0.f);
        }
        *(float4*)(ob + (size_t)(i0 + m) * NN + j0) = make_float4(r[0], r[1], r[2], r[3]);
    }
}

// ---------------- host orchestration ----------------------------------------
extern "C" void kernel_launch(void* const* d_in, const int* in_sizes, int n_in,
                              void* d_out, int out_size) {
    const float* adj  = (const float*)d_in[0];
    const int*   task = (const int*)d_in[1];
    const float* w[2][4];
    const float* bia[2][4];
    int idx = 2;
    for (int s = 0; s < 2; s++)
        for (int l = 0; l < 4; l++) {
            w[s][l]   = (const float*)d_in[idx++];
            bia[s][l] = (const float*)d_in[idx++];
        }
    const float* wc = (const float*)d_in[18];
    float* out = (float*)d_out;

    float* base = nullptr;
    cudaGetSymbolAddress((void**)&base, g_scratch);
    float* p_d  = base + OFF_D;
    float* p_H1 = base + OFF_H1;
    float* p_H2 = base + OFF_H2;
    float* p_H3 = base + OFF_H3;
    float* p_H4 = base + OFF_H4;
    float* p_Z  = base + OFF_Z;
    float* p_WB = base + OFF_WB;
    float* p_CC = base + OFF_CC;

    const size_t DH  = (size_t)BB * NN;
    const size_t S1  = (size_t)BB * NN * H1;
    const size_t S2  = (size_t)BB * NN * H2;
    const size_t S3  = (size_t)BB * NN * H3;
    const size_t S4  = (size_t)BB * NN * OUTD;

    // 1) degree factors
    rowsum_kernel<<<NZ * NN / 8, 256>>>(adj, p_d);

    // 2) layer 1: H1 = leaky(feat @ w1 + b1)   (Z = w1, shared)
    for (int s = 0; s < 2; s++)
        mma_gemm_kernel<64, 64, 32, 2, 2, true, true, true>
            <<<dim3(8, 2, BB), 128>>>(
                adj + (size_t)s * NN * NN, w[s][0], p_d + s * DH,
                bia[s][0], p_H1 + s * S1, NN, H1);

    // 3) layer 2: Z = H1 @ w2 ; H2 = leaky(feat @ Z + b2)
    for (int s = 0; s < 2; s++)
        mma_gemm_kernel<64, 64, 32, 2, 2, false, false, false>
            <<<dim3(BB * NN / 64, 1, 1), 128>>>(
                p_H1 + s * S1, w[s][1], nullptr, nullptr, p_Z + s * S2, H1, H2);
    for (int s = 0; s < 2; s++)
        mma_gemm_kernel<64, 64, 32, 2, 2, true, true, false>
            <<<dim3(8, 1, BB), 128>>>(
                adj + (size_t)s * NN * NN, p_Z + s * S2, p_d + s * DH,
                bia[s][1], p_H2 + s * S2, NN, H2);

    // 4) layer 3: Z = H2 @ w3 ; H3 = leaky(feat @ Z + b3)
    for (int s = 0; s < 2; s++)
        mma_gemm_kernel<64, 32, 32, 4, 1, false, false, false>
            <<<dim3(BB * NN / 64, 1, 1), 128>>>(
                p_H2 + s * S2, w[s][2], nullptr, nullptr, p_Z + s * S3, H2, H3);
    for (int s = 0; s < 2; s++)
        mma_gemm_kernel<64, 32, 32, 4, 1, true, true, false>
            <<<dim3(8, 1, BB), 128>>>(
                adj + (size_t)s * NN * NN, p_Z + s * S3, p_d + s * DH,
                bia[s][2], p_H3 + s * S3, NN, H3);

    // 5) layer 4 (N=8, fp32): Z = H3 @ w4 ; H4 = feat @ Z + b4 (no act)
    for (int s = 0; s < 2; s++)
        gemm_plain_kernel<64, 8, 32, 4, 2>
            <<<dim3(BB * NN / 64, 1), dim3(4, 16)>>>(
                p_H3 + s * S3, w[s][3], p_Z + s * S4, H3, OUTD);
    for (int s = 0; s < 2; s++)
        gcn_layer_kernel<64, 8, 32, 4, 2, false, false>
            <<<dim3(8, 1, BB), dim3(4, 16)>>>(
                adj + (size_t)s * NN * NN, p_Z + s * S4, p_d + s * DH,
                bia[s][3], p_H4 + s * S4, OUTD);

    // 6) dynamic head params (uses conv3 = H3)
    dcl_params_kernel<<<NZ, 256>>>(task, wc, p_H3, p_WB);

    // 7) logits + interleave into cc
    cc_kernel<<<NZ, 256>>>(p_H4, p_WB, p_CC);

    // 8) final gram + softplus
    final_kernel<<<dim3(8, 8, NZ), dim3(16, 16)>>>(p_CC, out);

    (void)in_sizes; (void)n_in; (void)out_size;
}

// round 4
// speedup vs baseline: 3.0696x; 1.4309x over previous
#include <cuda_runtime.h>
#include <cuda_bf16.h>
#include <math.h>
#include <stdint.h>

#define NN 512
#define BB 64
#define NZ 128            // B*2 branch instances
#define H1 128
#define H2 64
#define H3 32
#define OUTD 8
#define CLS 16
#define PDIM 72           // OUT*OUT + OUT
#define CDIM 48           // H3 + CLS

// ---------------- scratch (single static device buffer, no allocs) ----------
static const size_t OFF_D   = 0;
static const size_t OFF_H1  = OFF_D   + (size_t)NZ*NN;
static const size_t OFF_H2  = OFF_H1  + (size_t)NZ*NN*H1;
static const size_t OFF_H3  = OFF_H2  + (size_t)NZ*NN*H2;
static const size_t OFF_H4  = OFF_H3  + (size_t)NZ*NN*H3;
static const size_t OFF_Z   = OFF_H4  + (size_t)NZ*NN*OUTD;
static const size_t OFF_WB  = OFF_Z   + (size_t)NZ*NN*H2;
static const size_t OFF_CC  = OFF_WB  + (size_t)NZ*PDIM;
static const size_t TOTAL_SCRATCH = OFF_CC + (size_t)BB*2*NN*OUTD;

__device__ float g_scratch[TOTAL_SCRATCH];

// ---------------- kernel 1: row-sum normalization factors -------------------
__global__ void rowsum_kernel(const float* __restrict__ adj, float* __restrict__ dout) {
    int gw   = (blockIdx.x * blockDim.x + threadIdx.x) >> 5;
    int lane = threadIdx.x & 31;
    int b2  = gw >> 9;
    int row = gw & 511;
    const float* r = adj + (size_t)b2 * NN * NN + (size_t)row * NN;
    float ssum = 0.f;
    #pragma unroll
    for (int k = lane; k < NN; k += 32) ssum += r[k];
    #pragma unroll
    for (int o = 16; o; o >>= 1) ssum += __shfl_xor_sync(0xffffffffu, ssum, o);
    if (lane == 0) {
        int s = b2 & 1, b = b2 >> 1;
        dout[(size_t)(s * BB + b) * NN + row] = rsqrtf(ssum + 1.0f);
    }
}

// ---------------- tf32 split helpers -----------------------------------------
__device__ __forceinline__ void split_tf32(float v, float& hi, float& lo) {
    uint32_t u;
    asm("cvt.rna.tf32.f32 %0, %1;" : "=r"(u) : "f"(v));
    hi = __uint_as_float(u);
    float r = v - hi;
    uint32_t u2;
    asm("cvt.rna.tf32.f32 %0, %1;" : "=r"(u2) : "f"(r));
    lo = __uint_as_float(u2);
}
__device__ __forceinline__ void split4(float4 v, float4& h, float4& l) {
    split_tf32(v.x, h.x, l.x);
    split_tf32(v.y, h.y, l.y);
    split_tf32(v.z, h.z, l.z);
    split_tf32(v.w, h.w, l.w);
}
__device__ __forceinline__ void mma_tf32(float c[4],
    uint32_t a0, uint32_t a1, uint32_t a2, uint32_t a3,
    uint32_t b0, uint32_t b1) {
    asm volatile(
        "mma.sync.aligned.m16n8k8.row.col.f32.tf32.tf32.f32 "
        "{%0,%1,%2,%3}, {%4,%5,%6,%7}, {%8,%9}, {%0,%1,%2,%3};"
        : "+f"(c[0]), "+f"(c[1]), "+f"(c[2]), "+f"(c[3])
        : "r"(a0), "r"(a1), "r"(a2), "r"(a3), "r"(b0), "r"(b1));
}

// ---------------- unified split-TF32 MMA GEMM (256 thr, reg-prefetch) --------
// GCN=true : blockIdx.z = z in [0,128): s=z>>6, b=z&63
//            C_z = epi(adj_{b,s} @ (d_z ∘ Z_z)); epilogue adds d_i^2*Z + bias (+leaky)
//            ZSHARED: Z = weight matrix shared across batch (B0/B1 per s)
// GCN=false: blockIdx.z = s in {0,1}: C = A_s @ W_s (flat rows)
template<int BM, int BN, int BK, int WGM, int WGN, bool GCN, bool ACT, bool ZSHARED>
__global__ void __launch_bounds__(WGM*WGN*32)
mma_gemm_kernel(const float* __restrict__ Abase,
                const float* __restrict__ B0,
                const float* __restrict__ B1,
                const float* __restrict__ dbase,
                const float* __restrict__ bias0,
                const float* __restrict__ bias1,
                float* __restrict__ Cbase,
                int K, int Ncols, size_t sA, size_t sC)
{
    constexpr int WM = BM / WGM, WN = BN / WGN;
    constexpr int MT = WM / 16, NT = WN / 8;
    constexpr int NTHREADS = WGM * WGN * 32;
    constexpr int BKP = BK + 4;
    constexpr int BNP = BN + 8;
    constexpr int A_LD4 = BM * BK / 4 / NTHREADS;
    constexpr int B_LD4 = BK * BN / 4 / NTHREADS;
    static_assert(BM * BK / 4 % NTHREADS == 0, "A load divisibility");
    static_assert(BK * BN / 4 % NTHREADS == 0, "B load divisibility");

    __shared__ float Ah[BM][BKP], Al[BM][BKP];
    __shared__ float Bh[BK][BNP], Bl[BK][BNP];

    const int z = blockIdx.z;
    const float* A; const float* B; const float* bias = nullptr;
    const float* dz = nullptr; float* C;
    int lda;
    if (GCN) {
        int s = z >> 6, b = z & 63;
        A   = Abase + (size_t)(b * 2 + s) * NN * NN; lda = NN;
        B   = ZSHARED ? (s ? B1 : B0) : B0 + (size_t)z * NN * Ncols;
        bias = s ? bias1 : bias0;
        dz  = dbase + (size_t)z * NN;
        C   = Cbase + (size_t)z * NN * Ncols;
    } else {
        A = Abase + (size_t)z * sA; lda = K;
        B = z ? B1 : B0;
        C = Cbase + (size_t)z * sC;
    }

    const int m0 = blockIdx.x * BM;
    const int n0 = blockIdx.y * BN;
    const int tid = threadIdx.x;
    const int w = tid >> 5, lane = tid & 31;
    const int g = lane >> 2, tig = lane & 3;
    const int wm = (w / WGN) * WM;
    const int wn = (w % WGN) * WN;

    float acc[MT][NT][4] = {};
    float4 aReg[A_LD4], bReg[B_LD4];

    // prologue: load first tile
    #pragma unroll
    for (int i = 0; i < A_LD4; i++) {
        int idx = tid + i * NTHREADS;
        int r = idx / (BK / 4), c4 = (idx % (BK / 4)) * 4;
        aReg[i] = *(const float4*)&A[(size_t)(m0 + r) * lda + c4];
    }
    #pragma unroll
    for (int i = 0; i < B_LD4; i++) {
        int idx = tid + i * NTHREADS;
        int r = idx / (BN / 4), c4 = (idx % (BN / 4)) * 4;
        bReg[i] = *(const float4*)&B[(size_t)r * Ncols + n0 + c4];
    }

    for (int k0 = 0; k0 < K; k0 += BK) {
        // store current tile (split) to smem
        #pragma unroll
        for (int i = 0; i < A_LD4; i++) {
            int idx = tid + i * NTHREADS;
            int r = idx / (BK / 4), c4 = (idx % (BK / 4)) * 4;
            float4 h, l; split4(aReg[i], h, l);
            *(float4*)&Ah[r][c4] = h;
            *(float4*)&Al[r][c4] = l;
        }
        #pragma unroll
        for (int i = 0; i < B_LD4; i++) {
            int idx = tid + i * NTHREADS;
            int r = idx / (BN / 4), c4 = (idx % (BN / 4)) * 4;
            float4 v = bReg[i];
            if (GCN) { float dk = dz[k0 + r]; v.x *= dk; v.y *= dk; v.z *= dk; v.w *= dk; }
            float4 h, l; split4(v, h, l);
            *(float4*)&Bh[r][c4] = h;
            *(float4*)&Bl[r][c4] = l;
        }
        __syncthreads();

        // prefetch next tile into registers (overlaps with compute below)
        if (k0 + BK < K) {
            #pragma unroll
            for (int i = 0; i < A_LD4; i++) {
                int idx = tid + i * NTHREADS;
                int r = idx / (BK / 4), c4 = (idx % (BK / 4)) * 4;
                aReg[i] = *(const float4*)&A[(size_t)(m0 + r) * lda + (k0 + BK) + c4];
            }
            #pragma unroll
            for (int i = 0; i < B_LD4; i++) {
                int idx = tid + i * NTHREADS;
                int r = idx / (BN / 4), c4 = (idx % (BN / 4)) * 4;
                bReg[i] = *(const float4*)&B[(size_t)(k0 + BK + r) * Ncols + n0 + c4];
            }
        }

        #pragma unroll
        for (int kk = 0; kk < BK; kk += 8) {
            uint32_t ah[MT][4], al[MT][4], bh[NT][2], bl[NT][2];
            #pragma unroll
            for (int mt = 0; mt < MT; mt++) {
                int rb = wm + mt * 16;
                ah[mt][0] = __float_as_uint(Ah[rb + g    ][kk + tig    ]);
                ah[mt][1] = __float_as_uint(Ah[rb + g + 8][kk + tig    ]);
                ah[mt][2] = __float_as_uint(Ah[rb + g    ][kk + tig + 4]);
                ah[mt][3] = __float_as_uint(Ah[rb + g + 8][kk + tig + 4]);
                al[mt][0] = __float_as_uint(Al[rb + g    ][kk + tig    ]);
                al[mt][1] = __float_as_uint(Al[rb + g + 8][kk + tig    ]);
                al[mt][2] = __float_as_uint(Al[rb + g    ][kk + tig + 4]);
                al[mt][3] = __float_as_uint(Al[rb + g + 8][kk + tig + 4]);
            }
            #pragma unroll
            for (int nt = 0; nt < NT; nt++) {
                int cb = wn + nt * 8 + g;
                bh[nt][0] = __float_as_uint(Bh[kk + tig    ][cb]);
                bh[nt][1] = __float_as_uint(Bh[kk + tig + 4][cb]);
                bl[nt][0] = __float_as_uint(Bl[kk + tig    ][cb]);
                bl[nt][1] = __float_as_uint(Bl[kk + tig + 4][cb]);
            }
            #pragma unroll
            for (int mt = 0; mt < MT; mt++)
                #pragma unroll
                for (int nt = 0; nt < NT; nt++) {
                    mma_tf32(acc[mt][nt], ah[mt][0], ah[mt][1], ah[mt][2], ah[mt][3],
                             bh[nt][0], bh[nt][1]);
                    mma_tf32(acc[mt][nt], ah[mt][0], ah[mt][1], ah[mt][2], ah[mt][3],
                             bl[nt][0], bl[nt][1]);
                    mma_tf32(acc[mt][nt], al[mt][0], al[mt][1], al[mt][2], al[mt][3],
                             bh[nt][0], bh[nt][1]);
                }
        }
        __syncthreads();
    }

    // epilogue
    #pragma unroll
    for (int mt = 0; mt < MT; mt++) {
        int r0 = m0 + wm + mt * 16 + g;
        int r1 = r0 + 8;
        float d0 = 0.f, d1 = 0.f;
        if (GCN) { d0 = dz[r0]; d1 = dz[r1]; }
        #pragma unroll
        for (int nt = 0; nt < NT; nt++) {
            int c = n0 + wn + nt * 8 + tig * 2;
            float v00 = acc[mt][nt][0], v01 = acc[mt][nt][1];
            float v10 = acc[mt][nt][2], v11 = acc[mt][nt][3];
            if (GCN) {
                float2 z0 = *(const float2*)&B[(size_t)r0 * Ncols + c];
                float2 z1 = *(const float2*)&B[(size_t)r1 * Ncols + c];
                float bc0 = bias[c], bc1 = bias[c + 1];
                v00 = d0 * v00 + d0 * d0 * z0.x + bc0;
                v01 = d0 * v01 + d0 * d0 * z0.y + bc1;
                v10 = d1 * v10 + d1 * d1 * z1.x + bc0;
                v11 = d1 * v11 + d1 * d1 * z1.y + bc1;
                if (ACT) {
                    v00 = (v00 >= 0.f) ? v00 : 0.2f * v00;
                    v01 = (v01 >= 0.f) ? v01 : 0.2f * v01;
                    v10 = (v10 >= 0.f) ? v10 : 0.2f * v10;
                    v11 = (v11 >= 0.f) ? v11 : 0.2f * v11;
                }
            }
            *(float2*)&C[(size_t)r0 * Ncols + c] = make_float2(v00, v01);
            *(float2*)&C[(size_t)r1 * Ncols + c] = make_float2(v10, v11);
        }
    }
}

// ---------------- fp32 kernels for layer 4 (N=8), both s merged --------------
template<int BM, int BN, int BK, int TM, int TN>
__global__ void gemm_plain_kernel(const float* __restrict__ Abase,
                                  const float* __restrict__ W0,
                                  const float* __restrict__ W1,
                                  float* __restrict__ Cbase,
                                  int K, int Ncols, size_t sA, size_t sC) {
    const float* A = Abase + (size_t)blockIdx.z * sA;
    const float* W = blockIdx.z ? W1 : W0;
    float* C = Cbase + (size_t)blockIdx.z * sC;
    __shared__ float As[BK][BM + 1];
    __shared__ float Bs[BK][BN + 1];
    const int NT  = (BM / TM) * (BN / TN);
    const int tx  = threadIdx.x, ty = threadIdx.y;
    const int tid = ty * (BN / TN) + tx;
    const int m0  = blockIdx.x * BM;
    const int n0  = blockIdx.y * BN;
    float acc[TM][TN] = {};
    for (int k0 = 0; k0 < K; k0 += BK) {
        #pragma unroll
        for (int idx = tid; idx < BM * BK; idx += NT) {
            int k = idx % BK, m = idx / BK;
            As[k][m] = A[(size_t)(m0 + m) * K + k0 + k];
        }
        #pragma unroll
        for (int idx = tid; idx < BK * BN; idx += NT) {
            int n = idx % BN, k = idx / BN;
            Bs[k][n] = W[(size_t)(k0 + k) * Ncols + n0 + n];
        }
        __syncthreads();
        #pragma unroll
        for (int kk = 0; kk < BK; kk++) {
            float a[TM], b[TN];
            #pragma unroll
            for (int m = 0; m < TM; m++) a[m] = As[kk][ty * TM + m];
            #pragma unroll
            for (int n = 0; n < TN; n++) b[n] = Bs[kk][tx * TN + n];
            #pragma unroll
            for (int m = 0; m < TM; m++)
                #pragma unroll
                for (int n = 0; n < TN; n++) acc[m][n] += a[m] * b[n];
        }
        __syncthreads();
    }
    #pragma unroll
    for (int m = 0; m < TM; m++) {
        int i = m0 + ty * TM + m;
        #pragma unroll
        for (int n = 0; n < TN; n++) {
            int c = n0 + tx * TN + n;
            C[(size_t)i * Ncols + c] = acc[m][n];
        }
    }
}

template<int BM, int BN, int BK, int TM, int TN, bool ACT>
__global__ void gcn_layer_kernel(const float* __restrict__ adjbase,
                                 const float* __restrict__ Zbase,
                                 const float* __restrict__ dbase,
                                 const float* __restrict__ bias0,
                                 const float* __restrict__ bias1,
                                 float* __restrict__ Hbase,
                                 int Ncols) {
    const int z = blockIdx.z;
    const int s = z >> 6, b = z & 63;
    const float* A  = adjbase + (size_t)(b * 2 + s) * NN * NN;
    const float* Zb = Zbase + (size_t)z * NN * Ncols;
    const float* dz = dbase + (size_t)z * NN;
    const float* bias = s ? bias1 : bias0;
    float* Hout     = Hbase + (size_t)z * NN * Ncols;

    __shared__ float As[BK][BM + 1];
    __shared__ float Bs[BK][BN + 1];
    const int NT  = (BM / TM) * (BN / TN);
    const int tx  = threadIdx.x, ty = threadIdx.y;
    const int tid = ty * (BN / TN) + tx;
    const int m0  = blockIdx.x * BM;
    const int n0  = blockIdx.y * BN;
    float acc[TM][TN] = {};
    for (int k0 = 0; k0 < NN; k0 += BK) {
        #pragma unroll
        for (int idx = tid; idx < BM * BK; idx += NT) {
            int k = idx % BK, m = idx / BK;
            As[k][m] = A[(size_t)(m0 + m) * NN + k0 + k];
        }
        #pragma unroll
        for (int idx = tid; idx < BK * BN; idx += NT) {
            int n = idx % BN, k = idx / BN;
            Bs[k][n] = Zb[(size_t)(k0 + k) * Ncols + n0 + n] * dz[k0 + k];
        }
        __syncthreads();
        #pragma unroll
        for (int kk = 0; kk < BK; kk++) {
            float a[TM], bf[TN];
            #pragma unroll
            for (int m = 0; m < TM; m++) a[m] = As[kk][ty * TM + m];
            #pragma unroll
            for (int n = 0; n < TN; n++) bf[n] = Bs[kk][tx * TN + n];
            #pragma unroll
            for (int m = 0; m < TM; m++)
                #pragma unroll
                for (int n = 0; n < TN; n++) acc[m][n] += a[m] * bf[n];
        }
        __syncthreads();
    }
    #pragma unroll
    for (int m = 0; m < TM; m++) {
        int i = m0 + ty * TM + m;
        float di = dz[i];
        #pragma unroll
        for (int n = 0; n < TN; n++) {
            int c = n0 + tx * TN + n;
            float zv = Zb[(size_t)i * Ncols + c];
            float v = di * acc[m][n] + di * di * zv + bias[c];
            if (ACT) v = (v >= 0.f) ? v : 0.2f * v;
            Hout[(size_t)i * Ncols + c] = v;
        }
    }
}

// ---------------- dynamic head params ---------------------------------------
__global__ void dcl_params_kernel(const int* __restrict__ task,
                                  const float* __restrict__ wc,
                                  const float* __restrict__ H3b,
                                  float* __restrict__ wb) {
    int z = blockIdx.x;
    int b = z & 63;
    const float* conv3 = H3b + (size_t)z * NN * H3;
    __shared__ float partial[256];
    __shared__ float xc[CDIM];
    int tid = threadIdx.x;
    int col = tid & 31, g = tid >> 5;
    float p = 0.f;
    for (int r = g; r < NN; r += 8) p += conv3[(size_t)r * H3 + col];
    partial[tid] = p;
    __syncthreads();
    if (tid < H3) {
        float sum = 0.f;
        #pragma unroll
        for (int gg = 0; gg < 8; gg++) sum += partial[gg * 32 + tid];
        xc[tid] = sum * (1.0f / (float)NN);
    }
    if (tid >= H3 && tid < CDIM) {
        xc[tid] = (task[b] == tid - H3) ? 1.f : 0.f;
    }
    __syncthreads();
    if (tid < PDIM) {
        float acc = 0.f;
        #pragma unroll
        for (int c = 0; c < CDIM; c++) acc += wc[tid * CDIM + c] * xc[c];
        wb[(size_t)z * PDIM + tid] = acc;
    }
}

// ---------------- cc kernel: logits + interleave scatter --------------------
__global__ void cc_kernel(const float* __restrict__ H4b,
                          const float* __restrict__ wb,
                          float* __restrict__ cc) {
    int z = blockIdx.x;
    int q = z >> 6, b = z & 63;
    __shared__ float flat[NN * OUTD];
    __shared__ float wm[64];
    __shared__ float bv[8];
    int tid = threadIdx.x;
    const float4* src4 = (const float4*)(H4b + (size_t)z * NN * OUTD);
    float4* dst4 = (float4*)flat;
    for (int i = tid; i < NN * OUTD / 4; i += 256) dst4[i] = src4[i];
    if (tid < 64) wm[tid] = wb[(size_t)z * PDIM + tid];
    if (tid < 8)  bv[tid] = wb[(size_t)z * PDIM + 64 + tid];
    __syncthreads();
    for (int f = tid; f < NN * OUTD; f += 256) {
        int r = f >> 9, c = f & 511;
        float v = bv[r];
        #pragma unroll
        for (int i = 0; i < 8; i++) v += wm[r * 8 + i] * flat[i * NN + c];
        int n = f >> 3, o = f & 7;
        int scc = n >> 8;
        int n2 = ((n & 255) << 1) | q;
        cc[(((size_t)(b * 2 + scc) * NN + n2) << 3) + o] = v;
    }
}

// ---------------- final: out = softplus(-(cc @ cc^T)) -----------------------
__global__ void final_kernel(const float* __restrict__ cc, float* __restrict__ out) {
    int zz = blockIdx.z;
    __shared__ float Msm[NN * OUTD];
    int tid = threadIdx.y * 16 + threadIdx.x;
    const float4* src = (const float4*)(cc + (size_t)zz * NN * OUTD);
    float4* dst = (float4*)Msm;
    for (int i = tid; i < NN * OUTD / 4; i += 256) dst[i] = src[i];
    __syncthreads();
    int i0 = blockIdx.y * 64 + threadIdx.y * 4;
    int j0 = blockIdx.x * 64 + threadIdx.x * 4;
    float ai[4][8], aj[4][8];
    #pragma unroll
    for (int m = 0; m < 4; m++)
        #pragma unroll
        for (int o = 0; o < 8; o++) ai[m][o] = Msm[(i0 + m) * 8 + o];
    #pragma unroll
    for (int n = 0; n < 4; n++)
        #pragma unroll
        for (int o = 0; o < 8; o++) aj[n][o] = Msm[(j0 + n) * 8 + o];
    float* ob = out + (size_t)zz * NN * NN;
    #pragma unroll
    for (int m = 0; m < 4; m++) {
        float r[4];
        #pragma unroll
        for (int n = 0; n < 4; n++) {
            float x = 0.f;
            #pragma unroll
            for (int o = 0; o < 8; o++) x += ai[m][o] * aj[n][o];
            r[n] = log1pf(expf(-fabsf(x))) + fmaxf(-x, 0.f);
        }
        *(float4*)(ob + (size_t)(i0 + m) * NN + j0) = make_float4(r[0], r[1], r[2], r[3]);
    }
}

// ---------------- host orchestration ----------------------------------------
extern "C" void kernel_launch(void* const* d_in, const int* in_sizes, int n_in,
                              void* d_out, int out_size) {
    const float* adj  = (const float*)d_in[0];
    const int*   task = (const int*)d_in[1];
    const float* w[2][4];
    const float* bia[2][4];
    int idx = 2;
    for (int s = 0; s < 2; s++)
        for (int l = 0; l < 4; l++) {
            w[s][l]   = (const float*)d_in[idx++];
            bia[s][l] = (const float*)d_in[idx++];
        }
    const float* wc = (const float*)d_in[18];
    float* out = (float*)d_out;

    float* base = nullptr;
    cudaGetSymbolAddress((void**)&base, g_scratch);
    float* p_d  = base + OFF_D;
    float* p_H1 = base + OFF_H1;
    float* p_H2 = base + OFF_H2;
    float* p_H3 = base + OFF_H3;
    float* p_H4 = base + OFF_H4;
    float* p_Z  = base + OFF_Z;
    float* p_WB = base + OFF_WB;
    float* p_CC = base + OFF_CC;

    const size_t S1  = (size_t)BB * NN * H1;
    const size_t S2  = (size_t)BB * NN * H2;
    const size_t S3  = (size_t)BB * NN * H3;
    const size_t S4  = (size_t)BB * NN * OUTD;

    // 1) degree factors
    rowsum_kernel<<<NZ * NN / 8, 256>>>(adj, p_d);

    // 2) layer 1: H1 = leaky(feat @ w1 + b1)   (Z = w1, shared per-branch)
    //    BM=64, BN=128 -> single N pass over adj
    mma_gemm_kernel<64, 128, 32, 2, 4, true, true, true>
        <<<dim3(8, 1, NZ), 256>>>(
            adj, w[0][0], w[1][0], p_d, bia[0][0], bia[1][0], p_H1, NN, H1, 0, 0);

    // 3) layer 2: Z = H1 @ w2 ; H2 = leaky(feat @ Z + b2)
    mma_gemm_kernel<64, 64, 32, 4, 2, false, false, false>
        <<<dim3(BB * NN / 64, 1, 2), 256>>>(
            p_H1, w[0][1], w[1][1], nullptr, nullptr, nullptr, p_Z, H1, H2, S1, S2);
    mma_gemm_kernel<64, 64, 32, 4, 2, true, true, false>
        <<<dim3(8, 1, NZ), 256>>>(
            adj, p_Z, nullptr, p_d, bia[0][1], bia[1][1], p_H2, NN, H2, 0, 0);

    // 4) layer 3: Z = H2 @ w3 ; H3 = leaky(feat @ Z + b3)
    mma_gemm_kernel<64, 32, 32, 4, 2, false, false, false>
        <<<dim3(BB * NN / 64, 1, 2), 256>>>(
            p_H2, w[0][2], w[1][2], nullptr, nullptr, nullptr, p_Z, H2, H3, S2, S3);
    mma_gemm_kernel<64, 32, 32, 4, 2, true, true, false>
        <<<dim3(8, 1, NZ), 256>>>(
            adj, p_Z, nullptr, p_d, bia[0][2], bia[1][2], p_H3, NN, H3, 0, 0);

    // 5) layer 4 (N=8, fp32): Z = H3 @ w4 ; H4 = feat @ Z + b4 (no act)
    gemm_plain_kernel<64, 8, 32, 4, 2>
        <<<dim3(BB * NN / 64, 1, 2), dim3(4, 16)>>>(
            p_H3, w[0][3], w[1][3], p_Z, H3, OUTD, S3, S4);
    gcn_layer_kernel<64, 8, 32, 4, 2, false>
        <<<dim3(8, 1, NZ), dim3(4, 16)>>>(
            adj, p_Z, p_d, bia[0][3], bia[1][3], p_H4, OUTD);

    // 6) dynamic head params (uses conv3 = H3)
    dcl_params_kernel<<<NZ, 256>>>(task, wc, p_H3, p_WB);

    // 7) logits + interleave into cc
    cc_kernel<<<NZ, 256>>>(p_H4, p_WB, p_CC);

    // 8) final gram + softplus
    final_kernel<<<dim3(8, 8, NZ), dim3(16, 16)>>>(p_CC, out);

    (void)in_sizes; (void)n_in; (void)out_size;
}

// round 5
// speedup vs baseline: 3.7136x; 1.2098x over previous
#include <cuda_runtime.h>
#include <cuda_bf16.h>
#include <math.h>
#include <stdint.h>

#define NN 512
#define BB 64
#define NZ 128            // B*2 branch instances
#define H1 128
#define H2 64
#define H3 32
#define OUTD 8
#define CLS 16
#define PDIM 72           // OUT*OUT + OUT
#define CDIM 48           // H3 + CLS

// ---------------- scratch (single static device buffer, no allocs) ----------
static const size_t OFF_D   = 0;
static const size_t OFF_H1  = OFF_D   + (size_t)NZ*NN;
static const size_t OFF_H2  = OFF_H1  + (size_t)NZ*NN*H1;
static const size_t OFF_H3  = OFF_H2  + (size_t)NZ*NN*H2;
static const size_t OFF_H4  = OFF_H3  + (size_t)NZ*NN*H3;
static const size_t OFF_Z   = OFF_H4  + (size_t)NZ*NN*OUTD;
static const size_t OFF_WB  = OFF_Z   + (size_t)NZ*NN*H2;
static const size_t OFF_CC  = OFF_WB  + (size_t)NZ*PDIM;
static const size_t TOTAL_SCRATCH = OFF_CC + (size_t)BB*2*NN*OUTD;

__device__ float g_scratch[TOTAL_SCRATCH];

// ---------------- kernel 1: row-sum normalization factors -------------------
__global__ void rowsum_kernel(const float* __restrict__ adj, float* __restrict__ dout) {
    int gw   = (blockIdx.x * blockDim.x + threadIdx.x) >> 5;
    int lane = threadIdx.x & 31;
    int b2  = gw >> 9;
    int row = gw & 511;
    const float* r = adj + (size_t)b2 * NN * NN + (size_t)row * NN;
    float ssum = 0.f;
    #pragma unroll
    for (int k = lane; k < NN; k += 32) ssum += r[k];
    #pragma unroll
    for (int o = 16; o; o >>= 1) ssum += __shfl_xor_sync(0xffffffffu, ssum, o);
    if (lane == 0) {
        int s = b2 & 1, b = b2 >> 1;
        dout[(size_t)(s * BB + b) * NN + row] = rsqrtf(ssum + 1.0f);
    }
}

// ---------------- tf32 split helpers -----------------------------------------
__device__ __forceinline__ void split_tf32(float v, float& hi, float& lo) {
    uint32_t u;
    asm("cvt.rna.tf32.f32 %0, %1;" : "=r"(u) : "f"(v));
    hi = __uint_as_float(u);
    float r = v - hi;
    uint32_t u2;
    asm("cvt.rna.tf32.f32 %0, %1;" : "=r"(u2) : "f"(r));
    lo = __uint_as_float(u2);
}
__device__ __forceinline__ void split4(float4 v, float4& h, float4& l) {
    split_tf32(v.x, h.x, l.x);
    split_tf32(v.y, h.y, l.y);
    split_tf32(v.z, h.z, l.z);
    split_tf32(v.w, h.w, l.w);
}
__device__ __forceinline__ void mma_tf32(float c[4],
    uint32_t a0, uint32_t a1, uint32_t a2, uint32_t a3,
    uint32_t b0, uint32_t b1) {
    asm volatile(
        "mma.sync.aligned.m16n8k8.row.col.f32.tf32.tf32.f32 "
        "{%0,%1,%2,%3}, {%4,%5,%6,%7}, {%8,%9}, {%0,%1,%2,%3};"
        : "+f"(c[0]), "+f"(c[1]), "+f"(c[2]), "+f"(c[3])
        : "r"(a0), "r"(a1), "r"(a2), "r"(a3), "r"(b0), "r"(b1));
}

// ---------------- unified split-TF32 MMA GEMM (float2 hi/lo smem) ------------
// GCN=true : blockIdx.z = z in [0,128): s=z>>6, b=z&63
//            C_z = epi(adj_{b,s} @ (d_z ∘ Z_z)); epilogue adds d_i^2*Z + bias (+leaky)
// GCN=false: blockIdx.z = s in {0,1}: C = A_s @ W_s (flat rows)
template<int BM, int BN, int WGM, int WGN, bool GCN, bool ACT, bool ZSHARED>
__global__ void __launch_bounds__(WGM*WGN*32)
mma_gemm_kernel(const float* __restrict__ Abase,
                const float* __restrict__ B0,
                const float* __restrict__ B1,
                const float* __restrict__ dbase,
                const float* __restrict__ bias0,
                const float* __restrict__ bias1,
                float* __restrict__ Cbase,
                int K, int Ncols, size_t sA, size_t sC)
{
    constexpr int BK = 32;
    constexpr int WM = BM / WGM, WN = BN / WGN;
    constexpr int MT = WM / 16, NT = WN / 8;
    constexpr int NTHREADS = WGM * WGN * 32;
    constexpr int BKP = BK + 4;          // float2 stride; bank-safe
    constexpr int BNP = BN + 4;          // float2 stride; bank-safe
    constexpr int A_TOT4 = BM * BK / 4;  // #float4 global loads
    constexpr int B_TOT4 = BK * BN / 4;
    constexpr int A_LD4 = (A_TOT4 + NTHREADS - 1) / NTHREADS;
    constexpr int B_LD4 = (B_TOT4 + NTHREADS - 1) / NTHREADS;

    extern __shared__ float2 smdyn[];
    float2 (*Ahl)[BKP] = reinterpret_cast<float2(*)[BKP]>(smdyn);
    float2 (*Bhl)[BNP] = reinterpret_cast<float2(*)[BNP]>(smdyn + BM * BKP);

    const int z = blockIdx.z;
    const float* A; const float* B; const float* bias = nullptr;
    const float* dz = nullptr; float* C;
    int lda;
    if (GCN) {
        int s = z >> 6, b = z & 63;
        A   = Abase + (size_t)(b * 2 + s) * NN * NN; lda = NN;
        B   = ZSHARED ? (s ? B1 : B0) : B0 + (size_t)z * NN * Ncols;
        bias = s ? bias1 : bias0;
        dz  = dbase + (size_t)z * NN;
        C   = Cbase + (size_t)z * NN * Ncols;
    } else {
        A = Abase + (size_t)z * sA; lda = K;
        B = z ? B1 : B0;
        C = Cbase + (size_t)z * sC;
    }

    const int m0 = blockIdx.x * BM;
    const int n0 = blockIdx.y * BN;
    const int tid = threadIdx.x;
    const int w = tid >> 5, lane = tid & 31;
    const int g = lane >> 2, tig = lane & 3;
    const int wm = (w / WGN) * WM;
    const int wn = (w % WGN) * WN;

    float acc[MT][NT][4] = {};
    float4 aReg[A_LD4], bReg[B_LD4];

    // prologue: load first tile
    #pragma unroll
    for (int i = 0; i < A_LD4; i++) {
        int idx = tid + i * NTHREADS;
        if (idx < A_TOT4) {
            int r = idx / (BK / 4), c4 = (idx % (BK / 4)) * 4;
            aReg[i] = *(const float4*)&A[(size_t)(m0 + r) * lda + c4];
        }
    }
    #pragma unroll
    for (int i = 0; i < B_LD4; i++) {
        int idx = tid + i * NTHREADS;
        if (idx < B_TOT4) {
            int r = idx / (BN / 4), c4 = (idx % (BN / 4)) * 4;
            bReg[i] = *(const float4*)&B[(size_t)r * Ncols + n0 + c4];
        }
    }

    for (int k0 = 0; k0 < K; k0 += BK) {
        // store current tile split into smem (interleaved hi/lo)
        #pragma unroll
        for (int i = 0; i < A_LD4; i++) {
            int idx = tid + i * NTHREADS;
            if (idx < A_TOT4) {
                int r = idx / (BK / 4), c4 = (idx % (BK / 4)) * 4;
                float4 h, l; split4(aReg[i], h, l);
                *(float4*)&Ahl[r][c4]     = make_float4(h.x, l.x, h.y, l.y);
                *(float4*)&Ahl[r][c4 + 2] = make_float4(h.z, l.z, h.w, l.w);
            }
        }
        #pragma unroll
        for (int i = 0; i < B_LD4; i++) {
            int idx = tid + i * NTHREADS;
            if (idx < B_TOT4) {
                int r = idx / (BN / 4), c4 = (idx % (BN / 4)) * 4;
                float4 v = bReg[i];
                if (GCN) { float dk = dz[k0 + r]; v.x *= dk; v.y *= dk; v.z *= dk; v.w *= dk; }
                float4 h, l; split4(v, h, l);
                *(float4*)&Bhl[r][c4]     = make_float4(h.x, l.x, h.y, l.y);
                *(float4*)&Bhl[r][c4 + 2] = make_float4(h.z, l.z, h.w, l.w);
            }
        }
        __syncthreads();

        // prefetch next tile into registers (overlaps with compute below)
        if (k0 + BK < K) {
            #pragma unroll
            for (int i = 0; i < A_LD4; i++) {
                int idx = tid + i * NTHREADS;
                if (idx < A_TOT4) {
                    int r = idx / (BK / 4), c4 = (idx % (BK / 4)) * 4;
                    aReg[i] = *(const float4*)&A[(size_t)(m0 + r) * lda + (k0 + BK) + c4];
                }
            }
            #pragma unroll
            for (int i = 0; i < B_LD4; i++) {
                int idx = tid + i * NTHREADS;
                if (idx < B_TOT4) {
                    int r = idx / (BN / 4), c4 = (idx % (BN / 4)) * 4;
                    bReg[i] = *(const float4*)&B[(size_t)(k0 + BK + r) * Ncols + n0 + c4];
                }
            }
        }

        #pragma unroll
        for (int kk = 0; kk < BK; kk += 8) {
            uint32_t ah[MT][4], al[MT][4], bh[NT][2], bl[NT][2];
            #pragma unroll
            for (int mt = 0; mt < MT; mt++) {
                int rb = wm + mt * 16;
                float2 p0 = Ahl[rb + g    ][kk + tig    ];
                float2 p1 = Ahl[rb + g + 8][kk + tig    ];
                float2 p2 = Ahl[rb + g    ][kk + tig + 4];
                float2 p3 = Ahl[rb + g + 8][kk + tig + 4];
                ah[mt][0] = __float_as_uint(p0.x); al[mt][0] = __float_as_uint(p0.y);
                ah[mt][1] = __float_as_uint(p1.x); al[mt][1] = __float_as_uint(p1.y);
                ah[mt][2] = __float_as_uint(p2.x); al[mt][2] = __float_as_uint(p2.y);
                ah[mt][3] = __float_as_uint(p3.x); al[mt][3] = __float_as_uint(p3.y);
            }
            #pragma unroll
            for (int nt = 0; nt < NT; nt++) {
                int cb = wn + nt * 8 + g;
                float2 q0 = Bhl[kk + tig    ][cb];
                float2 q1 = Bhl[kk + tig + 4][cb];
                bh[nt][0] = __float_as_uint(q0.x); bl[nt][0] = __float_as_uint(q0.y);
                bh[nt][1] = __float_as_uint(q1.x); bl[nt][1] = __float_as_uint(q1.y);
            }
            #pragma unroll
            for (int mt = 0; mt < MT; mt++)
                #pragma unroll
                for (int nt = 0; nt < NT; nt++) {
                    mma_tf32(acc[mt][nt], ah[mt][0], ah[mt][1], ah[mt][2], ah[mt][3],
                             bh[nt][0], bh[nt][1]);
                    mma_tf32(acc[mt][nt], ah[mt][0], ah[mt][1], ah[mt][2], ah[mt][3],
                             bl[nt][0], bl[nt][1]);
                    mma_tf32(acc[mt][nt], al[mt][0], al[mt][1], al[mt][2], al[mt][3],
                             bh[nt][0], bh[nt][1]);
                }
        }
        __syncthreads();
    }

    // epilogue
    #pragma unroll
    for (int mt = 0; mt < MT; mt++) {
        int r0 = m0 + wm + mt * 16 + g;
        int r1 = r0 + 8;
        float d0 = 0.f, d1 = 0.f;
        if (GCN) { d0 = dz[r0]; d1 = dz[r1]; }
        #pragma unroll
        for (int nt = 0; nt < NT; nt++) {
            int c = n0 + wn + nt * 8 + tig * 2;
            float v00 = acc[mt][nt][0], v01 = acc[mt][nt][1];
            float v10 = acc[mt][nt][2], v11 = acc[mt][nt][3];
            if (GCN) {
                float2 z0 = *(const float2*)&B[(size_t)r0 * Ncols + c];
                float2 z1 = *(const float2*)&B[(size_t)r1 * Ncols + c];
                float bc0 = bias[c], bc1 = bias[c + 1];
                v00 = d0 * v00 + d0 * d0 * z0.x + bc0;
                v01 = d0 * v01 + d0 * d0 * z0.y + bc1;
                v10 = d1 * v10 + d1 * d1 * z1.x + bc0;
                v11 = d1 * v11 + d1 * d1 * z1.y + bc1;
                if (ACT) {
                    v00 = (v00 >= 0.f) ? v00 : 0.2f * v00;
                    v01 = (v01 >= 0.f) ? v01 : 0.2f * v01;
                    v10 = (v10 >= 0.f) ? v10 : 0.2f * v10;
                    v11 = (v11 >= 0.f) ? v11 : 0.2f * v11;
                }
            }
            *(float2*)&C[(size_t)r0 * Ncols + c] = make_float2(v00, v01);
            *(float2*)&C[(size_t)r1 * Ncols + c] = make_float2(v10, v11);
        }
    }
}

// ---------------- dynamic head params ---------------------------------------
__global__ void dcl_params_kernel(const int* __restrict__ task,
                                  const float* __restrict__ wc,
                                  const float* __restrict__ H3b,
                                  float* __restrict__ wb) {
    int z = blockIdx.x;
    int b = z & 63;
    const float* conv3 = H3b + (size_t)z * NN * H3;
    __shared__ float partial[256];
    __shared__ float xc[CDIM];
    int tid = threadIdx.x;
    int col = tid & 31, g = tid >> 5;
    float p = 0.f;
    for (int r = g; r < NN; r += 8) p += conv3[(size_t)r * H3 + col];
    partial[tid] = p;
    __syncthreads();
    if (tid < H3) {
        float sum = 0.f;
        #pragma unroll
        for (int gg = 0; gg < 8; gg++) sum += partial[gg * 32 + tid];
        xc[tid] = sum * (1.0f / (float)NN);
    }
    if (tid >= H3 && tid < CDIM) {
        xc[tid] = (task[b] == tid - H3) ? 1.f : 0.f;
    }
    __syncthreads();
    if (tid < PDIM) {
        float acc = 0.f;
        #pragma unroll
        for (int c = 0; c < CDIM; c++) acc += wc[tid * CDIM + c] * xc[c];
        wb[(size_t)z * PDIM + tid] = acc;
    }
}

// ---------------- cc kernel: logits + interleave scatter --------------------
__global__ void cc_kernel(const float* __restrict__ H4b,
                          const float* __restrict__ wb,
                          float* __restrict__ cc) {
    int z = blockIdx.x;
    int q = z >> 6, b = z & 63;
    __shared__ float flat[NN * OUTD];
    __shared__ float wm[64];
    __shared__ float bv[8];
    int tid = threadIdx.x;
    const float4* src4 = (const float4*)(H4b + (size_t)z * NN * OUTD);
    float4* dst4 = (float4*)flat;
    for (int i = tid; i < NN * OUTD / 4; i += 256) dst4[i] = src4[i];
    if (tid < 64) wm[tid] = wb[(size_t)z * PDIM + tid];
    if (tid < 8)  bv[tid] = wb[(size_t)z * PDIM + 64 + tid];
    __syncthreads();
    for (int f = tid; f < NN * OUTD; f += 256) {
        int r = f >> 9, c = f & 511;
        float v = bv[r];
        #pragma unroll
        for (int i = 0; i < 8; i++) v += wm[r * 8 + i] * flat[i * NN + c];
        int n = f >> 3, o = f & 7;
        int scc = n >> 8;
        int n2 = ((n & 255) << 1) | q;
        cc[(((size_t)(b * 2 + scc) * NN + n2) << 3) + o] = v;
    }
}

// ---------------- final: out = softplus(-(cc @ cc^T)) -----------------------
__global__ void final_kernel(const float* __restrict__ cc, float* __restrict__ out) {
    int zz = blockIdx.z;
    __shared__ float Msm[NN * OUTD];
    int tid = threadIdx.y * 16 + threadIdx.x;
    const float4* src = (const float4*)(cc + (size_t)zz * NN * OUTD);
    float4* dst = (float4*)Msm;
    for (int i = tid; i < NN * OUTD / 4; i += 256) dst[i] = src[i];
    __syncthreads();
    int i0 = blockIdx.y * 64 + threadIdx.y * 4;
    int j0 = blockIdx.x * 64 + threadIdx.x * 4;
    float ai[4][8], aj[4][8];
    #pragma unroll
    for (int m = 0; m < 4; m++)
        #pragma unroll
        for (int o = 0; o < 8; o++) ai[m][o] = Msm[(i0 + m) * 8 + o];
    #pragma unroll
    for (int n = 0; n < 4; n++)
        #pragma unroll
        for (int o = 0; o < 8; o++) aj[n][o] = Msm[(j0 + n) * 8 + o];
    float* ob = out + (size_t)zz * NN * NN;
    #pragma unroll
    for (int m = 0; m < 4; m++) {
        float r[4];
        #pragma unroll
        for (int n = 0; n < 4; n++) {
            float x = 0.f;
            #pragma unroll
            for (int o = 0; o < 8; o++) x += ai[m][o] * aj[n][o];
            r[n] = log1pf(expf(-fabsf(x))) + fmaxf(-x, 0.f);
        }
        *(float4*)(ob + (size_t)(i0 + m) * NN + j0) = make_float4(r[0], r[1], r[2], r[3]);
    }
}

// ---------------- host orchestration ----------------------------------------
// smem bytes helper: (BM*(BK+4) + BK*(BN+4)) float2s
#define SMEM_BYTES(BM, BN) (((BM) * 36 + 32 * ((BN) + 4)) * (int)sizeof(float2))

extern "C" void kernel_launch(void* const* d_in, const int* in_sizes, int n_in,
                              void* d_out, int out_size) {
    const float* adj  = (const float*)d_in[0];
    const int*   task = (const int*)d_in[1];
    const float* w[2][4];
    const float* bia[2][4];
    int idx = 2;
    for (int s = 0; s < 2; s++)
        for (int l = 0; l < 4; l++) {
            w[s][l]   = (const float*)d_in[idx++];
            bia[s][l] = (const float*)d_in[idx++];
        }
    const float* wc = (const float*)d_in[18];
    float* out = (float*)d_out;

    float* base = nullptr;
    cudaGetSymbolAddress((void**)&base, g_scratch);
    float* p_d  = base + OFF_D;
    float* p_H1 = base + OFF_H1;
    float* p_H2 = base + OFF_H2;
    float* p_H3 = base + OFF_H3;
    float* p_H4 = base + OFF_H4;
    float* p_Z  = base + OFF_Z;
    float* p_WB = base + OFF_WB;
    float* p_CC = base + OFF_CC;

    const size_t S1  = (size_t)BB * NN * H1;
    const size_t S2  = (size_t)BB * NN * H2;
    const size_t S3  = (size_t)BB * NN * H3;
    const size_t S4  = (size_t)BB * NN * OUTD;

    // layer-1 kernel needs >48KB dynamic smem: opt in (idempotent)
    cudaFuncSetAttribute(
        (const void*)mma_gemm_kernel<64, 128, 2, 4, true, true, true>,
        cudaFuncAttributeMaxDynamicSharedMemorySize, SMEM_BYTES(64, 128));

    // 1) degree factors
    rowsum_kernel<<<NZ * NN / 8, 256>>>(adj, p_d);

    // 2) layer 1: H1 = leaky(feat @ w1 + b1), Z = w1 shared; single adj pass
    mma_gemm_kernel<64, 128, 2, 4, true, true, true>
        <<<dim3(8, 1, NZ), 256, SMEM_BYTES(64, 128)>>>(
            adj, w[0][0], w[1][0], p_d, bia[0][0], bia[1][0], p_H1, NN, H1, 0, 0);

    // 3) layer 2: Z = H1 @ w2 ; H2 = leaky(feat @ Z + b2)
    mma_gemm_kernel<64, 64, 2, 2, false, false, false>
        <<<dim3(BB * NN / 64, 1, 2), 128, SMEM_BYTES(64, 64)>>>(
            p_H1, w[0][1], w[1][1], nullptr, nullptr, nullptr, p_Z, H1, H2, S1, S2);
    mma_gemm_kernel<64, 64, 2, 2, true, true, false>
        <<<dim3(8, 1, NZ), 128, SMEM_BYTES(64, 64)>>>(
            adj, p_Z, nullptr, p_d, bia[0][1], bia[1][1], p_H2, NN, H2, 0, 0);

    // 4) layer 3: Z = H2 @ w3 ; H3 = leaky(feat @ Z + b3)
    mma_gemm_kernel<128, 32, 4, 1, false, false, false>
        <<<dim3(BB * NN / 128, 1, 2), 128, SMEM_BYTES(128, 32)>>>(
            p_H2, w[0][2], w[1][2], nullptr, nullptr, nullptr, p_Z, H2, H3, S2, S3);
    mma_gemm_kernel<128, 32, 4, 1, true, true, false>
        <<<dim3(4, 1, NZ), 128, SMEM_BYTES(128, 32)>>>(
            adj, p_Z, nullptr, p_d, bia[0][2], bia[1][2], p_H3, NN, H3, 0, 0);

    // 5) layer 4: Z = H3 @ w4 ; H4 = feat @ Z + b4 (no act) — MMA path, N=8
    mma_gemm_kernel<128, 8, 4, 1, false, false, false>
        <<<dim3(BB * NN / 128, 1, 2), 128, SMEM_BYTES(128, 8)>>>(
            p_H3, w[0][3], w[1][3], nullptr, nullptr, nullptr, p_Z, H3, OUTD, S3, S4);
    mma_gemm_kernel<128, 8, 4, 1, true, false, false>
        <<<dim3(4, 1, NZ), 128, SMEM_BYTES(128, 8)>>>(
            adj, p_Z, nullptr, p_d, bia[0][3], bia[1][3], p_H4, NN, OUTD, 0, 0);

    // 6) dynamic head params (uses conv3 = H3)
    dcl_params_kernel<<<NZ, 256>>>(task, wc, p_H3, p_WB);

    // 7) logits + interleave into cc
    cc_kernel<<<NZ, 256>>>(p_H4, p_WB, p_CC);

    // 8) final gram + softplus
    final_kernel<<<dim3(8, 8, NZ), dim3(16, 16)>>>(p_CC, out);

    (void)in_sizes; (void)n_in; (void)out_size;
}

// round 6
// speedup vs baseline: 3.8344x; 1.0325x over previous
#include <cuda_runtime.h>
#include <cuda_bf16.h>
#include <math.h>
#include <stdint.h>

#define NN 512
#define BB 64
#define NZ 128            // B*2 branch instances
#define H1 128
#define H2 64
#define H3 32
#define OUTD 8
#define CLS 16
#define PDIM 72           // OUT*OUT + OUT
#define CDIM 48           // H3 + CLS

// ---------------- scratch (single static device buffer, no allocs) ----------
static const size_t OFF_D   = 0;
static const size_t OFF_H1  = OFF_D   + (size_t)NZ*NN;
static const size_t OFF_H2  = OFF_H1  + (size_t)NZ*NN*H1;
static const size_t OFF_H3  = OFF_H2  + (size_t)NZ*NN*H2;
static const size_t OFF_H4  = OFF_H3  + (size_t)NZ*NN*H3;
static const size_t OFF_Z   = OFF_H4  + (size_t)NZ*NN*OUTD;
static const size_t OFF_WB  = OFF_Z   + (size_t)NZ*NN*H2;
static const size_t OFF_CC  = OFF_WB  + (size_t)NZ*PDIM;
static const size_t TOTAL_SCRATCH = OFF_CC + (size_t)BB*2*NN*OUTD;

__device__ float g_scratch[TOTAL_SCRATCH];

// ---------------- kernel 1: row-sum normalization factors -------------------
__global__ void rowsum_kernel(const float* __restrict__ adj, float* __restrict__ dout) {
    int gw   = (blockIdx.x * blockDim.x + threadIdx.x) >> 5;
    int lane = threadIdx.x & 31;
    int b2  = gw >> 9;
    int row = gw & 511;
    const float4* r4 = (const float4*)(adj + (size_t)b2 * NN * NN + (size_t)row * NN);
    float ssum = 0.f;
    #pragma unroll
    for (int k = lane; k < NN / 4; k += 32) {
        float4 v = r4[k];
        ssum += (v.x + v.y) + (v.z + v.w);
    }
    #pragma unroll
    for (int o = 16; o; o >>= 1) ssum += __shfl_xor_sync(0xffffffffu, ssum, o);
    if (lane == 0) {
        int s = b2 & 1, b = b2 >> 1;
        dout[(size_t)(s * BB + b) * NN + row] = rsqrtf(ssum + 1.0f);
    }
}

// ---------------- tf32 split helpers -----------------------------------------
__device__ __forceinline__ void split_tf32(float v, float& hi, float& lo) {
    uint32_t u;
    asm("cvt.rna.tf32.f32 %0, %1;" : "=r"(u) : "f"(v));
    hi = __uint_as_float(u);
    float r = v - hi;
    uint32_t u2;
    asm("cvt.rna.tf32.f32 %0, %1;" : "=r"(u2) : "f"(r));
    lo = __uint_as_float(u2);
}
__device__ __forceinline__ void split4(float4 v, float4& h, float4& l) {
    split_tf32(v.x, h.x, l.x);
    split_tf32(v.y, h.y, l.y);
    split_tf32(v.z, h.z, l.z);
    split_tf32(v.w, h.w, l.w);
}
__device__ __forceinline__ void mma_tf32(float c[4],
    uint32_t a0, uint32_t a1, uint32_t a2, uint32_t a3,
    uint32_t b0, uint32_t b1) {
    asm volatile(
        "mma.sync.aligned.m16n8k8.row.col.f32.tf32.tf32.f32 "
        "{%0,%1,%2,%3}, {%4,%5,%6,%7}, {%8,%9}, {%0,%1,%2,%3};"
        : "+f"(c[0]), "+f"(c[1]), "+f"(c[2]), "+f"(c[3])
        : "r"(a0), "r"(a1), "r"(a2), "r"(a3), "r"(b0), "r"(b1));
}

// ---------------- unified split-TF32 MMA GEMM (float2 hi/lo smem) ------------
// GCN=true : blockIdx.z = z in [0,128): s=z>>6, b=z&63
//            C_z = epi(adj_{b,s} @ (d_z ∘ Z_z)); epilogue adds d_i^2*Z + bias (+leaky)
// GCN=false: blockIdx.z = s in {0,1}: C = A_s @ W_s (flat rows)
template<int BM, int BN, int WGM, int WGN, bool GCN, bool ACT, bool ZSHARED>
__global__ void __launch_bounds__(WGM*WGN*32, (WGM*WGN*32 == 256) ? 2 : 4)
mma_gemm_kernel(const float* __restrict__ Abase,
                const float* __restrict__ B0,
                const float* __restrict__ B1,
                const float* __restrict__ dbase,
                const float* __restrict__ bias0,
                const float* __restrict__ bias1,
                float* __restrict__ Cbase,
                int K, int Ncols, size_t sA, size_t sC)
{
    constexpr int BK = 32;
    constexpr int WM = BM / WGM, WN = BN / WGN;
    constexpr int MT = WM / 16, NT = WN / 8;
    constexpr int NTHREADS = WGM * WGN * 32;
    constexpr int BKP = BK + 4;          // float2 stride; bank-safe
    constexpr int BNP = BN + 4;          // float2 stride; bank-safe
    constexpr int A_TOT4 = BM * BK / 4;  // #float4 global loads
    constexpr int B_TOT4 = BK * BN / 4;
    constexpr int A_LD4 = (A_TOT4 + NTHREADS - 1) / NTHREADS;
    constexpr int B_LD4 = (B_TOT4 + NTHREADS - 1) / NTHREADS;

    extern __shared__ float2 smdyn[];
    float2 (*Ahl)[BKP] = reinterpret_cast<float2(*)[BKP]>(smdyn);
    float2 (*Bhl)[BNP] = reinterpret_cast<float2(*)[BNP]>(smdyn + BM * BKP);

    const int z = blockIdx.z;
    const float* A; const float* B; const float* bias = nullptr;
    const float* dz = nullptr; float* C;
    int lda;
    if (GCN) {
        int s = z >> 6, b = z & 63;
        A   = Abase + (size_t)(b * 2 + s) * NN * NN; lda = NN;
        B   = ZSHARED ? (s ? B1 : B0) : B0 + (size_t)z * NN * Ncols;
        bias = s ? bias1 : bias0;
        dz  = dbase + (size_t)z * NN;
        C   = Cbase + (size_t)z * NN * Ncols;
    } else {
        A = Abase + (size_t)z * sA; lda = K;
        B = z ? B1 : B0;
        C = Cbase + (size_t)z * sC;
    }

    const int m0 = blockIdx.x * BM;
    const int n0 = blockIdx.y * BN;
    const int tid = threadIdx.x;
    const int w = tid >> 5, lane = tid & 31;
    const int g = lane >> 2, tig = lane & 3;
    const int wm = (w / WGN) * WM;
    const int wn = (w % WGN) * WN;

    float acc[MT][NT][4] = {};
    float4 aReg[A_LD4], bReg[B_LD4];

    // prologue: load first tile
    #pragma unroll
    for (int i = 0; i < A_LD4; i++) {
        int idx = tid + i * NTHREADS;
        if (idx < A_TOT4) {
            int r = idx / (BK / 4), c4 = (idx % (BK / 4)) * 4;
            aReg[i] = *(const float4*)&A[(size_t)(m0 + r) * lda + c4];
        }
    }
    #pragma unroll
    for (int i = 0; i < B_LD4; i++) {
        int idx = tid + i * NTHREADS;
        if (idx < B_TOT4) {
            int r = idx / (BN / 4), c4 = (idx % (BN / 4)) * 4;
            bReg[i] = *(const float4*)&B[(size_t)r * Ncols + n0 + c4];
        }
    }

    for (int k0 = 0; k0 < K; k0 += BK) {
        // store current tile split into smem (interleaved hi/lo)
        #pragma unroll
        for (int i = 0; i < A_LD4; i++) {
            int idx = tid + i * NTHREADS;
            if (idx < A_TOT4) {
                int r = idx / (BK / 4), c4 = (idx % (BK / 4)) * 4;
                float4 h, l; split4(aReg[i], h, l);
                *(float4*)&Ahl[r][c4]     = make_float4(h.x, l.x, h.y, l.y);
                *(float4*)&Ahl[r][c4 + 2] = make_float4(h.z, l.z, h.w, l.w);
            }
        }
        #pragma unroll
        for (int i = 0; i < B_LD4; i++) {
            int idx = tid + i * NTHREADS;
            if (idx < B_TOT4) {
                int r = idx / (BN / 4), c4 = (idx % (BN / 4)) * 4;
                float4 v = bReg[i];
                if (GCN) { float dk = dz[k0 + r]; v.x *= dk; v.y *= dk; v.z *= dk; v.w *= dk; }
                float4 h, l; split4(v, h, l);
                *(float4*)&Bhl[r][c4]     = make_float4(h.x, l.x, h.y, l.y);
                *(float4*)&Bhl[r][c4 + 2] = make_float4(h.z, l.z, h.w, l.w);
            }
        }
        __syncthreads();

        // prefetch next tile into registers (overlaps with compute below)
        if (k0 + BK < K) {
            #pragma unroll
            for (int i = 0; i < A_LD4; i++) {
                int idx = tid + i * NTHREADS;
                if (idx < A_TOT4) {
                    int r = idx / (BK / 4), c4 = (idx % (BK / 4)) * 4;
                    aReg[i] = *(const float4*)&A[(size_t)(m0 + r) * lda + (k0 + BK) + c4];
                }
            }
            #pragma unroll
            for (int i = 0; i < B_LD4; i++) {
                int idx = tid + i * NTHREADS;
                if (idx < B_TOT4) {
                    int r = idx / (BN / 4), c4 = (idx % (BN / 4)) * 4;
                    bReg[i] = *(const float4*)&B[(size_t)(k0 + BK + r) * Ncols + n0 + c4];
                }
            }
        }

        #pragma unroll
        for (int kk = 0; kk < BK; kk += 8) {
            uint32_t ah[MT][4], al[MT][4], bh[NT][2], bl[NT][2];
            #pragma unroll
            for (int mt = 0; mt < MT; mt++) {
                int rb = wm + mt * 16;
                float2 p0 = Ahl[rb + g    ][kk + tig    ];
                float2 p1 = Ahl[rb + g + 8][kk + tig    ];
                float2 p2 = Ahl[rb + g    ][kk + tig + 4];
                float2 p3 = Ahl[rb + g + 8][kk + tig + 4];
                ah[mt][0] = __float_as_uint(p0.x); al[mt][0] = __float_as_uint(p0.y);
                ah[mt][1] = __float_as_uint(p1.x); al[mt][1] = __float_as_uint(p1.y);
                ah[mt][2] = __float_as_uint(p2.x); al[mt][2] = __float_as_uint(p2.y);
                ah[mt][3] = __float_as_uint(p3.x); al[mt][3] = __float_as_uint(p3.y);
            }
            #pragma unroll
            for (int nt = 0; nt < NT; nt++) {
                int cb = wn + nt * 8 + g;
                float2 q0 = Bhl[kk + tig    ][cb];
                float2 q1 = Bhl[kk + tig + 4][cb];
                bh[nt][0] = __float_as_uint(q0.x); bl[nt][0] = __float_as_uint(q0.y);
                bh[nt][1] = __float_as_uint(q1.x); bl[nt][1] = __float_as_uint(q1.y);
            }
            #pragma unroll
            for (int mt = 0; mt < MT; mt++)
                #pragma unroll
                for (int nt = 0; nt < NT; nt++) {
                    mma_tf32(acc[mt][nt], ah[mt][0], ah[mt][1], ah[mt][2], ah[mt][3],
                             bh[nt][0], bh[nt][1]);
                    mma_tf32(acc[mt][nt], ah[mt][0], ah[mt][1], ah[mt][2], ah[mt][3],
                             bl[nt][0], bl[nt][1]);
                    mma_tf32(acc[mt][nt], al[mt][0], al[mt][1], al[mt][2], al[mt][3],
                             bh[nt][0], bh[nt][1]);
                }
        }
        __syncthreads();
    }

    // epilogue
    #pragma unroll
    for (int mt = 0; mt < MT; mt++) {
        int r0 = m0 + wm + mt * 16 + g;
        int r1 = r0 + 8;
        float d0 = 0.f, d1 = 0.f;
        if (GCN) { d0 = dz[r0]; d1 = dz[r1]; }
        #pragma unroll
        for (int nt = 0; nt < NT; nt++) {
            int c = n0 + wn + nt * 8 + tig * 2;
            float v00 = acc[mt][nt][0], v01 = acc[mt][nt][1];
            float v10 = acc[mt][nt][2], v11 = acc[mt][nt][3];
            if (GCN) {
                float2 z0 = *(const float2*)&B[(size_t)r0 * Ncols + c];
                float2 z1 = *(const float2*)&B[(size_t)r1 * Ncols + c];
                float bc0 = bias[c], bc1 = bias[c + 1];
                v00 = d0 * v00 + d0 * d0 * z0.x + bc0;
                v01 = d0 * v01 + d0 * d0 * z0.y + bc1;
                v10 = d1 * v10 + d1 * d1 * z1.x + bc0;
                v11 = d1 * v11 + d1 * d1 * z1.y + bc1;
                if (ACT) {
                    v00 = (v00 >= 0.f) ? v00 : 0.2f * v00;
                    v01 = (v01 >= 0.f) ? v01 : 0.2f * v01;
                    v10 = (v10 >= 0.f) ? v10 : 0.2f * v10;
                    v11 = (v11 >= 0.f) ? v11 : 0.2f * v11;
                }
            }
            *(float2*)&C[(size_t)r0 * Ncols + c] = make_float2(v00, v01);
            *(float2*)&C[(size_t)r1 * Ncols + c] = make_float2(v10, v11);
        }
    }
}

// ---------------- dynamic head params ---------------------------------------
__global__ void dcl_params_kernel(const int* __restrict__ task,
                                  const float* __restrict__ wc,
                                  const float* __restrict__ H3b,
                                  float* __restrict__ wb) {
    int z = blockIdx.x;
    int b = z & 63;
    const float* conv3 = H3b + (size_t)z * NN * H3;
    __shared__ float partial[256];
    __shared__ float xc[CDIM];
    int tid = threadIdx.x;
    int col = tid & 31, g = tid >> 5;
    float p = 0.f;
    for (int r = g; r < NN; r += 8) p += conv3[(size_t)r * H3 + col];
    partial[tid] = p;
    __syncthreads();
    if (tid < H3) {
        float sum = 0.f;
        #pragma unroll
        for (int gg = 0; gg < 8; gg++) sum += partial[gg * 32 + tid];
        xc[tid] = sum * (1.0f / (float)NN);
    }
    if (tid >= H3 && tid < CDIM) {
        xc[tid] = (task[b] == tid - H3) ? 1.f : 0.f;
    }
    __syncthreads();
    if (tid < PDIM) {
        float acc = 0.f;
        #pragma unroll
        for (int c = 0; c < CDIM; c++) acc += wc[tid * CDIM + c] * xc[c];
        wb[(size_t)z * PDIM + tid] = acc;
    }
}

// ---------------- cc kernel: logits + interleave scatter --------------------
__global__ void cc_kernel(const float* __restrict__ H4b,
                          const float* __restrict__ wb,
                          float* __restrict__ cc) {
    int z = blockIdx.x;
    int q = z >> 6, b = z & 63;
    __shared__ float flat[NN * OUTD];
    __shared__ float wm[64];
    __shared__ float bv[8];
    int tid = threadIdx.x;
    const float4* src4 = (const float4*)(H4b + (size_t)z * NN * OUTD);
    float4* dst4 = (float4*)flat;
    for (int i = tid; i < NN * OUTD / 4; i += 256) dst4[i] = src4[i];
    if (tid < 64) wm[tid] = wb[(size_t)z * PDIM + tid];
    if (tid < 8)  bv[tid] = wb[(size_t)z * PDIM + 64 + tid];
    __syncthreads();
    for (int f = tid; f < NN * OUTD; f += 256) {
        int r = f >> 9, c = f & 511;
        float v = bv[r];
        #pragma unroll
        for (int i = 0; i < 8; i++) v += wm[r * 8 + i] * flat[i * NN + c];
        int n = f >> 3, o = f & 7;
        int scc = n >> 8;
        int n2 = ((n & 255) << 1) | q;
        cc[(((size_t)(b * 2 + scc) * NN + n2) << 3) + o] = v;
    }
}

// ---------------- final: out = softplus(-(cc @ cc^T)) -----------------------
__global__ void final_kernel(const float* __restrict__ cc, float* __restrict__ out) {
    int zz = blockIdx.z;
    __shared__ float Msm[NN * OUTD];
    int tid = threadIdx.y * 16 + threadIdx.x;
    const float4* src = (const float4*)(cc + (size_t)zz * NN * OUTD);
    float4* dst = (float4*)Msm;
    for (int i = tid; i < NN * OUTD / 4; i += 256) dst[i] = src[i];
    __syncthreads();
    int i0 = blockIdx.y * 64 + threadIdx.y * 4;
    int j0 = blockIdx.x * 64 + threadIdx.x * 4;
    float ai[4][8], aj[4][8];
    #pragma unroll
    for (int m = 0; m < 4; m++)
        #pragma unroll
        for (int o = 0; o < 8; o++) ai[m][o] = Msm[(i0 + m) * 8 + o];
    #pragma unroll
    for (int n = 0; n < 4; n++)
        #pragma unroll
        for (int o = 0; o < 8; o++) aj[n][o] = Msm[(j0 + n) * 8 + o];
    float* ob = out + (size_t)zz * NN * NN;
    #pragma unroll
    for (int m = 0; m < 4; m++) {
        float r[4];
        #pragma unroll
        for (int n = 0; n < 4; n++) {
            float x = 0.f;
            #pragma unroll
            for (int o = 0; o < 8; o++) x += ai[m][o] * aj[n][o];
            r[n] = log1pf(expf(-fabsf(x))) + fmaxf(-x, 0.f);
        }
        *(float4*)(ob + (size_t)(i0 + m) * NN + j0) = make_float4(r[0], r[1], r[2], r[3]);
    }
}

// ---------------- host orchestration ----------------------------------------
// smem bytes: (BM*(BK+4) + BK*(BN+4)) float2s
#define SMEM_BYTES(BM, BN) (((BM) * 36 + 32 * ((BN) + 4)) * (int)sizeof(float2))

extern "C" void kernel_launch(void* const* d_in, const int* in_sizes, int n_in,
                              void* d_out, int out_size) {
    const float* adj  = (const float*)d_in[0];
    const int*   task = (const int*)d_in[1];
    const float* w[2][4];
    const float* bia[2][4];
    int idx = 2;
    for (int s = 0; s < 2; s++)
        for (int l = 0; l < 4; l++) {
            w[s][l]   = (const float*)d_in[idx++];
            bia[s][l] = (const float*)d_in[idx++];
        }
    const float* wc = (const float*)d_in[18];
    float* out = (float*)d_out;

    float* base = nullptr;
    cudaGetSymbolAddress((void**)&base, g_scratch);
    float* p_d  = base + OFF_D;
    float* p_H1 = base + OFF_H1;
    float* p_H2 = base + OFF_H2;
    float* p_H3 = base + OFF_H3;
    float* p_H4 = base + OFF_H4;
    float* p_Z  = base + OFF_Z;
    float* p_WB = base + OFF_WB;
    float* p_CC = base + OFF_CC;

    const size_t S1  = (size_t)BB * NN * H1;
    const size_t S2  = (size_t)BB * NN * H2;
    const size_t S3  = (size_t)BB * NN * H3;
    const size_t S4  = (size_t)BB * NN * OUTD;

    // >48KB dynamic smem opt-ins (idempotent)
    cudaFuncSetAttribute(
        (const void*)mma_gemm_kernel<64, 128, 2, 4, true, true, true>,
        cudaFuncAttributeMaxDynamicSharedMemorySize, SMEM_BYTES(64, 128));
    cudaFuncSetAttribute(
        (const void*)mma_gemm_kernel<128, 64, 4, 2, false, false, false>,
        cudaFuncAttributeMaxDynamicSharedMemorySize, SMEM_BYTES(128, 64));
    cudaFuncSetAttribute(
        (const void*)mma_gemm_kernel<128, 64, 4, 2, true, true, false>,
        cudaFuncAttributeMaxDynamicSharedMemorySize, SMEM_BYTES(128, 64));

    // 1) degree factors
    rowsum_kernel<<<NZ * NN / 8, 256>>>(adj, p_d);

    // 2) layer 1: H1 = leaky(feat @ w1 + b1), Z = w1 shared; single adj pass
    //    warp tile 32x32 (WGM=2, WGN=4)
    mma_gemm_kernel<64, 128, 2, 4, true, true, true>
        <<<dim3(8, 1, NZ), 256, SMEM_BYTES(64, 128)>>>(
            adj, w[0][0], w[1][0], p_d, bia[0][0], bia[1][0], p_H1, NN, H1, 0, 0);

    // 3) layer 2: Z = H1 @ w2 ; H2 = leaky(feat @ Z + b2)  (warp tile 32x32)
    mma_gemm_kernel<128, 64, 4, 2, false, false, false>
        <<<dim3(BB * NN / 128, 1, 2), 256, SMEM_BYTES(128, 64)>>>(
            p_H1, w[0][1], w[1][1], nullptr, nullptr, nullptr, p_Z, H1, H2, S1, S2);
    mma_gemm_kernel<128, 64, 4, 2, true, true, false>
        <<<dim3(4, 1, NZ), 256, SMEM_BYTES(128, 64)>>>(
            adj, p_Z, nullptr, p_d, bia[0][1], bia[1][1], p_H2, NN, H2, 0, 0);

    // 4) layer 3: Z = H2 @ w3 ; H3 = leaky(feat @ Z + b3)  (warp tile 32x32)
    mma_gemm_kernel<128, 32, 4, 1, false, false, false>
        <<<dim3(BB * NN / 128, 1, 2), 128, SMEM_BYTES(128, 32)>>>(
            p_H2, w[0][2], w[1][2], nullptr, nullptr, nullptr, p_Z, H2, H3, S2, S3);
    mma_gemm_kernel<128, 32, 4, 1, true, true, false>
        <<<dim3(4, 1, NZ), 128, SMEM_BYTES(128, 32)>>>(
            adj, p_Z, nullptr, p_d, bia[0][2], bia[1][2], p_H3, NN, H3, 0, 0);

    // 5) layer 4: Z = H3 @ w4 ; H4 = feat @ Z + b4 (no act)  (warp tile 32x8)
    mma_gemm_kernel<128, 8, 4, 1, false, false, false>
        <<<dim3(BB * NN / 128, 1, 2), 128, SMEM_BYTES(128, 8)>>>(
            p_H3, w[0][3], w[1][3], nullptr, nullptr, nullptr, p_Z, H3, OUTD, S3, S4);
    mma_gemm_kernel<128, 8, 4, 1, true, false, false>
        <<<dim3(4, 1, NZ), 128, SMEM_BYTES(128, 8)>>>(
            adj, p_Z, nullptr, p_d, bia[0][3], bia[1][3], p_H4, NN, OUTD, 0, 0);

    // 6) dynamic head params (uses conv3 = H3)
    dcl_params_kernel<<<NZ, 256>>>(task, wc, p_H3, p_WB);

    // 7) logits + interleave into cc
    cc_kernel<<<NZ, 256>>>(p_H4, p_WB, p_CC);

    // 8) final gram + softplus
    final_kernel<<<dim3(8, 8, NZ), dim3(16, 16)>>>(p_CC, out);

    (void)in_sizes; (void)n_in; (void)out_size;
}

// round 7
// speedup vs baseline: 4.9063x; 1.2795x over previous
#include <cuda_runtime.h>
#include <cuda_bf16.h>
#include <math.h>
#include <stdint.h>

#define NN 512
#define BB 64
#define NZ 128            // B*2 branch instances
#define H1 128
#define H2 64
#define H3 32
#define OUTD 8
#define CLS 16
#define PDIM 72           // OUT*OUT + OUT
#define CDIM 48           // H3 + CLS

// ---------------- scratch (single static device buffer, no allocs) ----------
static const size_t OFF_D   = 0;
static const size_t OFF_H1  = OFF_D   + (size_t)NZ*NN;
static const size_t OFF_H2  = OFF_H1  + (size_t)NZ*NN*H1;
static const size_t OFF_H3  = OFF_H2  + (size_t)NZ*NN*H2;
static const size_t OFF_H4  = OFF_H3  + (size_t)NZ*NN*H3;
static const size_t OFF_Z   = OFF_H4  + (size_t)NZ*NN*OUTD;
static const size_t OFF_WB  = OFF_Z   + (size_t)NZ*NN*H2;
static const size_t OFF_CC  = OFF_WB  + (size_t)NZ*PDIM;
static const size_t TOTAL_SCRATCH = OFF_CC + (size_t)BB*2*NN*OUTD;

__device__ float g_scratch[TOTAL_SCRATCH];

// ---------------- kernel 1: row-sum normalization factors -------------------
__global__ void rowsum_kernel(const float* __restrict__ adj, float* __restrict__ dout) {
    int gw   = (blockIdx.x * blockDim.x + threadIdx.x) >> 5;
    int lane = threadIdx.x & 31;
    int b2  = gw >> 9;
    int row = gw & 511;
    const float4* r4 = (const float4*)(adj + (size_t)b2 * NN * NN + (size_t)row * NN);
    float ssum = 0.f;
    #pragma unroll
    for (int k = lane; k < NN / 4; k += 32) {
        float4 v = r4[k];
        ssum += (v.x + v.y) + (v.z + v.w);
    }
    #pragma unroll
    for (int o = 16; o; o >>= 1) ssum += __shfl_xor_sync(0xffffffffu, ssum, o);
    if (lane == 0) {
        int s = b2 & 1, b = b2 >> 1;
        dout[(size_t)(s * BB + b) * NN + row] = rsqrtf(ssum + 1.0f);
    }
}

// ---------------- tf32 split helpers -----------------------------------------
__device__ __forceinline__ float tf32_rna(float v) {
    uint32_t u;
    asm("cvt.rna.tf32.f32 %0, %1;" : "=r"(u) : "f"(v));
    return __uint_as_float(u);
}
__device__ __forceinline__ void split_tf32(float v, float& hi, float& lo) {
    hi = tf32_rna(v);
    lo = tf32_rna(v - hi);
}
__device__ __forceinline__ void split4(float4 v, float4& h, float4& l) {
    split_tf32(v.x, h.x, l.x);
    split_tf32(v.y, h.y, l.y);
    split_tf32(v.z, h.z, l.z);
    split_tf32(v.w, h.w, l.w);
}
__device__ __forceinline__ void mma_tf32(float c[4],
    uint32_t a0, uint32_t a1, uint32_t a2, uint32_t a3,
    uint32_t b0, uint32_t b1) {
    asm volatile(
        "mma.sync.aligned.m16n8k8.row.col.f32.tf32.tf32.f32 "
        "{%0,%1,%2,%3}, {%4,%5,%6,%7}, {%8,%9}, {%0,%1,%2,%3};"
        : "+f"(c[0]), "+f"(c[1]), "+f"(c[2]), "+f"(c[3])
        : "r"(a0), "r"(a1), "r"(a2), "r"(a3), "r"(b0), "r"(b1));
}

// ---------------- unified split-TF32 MMA GEMM --------------------------------
// GCN=true : blockIdx.z = z in [0,128): s=z>>6, b=z&63
//            C_z = epi(adj_{b,s} @ (d_z ∘ Z_z)); epilogue adds d_i^2*Z + bias (+leaky)
//            A = adj (all-positive) -> ASPLIT=false: A stored as single tf32 hi,
//            2 MMAs per fragment pair (error ~1e-5, fine vs 1e-3 budget).
// GCN=false: blockIdx.z = s in {0,1}: C = A_s @ W_s, full 3-MMA split (ASPLIT=true).
template<int BM, int BN, int WGM, int WGN, bool GCN, bool ACT, bool ZSHARED, bool ASPLIT>
__global__ void __launch_bounds__(WGM*WGN*32, (WGM*WGN*32 == 256) ? 2 : 4)
mma_gemm_kernel(const float* __restrict__ Abase,
                const float* __restrict__ B0,
                const float* __restrict__ B1,
                const float* __restrict__ dbase,
                const float* __restrict__ bias0,
                const float* __restrict__ bias1,
                float* __restrict__ Cbase,
                int K, int Ncols, size_t sA, size_t sC)
{
    constexpr int BK = 32;
    constexpr int WM = BM / WGM, WN = BN / WGN;
    constexpr int MT = WM / 16, NT = WN / 8;
    constexpr int NTHREADS = WGM * WGN * 32;
    constexpr int BKP = BK + 4;          // A stride (elements); bank-safe
    constexpr int BNP = BN + 4;          // B float2 stride; bank-safe
    constexpr int A_TOT4 = BM * BK / 4;  // #float4 global loads
    constexpr int B_TOT4 = BK * BN / 4;
    constexpr int A_LD4 = (A_TOT4 + NTHREADS - 1) / NTHREADS;
    constexpr int B_LD4 = (B_TOT4 + NTHREADS - 1) / NTHREADS;
    constexpr int A_SM_F = BM * BKP * (ASPLIT ? 2 : 1);   // floats for A region

    extern __shared__ float smraw[];
    float2 (*Ahl)[BKP] = reinterpret_cast<float2(*)[BKP]>(smraw);        // ASPLIT
    float  (*Ah1)[BKP] = reinterpret_cast<float (*)[BKP]>(smraw);        // !ASPLIT
    float2 (*Bhl)[BNP] = reinterpret_cast<float2(*)[BNP]>(smraw + A_SM_F);

    const int z = blockIdx.z;
    const float* A; const float* B; const float* bias = nullptr;
    const float* dz = nullptr; float* C;
    int lda;
    if (GCN) {
        int s = z >> 6, b = z & 63;
        A   = Abase + (size_t)(b * 2 + s) * NN * NN; lda = NN;
        B   = ZSHARED ? (s ? B1 : B0) : B0 + (size_t)z * NN * Ncols;
        bias = s ? bias1 : bias0;
        dz  = dbase + (size_t)z * NN;
        C   = Cbase + (size_t)z * NN * Ncols;
    } else {
        A = Abase + (size_t)z * sA; lda = K;
        B = z ? B1 : B0;
        C = Cbase + (size_t)z * sC;
    }

    const int m0 = blockIdx.x * BM;
    const int n0 = blockIdx.y * BN;
    const int tid = threadIdx.x;
    const int w = tid >> 5, lane = tid & 31;
    const int g = lane >> 2, tig = lane & 3;
    const int wm = (w / WGN) * WM;
    const int wn = (w % WGN) * WN;

    float acc[MT][NT][4] = {};
    float4 aReg[A_LD4], bReg[B_LD4];

    // prologue: load first tile
    #pragma unroll
    for (int i = 0; i < A_LD4; i++) {
        int idx = tid + i * NTHREADS;
        if (idx < A_TOT4) {
            int r = idx / (BK / 4), c4 = (idx % (BK / 4)) * 4;
            aReg[i] = *(const float4*)&A[(size_t)(m0 + r) * lda + c4];
        }
    }
    #pragma unroll
    for (int i = 0; i < B_LD4; i++) {
        int idx = tid + i * NTHREADS;
        if (idx < B_TOT4) {
            int r = idx / (BN / 4), c4 = (idx % (BN / 4)) * 4;
            bReg[i] = *(const float4*)&B[(size_t)r * Ncols + n0 + c4];
        }
    }

    for (int k0 = 0; k0 < K; k0 += BK) {
        // store current tile into smem
        #pragma unroll
        for (int i = 0; i < A_LD4; i++) {
            int idx = tid + i * NTHREADS;
            if (idx < A_TOT4) {
                int r = idx / (BK / 4), c4 = (idx % (BK / 4)) * 4;
                if (ASPLIT) {
                    float4 h, l; split4(aReg[i], h, l);
                    *(float4*)&Ahl[r][c4]     = make_float4(h.x, l.x, h.y, l.y);
                    *(float4*)&Ahl[r][c4 + 2] = make_float4(h.z, l.z, h.w, l.w);
                } else {
                    float4 h;
                    h.x = tf32_rna(aReg[i].x); h.y = tf32_rna(aReg[i].y);
                    h.z = tf32_rna(aReg[i].z); h.w = tf32_rna(aReg[i].w);
                    *(float4*)&Ah1[r][c4] = h;
                }
            }
        }
        #pragma unroll
        for (int i = 0; i < B_LD4; i++) {
            int idx = tid + i * NTHREADS;
            if (idx < B_TOT4) {
                int r = idx / (BN / 4), c4 = (idx % (BN / 4)) * 4;
                float4 v = bReg[i];
                if (GCN) { float dk = dz[k0 + r]; v.x *= dk; v.y *= dk; v.z *= dk; v.w *= dk; }
                float4 h, l; split4(v, h, l);
                *(float4*)&Bhl[r][c4]     = make_float4(h.x, l.x, h.y, l.y);
                *(float4*)&Bhl[r][c4 + 2] = make_float4(h.z, l.z, h.w, l.w);
            }
        }
        __syncthreads();

        // prefetch next tile into registers (overlaps with compute below)
        if (k0 + BK < K) {
            #pragma unroll
            for (int i = 0; i < A_LD4; i++) {
                int idx = tid + i * NTHREADS;
                if (idx < A_TOT4) {
                    int r = idx / (BK / 4), c4 = (idx % (BK / 4)) * 4;
                    aReg[i] = *(const float4*)&A[(size_t)(m0 + r) * lda + (k0 + BK) + c4];
                }
            }
            #pragma unroll
            for (int i = 0; i < B_LD4; i++) {
                int idx = tid + i * NTHREADS;
                if (idx < B_TOT4) {
                    int r = idx / (BN / 4), c4 = (idx % (BN / 4)) * 4;
                    bReg[i] = *(const float4*)&B[(size_t)(k0 + BK + r) * Ncols + n0 + c4];
                }
            }
        }

        #pragma unroll
        for (int kk = 0; kk < BK; kk += 8) {
            uint32_t ah[MT][4], al[MT][4], bh[NT][2], bl[NT][2];
            #pragma unroll
            for (int mt = 0; mt < MT; mt++) {
                int rb = wm + mt * 16;
                if (ASPLIT) {
                    float2 p0 = Ahl[rb + g    ][kk + tig    ];
                    float2 p1 = Ahl[rb + g + 8][kk + tig    ];
                    float2 p2 = Ahl[rb + g    ][kk + tig + 4];
                    float2 p3 = Ahl[rb + g + 8][kk + tig + 4];
                    ah[mt][0] = __float_as_uint(p0.x); al[mt][0] = __float_as_uint(p0.y);
                    ah[mt][1] = __float_as_uint(p1.x); al[mt][1] = __float_as_uint(p1.y);
                    ah[mt][2] = __float_as_uint(p2.x); al[mt][2] = __float_as_uint(p2.y);
                    ah[mt][3] = __float_as_uint(p3.x); al[mt][3] = __float_as_uint(p3.y);
                } else {
                    ah[mt][0] = __float_as_uint(Ah1[rb + g    ][kk + tig    ]);
                    ah[mt][1] = __float_as_uint(Ah1[rb + g + 8][kk + tig    ]);
                    ah[mt][2] = __float_as_uint(Ah1[rb + g    ][kk + tig + 4]);
                    ah[mt][3] = __float_as_uint(Ah1[rb + g + 8][kk + tig + 4]);
                }
            }
            #pragma unroll
            for (int nt = 0; nt < NT; nt++) {
                int cb = wn + nt * 8 + g;
                float2 q0 = Bhl[kk + tig    ][cb];
                float2 q1 = Bhl[kk + tig + 4][cb];
                bh[nt][0] = __float_as_uint(q0.x); bl[nt][0] = __float_as_uint(q0.y);
                bh[nt][1] = __float_as_uint(q1.x); bl[nt][1] = __float_as_uint(q1.y);
            }
            #pragma unroll
            for (int mt = 0; mt < MT; mt++)
                #pragma unroll
                for (int nt = 0; nt < NT; nt++) {
                    mma_tf32(acc[mt][nt], ah[mt][0], ah[mt][1], ah[mt][2], ah[mt][3],
                             bh[nt][0], bh[nt][1]);
                    mma_tf32(acc[mt][nt], ah[mt][0], ah[mt][1], ah[mt][2], ah[mt][3],
                             bl[nt][0], bl[nt][1]);
                    if (ASPLIT)
                        mma_tf32(acc[mt][nt], al[mt][0], al[mt][1], al[mt][2], al[mt][3],
                                 bh[nt][0], bh[nt][1]);
                }
        }
        __syncthreads();
    }

    // epilogue
    #pragma unroll
    for (int mt = 0; mt < MT; mt++) {
        int r0 = m0 + wm + mt * 16 + g;
        int r1 = r0 + 8;
        float d0 = 0.f, d1 = 0.f;
        if (GCN) { d0 = dz[r0]; d1 = dz[r1]; }
        #pragma unroll
        for (int nt = 0; nt < NT; nt++) {
            int c = n0 + wn + nt * 8 + tig * 2;
            float v00 = acc[mt][nt][0], v01 = acc[mt][nt][1];
            float v10 = acc[mt][nt][2], v11 = acc[mt][nt][3];
            if (GCN) {
                float2 z0 = *(const float2*)&B[(size_t)r0 * Ncols + c];
                float2 z1 = *(const float2*)&B[(size_t)r1 * Ncols + c];
                float bc0 = bias[c], bc1 = bias[c + 1];
                v00 = d0 * v00 + d0 * d0 * z0.x + bc0;
                v01 = d0 * v01 + d0 * d0 * z0.y + bc1;
                v10 = d1 * v10 + d1 * d1 * z1.x + bc0;
                v11 = d1 * v11 + d1 * d1 * z1.y + bc1;
                if (ACT) {
                    v00 = (v00 >= 0.f) ? v00 : 0.2f * v00;
                    v01 = (v01 >= 0.f) ? v01 : 0.2f * v01;
                    v10 = (v10 >= 0.f) ? v10 : 0.2f * v10;
                    v11 = (v11 >= 0.f) ? v11 : 0.2f * v11;
                }
            }
            *(float2*)&C[(size_t)r0 * Ncols + c] = make_float2(v00, v01);
            *(float2*)&C[(size_t)r1 * Ncols + c] = make_float2(v10, v11);
        }
    }
}

// ---------------- dynamic head params ---------------------------------------
__global__ void dcl_params_kernel(const int* __restrict__ task,
                                  const float* __restrict__ wc,
                                  const float* __restrict__ H3b,
                                  float* __restrict__ wb) {
    int z = blockIdx.x;
    int b = z & 63;
    const float* conv3 = H3b + (size_t)z * NN * H3;
    __shared__ float partial[256];
    __shared__ float xc[CDIM];
    int tid = threadIdx.x;
    int col = tid & 31, g = tid >> 5;
    float p = 0.f;
    for (int r = g; r < NN; r += 8) p += conv3[(size_t)r * H3 + col];
    partial[tid] = p;
    __syncthreads();
    if (tid < H3) {
        float sum = 0.f;
        #pragma unroll
        for (int gg = 0; gg < 8; gg++) sum += partial[gg * 32 + tid];
        xc[tid] = sum * (1.0f / (float)NN);
    }
    if (tid >= H3 && tid < CDIM) {
        xc[tid] = (task[b] == tid - H3) ? 1.f : 0.f;
    }
    __syncthreads();
    if (tid < PDIM) {
        float acc = 0.f;
        #pragma unroll
        for (int c = 0; c < CDIM; c++) acc += wc[tid * CDIM + c] * xc[c];
        wb[(size_t)z * PDIM + tid] = acc;
    }
}

// ---------------- cc kernel: logits + interleave scatter --------------------
__global__ void cc_kernel(const float* __restrict__ H4b,
                          const float* __restrict__ wb,
                          float* __restrict__ cc) {
    int z = blockIdx.x;
    int q = z >> 6, b = z & 63;
    __shared__ float flat[NN * OUTD];
    __shared__ float wm[64];
    __shared__ float bv[8];
    int tid = threadIdx.x;
    const float4* src4 = (const float4*)(H4b + (size_t)z * NN * OUTD);
    float4* dst4 = (float4*)flat;
    for (int i = tid; i < NN * OUTD / 4; i += 256) dst4[i] = src4[i];
    if (tid < 64) wm[tid] = wb[(size_t)z * PDIM + tid];
    if (tid < 8)  bv[tid] = wb[(size_t)z * PDIM + 64 + tid];
    __syncthreads();
    for (int f = tid; f < NN * OUTD; f += 256) {
        int r = f >> 9, c = f & 511;
        float v = bv[r];
        #pragma unroll
        for (int i = 0; i < 8; i++) v += wm[r * 8 + i] * flat[i * NN + c];
        int n = f >> 3, o = f & 7;
        int scc = n >> 8;
        int n2 = ((n & 255) << 1) | q;
        cc[(((size_t)(b * 2 + scc) * NN + n2) << 3) + o] = v;
    }
}

// ---------------- final: out = softplus(-(cc @ cc^T)) -----------------------
__global__ void final_kernel(const float* __restrict__ cc, float* __restrict__ out) {
    int zz = blockIdx.z;
    __shared__ float Msm[NN * OUTD];
    int tid = threadIdx.y * 16 + threadIdx.x;
    const float4* src = (const float4*)(cc + (size_t)zz * NN * OUTD);
    float4* dst = (float4*)Msm;
    for (int i = tid; i < NN * OUTD / 4; i += 256) dst[i] = src[i];
    __syncthreads();
    int i0 = blockIdx.y * 64 + threadIdx.y * 4;
    int j0 = blockIdx.x * 64 + threadIdx.x * 4;
    float ai[4][8], aj[4][8];
    #pragma unroll
    for (int m = 0; m < 4; m++)
        #pragma unroll
        for (int o = 0; o < 8; o++) ai[m][o] = Msm[(i0 + m) * 8 + o];
    #pragma unroll
    for (int n = 0; n < 4; n++)
        #pragma unroll
        for (int o = 0; o < 8; o++) aj[n][o] = Msm[(j0 + n) * 8 + o];
    float* ob = out + (size_t)zz * NN * NN;
    #pragma unroll
    for (int m = 0; m < 4; m++) {
        float r[4];
        #pragma unroll
        for (int n = 0; n < 4; n++) {
            float x = 0.f;
            #pragma unroll
            for (int o = 0; o < 8; o++) x += ai[m][o] * aj[n][o];
            // softplus(-x) = log(1 + exp(-|x|)) + max(-x, 0)  (fast intrinsics)
            r[n] = __logf(1.0f + __expf(-fabsf(x))) + fmaxf(-x, 0.f);
        }
        *(float4*)(ob + (size_t)(i0 + m) * NN + j0) = make_float4(r[0], r[1], r[2], r[3]);
    }
}

// ---------------- host orchestration ----------------------------------------
// smem bytes: A region + B region
#define SMEM_BYTES_SPLIT(BM, BN) (((BM) * 36 * 2 + 32 * ((BN) + 4) * 2) * 4)
#define SMEM_BYTES_HI(BM, BN)    (((BM) * 36     + 32 * ((BN) + 4) * 2) * 4)

extern "C" void kernel_launch(void* const* d_in, const int* in_sizes, int n_in,
                              void* d_out, int out_size) {
    const float* adj  = (const float*)d_in[0];
    const int*   task = (const int*)d_in[1];
    const float* w[2][4];
    const float* bia[2][4];
    int idx = 2;
    for (int s = 0; s < 2; s++)
        for (int l = 0; l < 4; l++) {
            w[s][l]   = (const float*)d_in[idx++];
            bia[s][l] = (const float*)d_in[idx++];
        }
    const float* wc = (const float*)d_in[18];
    float* out = (float*)d_out;

    float* base = nullptr;
    cudaGetSymbolAddress((void**)&base, g_scratch);
    float* p_d  = base + OFF_D;
    float* p_H1 = base + OFF_H1;
    float* p_H2 = base + OFF_H2;
    float* p_H3 = base + OFF_H3;
    float* p_H4 = base + OFF_H4;
    float* p_Z  = base + OFF_Z;
    float* p_WB = base + OFF_WB;
    float* p_CC = base + OFF_CC;

    const size_t S1  = (size_t)BB * NN * H1;
    const size_t S2  = (size_t)BB * NN * H2;
    const size_t S3  = (size_t)BB * NN * H3;
    const size_t S4  = (size_t)BB * NN * OUTD;

    // >48KB dynamic smem opt-in (only the 128x64 full-split plain GEMM needs it)
    cudaFuncSetAttribute(
        (const void*)mma_gemm_kernel<128, 64, 4, 2, false, false, false, true>,
        cudaFuncAttributeMaxDynamicSharedMemorySize, SMEM_BYTES_SPLIT(128, 64));

    // 1) degree factors
    rowsum_kernel<<<NZ * NN / 8, 256>>>(adj, p_d);

    // 2) layer 1: H1 = leaky(feat @ w1 + b1), Z = w1 shared; single adj pass
    mma_gemm_kernel<64, 128, 2, 4, true, true, true, false>
        <<<dim3(8, 1, NZ), 256, SMEM_BYTES_HI(64, 128)>>>(
            adj, w[0][0], w[1][0], p_d, bia[0][0], bia[1][0], p_H1, NN, H1, 0, 0);

    // 3) layer 2: Z = H1 @ w2 ; H2 = leaky(feat @ Z + b2)
    mma_gemm_kernel<128, 64, 4, 2, false, false, false, true>
        <<<dim3(BB * NN / 128, 1, 2), 256, SMEM_BYTES_SPLIT(128, 64)>>>(
            p_H1, w[0][1], w[1][1], nullptr, nullptr, nullptr, p_Z, H1, H2, S1, S2);
    mma_gemm_kernel<128, 64, 4, 2, true, true, false, false>
        <<<dim3(4, 1, NZ), 256, SMEM_BYTES_HI(128, 64)>>>(
            adj, p_Z, nullptr, p_d, bia[0][1], bia[1][1], p_H2, NN, H2, 0, 0);

    // 4) layer 3: Z = H2 @ w3 ; H3 = leaky(feat @ Z + b3)
    mma_gemm_kernel<128, 32, 4, 1, false, false, false, true>
        <<<dim3(BB * NN / 128, 1, 2), 128, SMEM_BYTES_SPLIT(128, 32)>>>(
            p_H2, w[0][2], w[1][2], nullptr, nullptr, nullptr, p_Z, H2, H3, S2, S3);
    mma_gemm_kernel<128, 32, 4, 1, true, true, false, false>
        <<<dim3(4, 1, NZ), 128, SMEM_BYTES_HI(128, 32)>>>(
            adj, p_Z, nullptr, p_d, bia[0][2], bia[1][2], p_H3, NN, H3, 0, 0);

    // 5) layer 4: Z = H3 @ w4 ; H4 = feat @ Z + b4 (no act)
    mma_gemm_kernel<128, 8, 4, 1, false, false, false, true>
        <<<dim3(BB * NN / 128, 1, 2), 128, SMEM_BYTES_SPLIT(128, 8)>>>(
            p_H3, w[0][3], w[1][3], nullptr, nullptr, nullptr, p_Z, H3, OUTD, S3, S4);
    mma_gemm_kernel<128, 8, 4, 1, true, false, false, false>
        <<<dim3(4, 1, NZ), 128, SMEM_BYTES_HI(128, 8)>>>(
            adj, p_Z, nullptr, p_d, bia[0][3], bia[1][3], p_H4, NN, OUTD, 0, 0);

    // 6) dynamic head params (uses conv3 = H3)
    dcl_params_kernel<<<NZ, 256>>>(task, wc, p_H3, p_WB);

    // 7) logits + interleave into cc
    cc_kernel<<<NZ, 256>>>(p_H4, p_WB, p_CC);

    // 8) final gram + softplus
    final_kernel<<<dim3(8, 8, NZ), dim3(16, 16)>>>(p_CC, out);

    (void)in_sizes; (void)n_in; (void)out_size;
}

// round 8
// speedup vs baseline: 5.9396x; 1.2106x over previous
#include <cuda_runtime.h>
#include <cuda_bf16.h>
#include <math.h>
#include <stdint.h>

#define NN 512
#define BB 64
#define NZ 128            // B*2 branch instances
#define H1 128
#define H2 64
#define H3 32
#define OUTD 8
#define CLS 16
#define PDIM 72           // OUT*OUT + OUT
#define CDIM 48           // H3 + CLS

// ---------------- scratch (static device buffers, no allocs) ----------------
static const size_t OFF_D   = 0;
static const size_t OFF_H1  = OFF_D   + (size_t)NZ*NN;
static const size_t OFF_H2  = OFF_H1  + (size_t)NZ*NN*H1;
static const size_t OFF_H3  = OFF_H2  + (size_t)NZ*NN*H2;
static const size_t OFF_H4  = OFF_H3  + (size_t)NZ*NN*H3;
static const size_t OFF_Z   = OFF_H4  + (size_t)NZ*NN*OUTD;
static const size_t OFF_WB  = OFF_Z   + (size_t)NZ*NN*H2;
static const size_t OFF_CC  = OFF_WB  + (size_t)NZ*PDIM;
static const size_t TOTAL_SCRATCH = OFF_CC + (size_t)BB*2*NN*OUTD;

__device__ float g_scratch[TOTAL_SCRATCH];
// adj as packed bf16x2 (k-pairs): [b2][512][256] uint32
__device__ uint32_t g_adjb[(size_t)NZ * NN * (NN / 2)];

// ---------------- bf16 helpers ------------------------------------------------
__device__ __forceinline__ uint32_t pack_bf16(float a, float b) {
    __nv_bfloat162 t = __floats2bfloat162_rn(a, b);   // .x = a (low), .y = b (high)
    return *reinterpret_cast<uint32_t*>(&t);
}
__device__ __forceinline__ void split_bf16(float v, float& hi, float& lo) {
    __nv_bfloat16 h = __float2bfloat16(v);
    hi = __bfloat162float(h);
    lo = v - hi;   // bf16 conversion of lo happens at pack time
}

// ---------------- tf32 split helpers (plain GEMMs) ---------------------------
__device__ __forceinline__ float tf32_rna(float v) {
    uint32_t u;
    asm("cvt.rna.tf32.f32 %0, %1;" : "=r"(u) : "f"(v));
    return __uint_as_float(u);
}
__device__ __forceinline__ void split_tf32(float v, float& hi, float& lo) {
    hi = tf32_rna(v);
    lo = tf32_rna(v - hi);
}
__device__ __forceinline__ void split4(float4 v, float4& h, float4& l) {
    split_tf32(v.x, h.x, l.x);
    split_tf32(v.y, h.y, l.y);
    split_tf32(v.z, h.z, l.z);
    split_tf32(v.w, h.w, l.w);
}
__device__ __forceinline__ void mma_tf32(float c[4],
    uint32_t a0, uint32_t a1, uint32_t a2, uint32_t a3,
    uint32_t b0, uint32_t b1) {
    asm volatile(
        "mma.sync.aligned.m16n8k8.row.col.f32.tf32.tf32.f32 "
        "{%0,%1,%2,%3}, {%4,%5,%6,%7}, {%8,%9}, {%0,%1,%2,%3};"
        : "+f"(c[0]), "+f"(c[1]), "+f"(c[2]), "+f"(c[3])
        : "r"(a0), "r"(a1), "r"(a2), "r"(a3), "r"(b0), "r"(b1));
}
__device__ __forceinline__ void mma_bf16(float c[4],
    uint32_t a0, uint32_t a1, uint32_t a2, uint32_t a3,
    uint32_t b0, uint32_t b1) {
    asm volatile(
        "mma.sync.aligned.m16n8k16.row.col.f32.bf16.bf16.f32 "
        "{%0,%1,%2,%3}, {%4,%5,%6,%7}, {%8,%9}, {%0,%1,%2,%3};"
        : "+f"(c[0]), "+f"(c[1]), "+f"(c[2]), "+f"(c[3])
        : "r"(a0), "r"(a1), "r"(a2), "r"(a3), "r"(b0), "r"(b1));
}

// ---------------- preprocess: rowsum (d) + adj -> packed bf16 -----------------
// warp per (b2, row): d[z][row] = rsqrt(1 + rowsum); adjb packed bf16x2.
__global__ void prep_kernel(const float* __restrict__ adj,
                            float* __restrict__ dout,
                            uint32_t* __restrict__ adjb) {
    int gw   = (blockIdx.x * blockDim.x + threadIdx.x) >> 5;
    int lane = threadIdx.x & 31;
    int b2  = gw >> 9;
    int row = gw & 511;
    const float4* r4 = (const float4*)(adj + (size_t)b2 * NN * NN + (size_t)row * NN);
    uint2* w2 = (uint2*)(adjb + (size_t)b2 * NN * (NN / 2) + (size_t)row * (NN / 2));
    float ssum = 0.f;
    #pragma unroll
    for (int j = lane; j < NN / 4; j += 32) {
        float4 v = r4[j];
        ssum += (v.x + v.y) + (v.z + v.w);
        uint2 p;
        p.x = pack_bf16(v.x, v.y);
        p.y = pack_bf16(v.z, v.w);
        w2[j] = p;
    }
    #pragma unroll
    for (int o = 16; o; o >>= 1) ssum += __shfl_xor_sync(0xffffffffu, ssum, o);
    if (lane == 0) {
        int s = b2 & 1, b = b2 >> 1;
        dout[(size_t)(s * BB + b) * NN + row] = rsqrtf(ssum + 1.0f);
    }
}

// ---------------- GCN layer: bf16 MMA (m16n8k16) ------------------------------
// blockIdx.z = z in [0,128): s=z>>6, b=z&63, adjb index b2=b*2+s
// C_z = epi(adj @ (d∘Z)); epilogue adds d_i^2*Z_i + bias (+leaky)
// A = adj bf16 (hi only); B split bf16 hi+lo -> 2 MMAs per k16.
template<int BM, int BN, int WGM, int WGN, bool ACT, bool ZSHARED>
__global__ void __launch_bounds__(WGM*WGN*32)
gcn_bf16_kernel(const uint32_t* __restrict__ Adjb,
                const float* __restrict__ B0,
                const float* __restrict__ B1,
                const float* __restrict__ dbase,
                const float* __restrict__ bias0,
                const float* __restrict__ bias1,
                float* __restrict__ Cbase,
                int Ncols)
{
    constexpr int BK = 32;
    constexpr int KP = BK / 2;           // 16 k-pairs per tile
    constexpr int WM = BM / WGM, WN = BN / WGN;
    constexpr int MT = WM / 16, NT = WN / 8;
    constexpr int NTHREADS = WGM * WGN * 32;
    constexpr int ASTRIDE = 24;          // uint32 per A row (16 pairs + 8 pad)
    constexpr int BNP = (BN == 8) ? 8 : BN + 8;
    constexpr int A_TOTU = BM * 4;       // uint4 loads per tile (4 pairs each)
    constexpr int A_LDU = (A_TOTU + NTHREADS - 1) / NTHREADS;
    constexpr int B_TOTP = KP * BN;      // B k-pair elements per tile
    constexpr int B_LDP = (B_TOTP + NTHREADS - 1) / NTHREADS;

    __shared__ uint32_t Asm[BM][ASTRIDE];
    __shared__ uint32_t Bh[KP][BNP];
    __shared__ uint32_t Bl[KP][BNP];

    const int z = blockIdx.z;
    const int s = z >> 6, b = z & 63;
    const uint32_t* A = Adjb + (size_t)(b * 2 + s) * NN * (NN / 2);
    const float* B    = ZSHARED ? (s ? B1 : B0) : B0 + (size_t)z * NN * Ncols;
    const float* bias = s ? bias1 : bias0;
    const float* dz   = dbase + (size_t)z * NN;
    float* C          = Cbase + (size_t)z * NN * Ncols;

    const int m0 = blockIdx.x * BM;
    const int tid = threadIdx.x;
    const int w = tid >> 5, lane = tid & 31;
    const int g = lane >> 2, tig = lane & 3;
    const int wm = (w / WGN) * WM;
    const int wn = (w % WGN) * WN;

    float acc[MT][NT][4] = {};
    uint4  aU[A_LDU];
    float2 bF[B_LDP];

    // prologue: load first k-tile
    #pragma unroll
    for (int i = 0; i < A_LDU; i++) {
        int idx = tid + i * NTHREADS;
        if (idx < A_TOTU) {
            int r = idx >> 2, q = idx & 3;
            aU[i] = *(const uint4*)&A[(size_t)(m0 + r) * (NN / 2) + q * 4];
        }
    }
    #pragma unroll
    for (int i = 0; i < B_LDP; i++) {
        int e = tid + i * NTHREADS;
        if (e < B_TOTP) {
            int p = e / BN, n = e % BN;
            int k = 2 * p;
            bF[i].x = B[(size_t)k * Ncols + n] * dz[k];
            bF[i].y = B[(size_t)(k + 1) * Ncols + n] * dz[k + 1];
        }
    }

    for (int k0 = 0; k0 < NN; k0 += BK) {
        // store A tile with k-pair permutation (pairs tig / tig+4 adjacent)
        #pragma unroll
        for (int i = 0; i < A_LDU; i++) {
            int idx = tid + i * NTHREADS;
            if (idx < A_TOTU) {
                int r = idx >> 2, q = idx & 3;
                int base = (q >> 1) * 8 + (q & 1);
                Asm[r][base]     = aU[i].x;
                Asm[r][base + 2] = aU[i].y;
                Asm[r][base + 4] = aU[i].z;
                Asm[r][base + 6] = aU[i].w;
            }
        }
        // store B tile split into bf16 hi/lo pairs
        #pragma unroll
        for (int i = 0; i < B_LDP; i++) {
            int e = tid + i * NTHREADS;
            if (e < B_TOTP) {
                int p = e / BN, n = e % BN;
                float h0, l0, h1, l1;
                split_bf16(bF[i].x, h0, l0);
                split_bf16(bF[i].y, h1, l1);
                Bh[p][n] = pack_bf16(h0, h1);
                Bl[p][n] = pack_bf16(l0, l1);
            }
        }
        __syncthreads();

        // prefetch next k-tile (overlaps with MMAs below)
        if (k0 + BK < NN) {
            #pragma unroll
            for (int i = 0; i < A_LDU; i++) {
                int idx = tid + i * NTHREADS;
                if (idx < A_TOTU) {
                    int r = idx >> 2, q = idx & 3;
                    aU[i] = *(const uint4*)&A[(size_t)(m0 + r) * (NN / 2) + (k0 + BK) / 2 + q * 4];
                }
            }
            #pragma unroll
            for (int i = 0; i < B_LDP; i++) {
                int e = tid + i * NTHREADS;
                if (e < B_TOTP) {
                    int p = e / BN, n = e % BN;
                    int k = k0 + BK + 2 * p;
                    bF[i].x = B[(size_t)k * Ncols + n] * dz[k];
                    bF[i].y = B[(size_t)(k + 1) * Ncols + n] * dz[k + 1];
                }
            }
        }

        #pragma unroll
        for (int kk = 0; kk < 2; kk++) {        // two k16 steps
            uint32_t a0[MT], a1[MT], a2[MT], a3[MT];
            uint32_t bh0[NT], bh1[NT], bl0[NT], bl1[NT];
            #pragma unroll
            for (int mt = 0; mt < MT; mt++) {
                int r0 = wm + mt * 16 + g;
                uint2 u0 = *(const uint2*)&Asm[r0][kk * 8 + 2 * tig];
                uint2 u1 = *(const uint2*)&Asm[r0 + 8][kk * 8 + 2 * tig];
                a0[mt] = u0.x; a2[mt] = u0.y;
                a1[mt] = u1.x; a3[mt] = u1.y;
            }
            #pragma unroll
            for (int nt = 0; nt < NT; nt++) {
                int cb = wn + nt * 8 + g;
                bh0[nt] = Bh[kk * 8 + tig][cb];
                bh1[nt] = Bh[kk * 8 + tig + 4][cb];
                bl0[nt] = Bl[kk * 8 + tig][cb];
                bl1[nt] = Bl[kk * 8 + tig + 4][cb];
            }
            #pragma unroll
            for (int mt = 0; mt < MT; mt++)
                #pragma unroll
                for (int nt = 0; nt < NT; nt++) {
                    mma_bf16(acc[mt][nt], a0[mt], a1[mt], a2[mt], a3[mt],
                             bh0[nt], bh1[nt]);
                    mma_bf16(acc[mt][nt], a0[mt], a1[mt], a2[mt], a3[mt],
                             bl0[nt], bl1[nt]);
                }
        }
        __syncthreads();
    }

    // epilogue: v = d_i * acc + d_i^2 * Z_i + bias (+leaky)
    #pragma unroll
    for (int mt = 0; mt < MT; mt++) {
        int r0 = m0 + wm + mt * 16 + g;
        int r1 = r0 + 8;
        float d0 = dz[r0], d1 = dz[r1];
        #pragma unroll
        for (int nt = 0; nt < NT; nt++) {
            int c = wn + nt * 8 + tig * 2;
            float2 z0 = *(const float2*)&B[(size_t)r0 * Ncols + c];
            float2 z1 = *(const float2*)&B[(size_t)r1 * Ncols + c];
            float bc0 = bias[c], bc1 = bias[c + 1];
            float v00 = d0 * acc[mt][nt][0] + d0 * d0 * z0.x + bc0;
            float v01 = d0 * acc[mt][nt][1] + d0 * d0 * z0.y + bc1;
            float v10 = d1 * acc[mt][nt][2] + d1 * d1 * z1.x + bc0;
            float v11 = d1 * acc[mt][nt][3] + d1 * d1 * z1.y + bc1;
            if (ACT) {
                v00 = (v00 >= 0.f) ? v00 : 0.2f * v00;
                v01 = (v01 >= 0.f) ? v01 : 0.2f * v01;
                v10 = (v10 >= 0.f) ? v10 : 0.2f * v10;
                v11 = (v11 >= 0.f) ? v11 : 0.2f * v11;
            }
            *(float2*)&C[(size_t)r0 * Ncols + c] = make_float2(v00, v01);
            *(float2*)&C[(size_t)r1 * Ncols + c] = make_float2(v10, v11);
        }
    }
}

// ---------------- plain split-TF32 MMA GEMM: C = A_s @ W_s --------------------
template<int BM, int BN, int WGM, int WGN>
__global__ void __launch_bounds__(WGM*WGN*32, (WGM*WGN*32 == 256) ? 2 : 4)
plain_gemm_kernel(const float* __restrict__ Abase,
                  const float* __restrict__ B0,
                  const float* __restrict__ B1,
                  float* __restrict__ Cbase,
                  int K, int Ncols, size_t sA, size_t sC)
{
    constexpr int BK = 32;
    constexpr int WM = BM / WGM, WN = BN / WGN;
    constexpr int MT = WM / 16, NT = WN / 8;
    constexpr int NTHREADS = WGM * WGN * 32;
    constexpr int BKP = BK + 4;
    constexpr int BNP = BN + 4;
    constexpr int A_TOT4 = BM * BK / 4;
    constexpr int B_TOT4 = BK * BN / 4;
    constexpr int A_LD4 = (A_TOT4 + NTHREADS - 1) / NTHREADS;
    constexpr int B_LD4 = (B_TOT4 + NTHREADS - 1) / NTHREADS;
    constexpr int A_SM_F = BM * BKP * 2;

    extern __shared__ float smraw[];
    float2 (*Ahl)[BKP] = reinterpret_cast<float2(*)[BKP]>(smraw);
    float2 (*Bhl)[BNP] = reinterpret_cast<float2(*)[BNP]>(smraw + A_SM_F);

    const int z = blockIdx.z;
    const float* A = Abase + (size_t)z * sA;
    const float* B = z ? B1 : B0;
    float* C = Cbase + (size_t)z * sC;

    const int m0 = blockIdx.x * BM;
    const int tid = threadIdx.x;
    const int w = tid >> 5, lane = tid & 31;
    const int g = lane >> 2, tig = lane & 3;
    const int wm = (w / WGN) * WM;
    const int wn = (w % WGN) * WN;

    float acc[MT][NT][4] = {};
    float4 aReg[A_LD4], bReg[B_LD4];

    #pragma unroll
    for (int i = 0; i < A_LD4; i++) {
        int idx = tid + i * NTHREADS;
        if (idx < A_TOT4) {
            int r = idx / (BK / 4), c4 = (idx % (BK / 4)) * 4;
            aReg[i] = *(const float4*)&A[(size_t)(m0 + r) * K + c4];
        }
    }
    #pragma unroll
    for (int i = 0; i < B_LD4; i++) {
        int idx = tid + i * NTHREADS;
        if (idx < B_TOT4) {
            int r = idx / (BN / 4), c4 = (idx % (BN / 4)) * 4;
            bReg[i] = *(const float4*)&B[(size_t)r * Ncols + c4];
        }
    }

    for (int k0 = 0; k0 < K; k0 += BK) {
        #pragma unroll
        for (int i = 0; i < A_LD4; i++) {
            int idx = tid + i * NTHREADS;
            if (idx < A_TOT4) {
                int r = idx / (BK / 4), c4 = (idx % (BK / 4)) * 4;
                float4 h, l; split4(aReg[i], h, l);
                *(float4*)&Ahl[r][c4]     = make_float4(h.x, l.x, h.y, l.y);
                *(float4*)&Ahl[r][c4 + 2] = make_float4(h.z, l.z, h.w, l.w);
            }
        }
        #pragma unroll
        for (int i = 0; i < B_LD4; i++) {
            int idx = tid + i * NTHREADS;
            if (idx < B_TOT4) {
                int r = idx / (BN / 4), c4 = (idx % (BN / 4)) * 4;
                float4 h, l; split4(bReg[i], h, l);
                *(float4*)&Bhl[r][c4]     = make_float4(h.x, l.x, h.y, l.y);
                *(float4*)&Bhl[r][c4 + 2] = make_float4(h.z, l.z, h.w, l.w);
            }
        }
        __syncthreads();

        if (k0 + BK < K) {
            #pragma unroll
            for (int i = 0; i < A_LD4; i++) {
                int idx = tid + i * NTHREADS;
                if (idx < A_TOT4) {
                    int r = idx / (BK / 4), c4 = (idx % (BK / 4)) * 4;
                    aReg[i] = *(const float4*)&A[(size_t)(m0 + r) * K + (k0 + BK) + c4];
                }
            }
            #pragma unroll
            for (int i = 0; i < B_LD4; i++) {
                int idx = tid + i * NTHREADS;
                if (idx < B_TOT4) {
                    int r = idx / (BN / 4), c4 = (idx % (BN / 4)) * 4;
                    bReg[i] = *(const float4*)&B[(size_t)(k0 + BK + r) * Ncols + c4];
                }
            }
        }

        #pragma unroll
        for (int kk = 0; kk < BK; kk += 8) {
            uint32_t ah[MT][4], al[MT][4], bh[NT][2], bl[NT][2];
            #pragma unroll
            for (int mt = 0; mt < MT; mt++) {
                int rb = wm + mt * 16;
                float2 p0 = Ahl[rb + g    ][kk + tig    ];
                float2 p1 = Ahl[rb + g + 8][kk + tig    ];
                float2 p2 = Ahl[rb + g    ][kk + tig + 4];
                float2 p3 = Ahl[rb + g + 8][kk + tig + 4];
                ah[mt][0] = __float_as_uint(p0.x); al[mt][0] = __float_as_uint(p0.y);
                ah[mt][1] = __float_as_uint(p1.x); al[mt][1] = __float_as_uint(p1.y);
                ah[mt][2] = __float_as_uint(p2.x); al[mt][2] = __float_as_uint(p2.y);
                ah[mt][3] = __float_as_uint(p3.x); al[mt][3] = __float_as_uint(p3.y);
            }
            #pragma unroll
            for (int nt = 0; nt < NT; nt++) {
                int cb = wn + nt * 8 + g;
                float2 q0 = Bhl[kk + tig    ][cb];
                float2 q1 = Bhl[kk + tig + 4][cb];
                bh[nt][0] = __float_as_uint(q0.x); bl[nt][0] = __float_as_uint(q0.y);
                bh[nt][1] = __float_as_uint(q1.x); bl[nt][1] = __float_as_uint(q1.y);
            }
            #pragma unroll
            for (int mt = 0; mt < MT; mt++)
                #pragma unroll
                for (int nt = 0; nt < NT; nt++) {
                    mma_tf32(acc[mt][nt], ah[mt][0], ah[mt][1], ah[mt][2], ah[mt][3],
                             bh[nt][0], bh[nt][1]);
                    mma_tf32(acc[mt][nt], ah[mt][0], ah[mt][1], ah[mt][2], ah[mt][3],
                             bl[nt][0], bl[nt][1]);
                    mma_tf32(acc[mt][nt], al[mt][0], al[mt][1], al[mt][2], al[mt][3],
                             bh[nt][0], bh[nt][1]);
                }
        }
        __syncthreads();
    }

    #pragma unroll
    for (int mt = 0; mt < MT; mt++) {
        int r0 = m0 + wm + mt * 16 + g;
        int r1 = r0 + 8;
        #pragma unroll
        for (int nt = 0; nt < NT; nt++) {
            int c = wn + nt * 8 + tig * 2;
            *(float2*)&C[(size_t)r0 * Ncols + c] = make_float2(acc[mt][nt][0], acc[mt][nt][1]);
            *(float2*)&C[(size_t)r1 * Ncols + c] = make_float2(acc[mt][nt][2], acc[mt][nt][3]);
        }
    }
}

// ---------------- dynamic head params ---------------------------------------
__global__ void dcl_params_kernel(const int* __restrict__ task,
                                  const float* __restrict__ wc,
                                  const float* __restrict__ H3b,
                                  float* __restrict__ wb) {
    int z = blockIdx.x;
    int b = z & 63;
    const float* conv3 = H3b + (size_t)z * NN * H3;
    __shared__ float partial[256];
    __shared__ float xc[CDIM];
    int tid = threadIdx.x;
    int col = tid & 31, g = tid >> 5;
    float p = 0.f;
    for (int r = g; r < NN; r += 8) p += conv3[(size_t)r * H3 + col];
    partial[tid] = p;
    __syncthreads();
    if (tid < H3) {
        float sum = 0.f;
        #pragma unroll
        for (int gg = 0; gg < 8; gg++) sum += partial[gg * 32 + tid];
        xc[tid] = sum * (1.0f / (float)NN);
    }
    if (tid >= H3 && tid < CDIM) {
        xc[tid] = (task[b] == tid - H3) ? 1.f : 0.f;
    }
    __syncthreads();
    if (tid < PDIM) {
        float acc = 0.f;
        #pragma unroll
        for (int c = 0; c < CDIM; c++) acc += wc[tid * CDIM + c] * xc[c];
        wb[(size_t)z * PDIM + tid] = acc;
    }
}

// ---------------- cc kernel: logits + interleave scatter --------------------
__global__ void cc_kernel(const float* __restrict__ H4b,
                          const float* __restrict__ wb,
                          float* __restrict__ cc) {
    int z = blockIdx.x;
    int q = z >> 6, b = z & 63;
    __shared__ float flat[NN * OUTD];
    __shared__ float wm[64];
    __shared__ float bv[8];
    int tid = threadIdx.x;
    const float4* src4 = (const float4*)(H4b + (size_t)z * NN * OUTD);
    float4* dst4 = (float4*)flat;
    for (int i = tid; i < NN * OUTD / 4; i += 256) dst4[i] = src4[i];
    if (tid < 64) wm[tid] = wb[(size_t)z * PDIM + tid];
    if (tid < 8)  bv[tid] = wb[(size_t)z * PDIM + 64 + tid];
    __syncthreads();
    for (int f = tid; f < NN * OUTD; f += 256) {
        int r = f >> 9, c = f & 511;
        float v = bv[r];
        #pragma unroll
        for (int i = 0; i < 8; i++) v += wm[r * 8 + i] * flat[i * NN + c];
        int n = f >> 3, o = f & 7;
        int scc = n >> 8;
        int n2 = ((n & 255) << 1) | q;
        cc[(((size_t)(b * 2 + scc) * NN + n2) << 3) + o] = v;
    }
}

// ---------------- final: out = softplus(-(cc @ cc^T)) -----------------------
__global__ void final_kernel(const float* __restrict__ cc, float* __restrict__ out) {
    int zz = blockIdx.z;
    __shared__ float Msm[NN * OUTD];
    int tid = threadIdx.y * 16 + threadIdx.x;
    const float4* src = (const float4*)(cc + (size_t)zz * NN * OUTD);
    float4* dst = (float4*)Msm;
    for (int i = tid; i < NN * OUTD / 4; i += 256) dst[i] = src[i];
    __syncthreads();
    int i0 = blockIdx.y * 64 + threadIdx.y * 4;
    int j0 = blockIdx.x * 64 + threadIdx.x * 4;
    float ai[4][8], aj[4][8];
    #pragma unroll
    for (int m = 0; m < 4; m++)
        #pragma unroll
        for (int o = 0; o < 8; o++) ai[m][o] = Msm[(i0 + m) * 8 + o];
    #pragma unroll
    for (int n = 0; n < 4; n++)
        #pragma unroll
        for (int o = 0; o < 8; o++) aj[n][o] = Msm[(j0 + n) * 8 + o];
    float* ob = out + (size_t)zz * NN * NN;
    #pragma unroll
    for (int m = 0; m < 4; m++) {
        float r[4];
        #pragma unroll
        for (int n = 0; n < 4; n++) {
            float x = 0.f;
            #pragma unroll
            for (int o = 0; o < 8; o++) x += ai[m][o] * aj[n][o];
            r[n] = __logf(1.0f + __expf(-fabsf(x))) + fmaxf(-x, 0.f);
        }
        *(float4*)(ob + (size_t)(i0 + m) * NN + j0) = make_float4(r[0], r[1], r[2], r[3]);
    }
}

// ---------------- host orchestration ----------------------------------------
#define SMEM_BYTES_SPLIT(BM, BN) (((BM) * 36 * 2 + 32 * ((BN) + 4) * 2) * 4)

extern "C" void kernel_launch(void* const* d_in, const int* in_sizes, int n_in,
                              void* d_out, int out_size) {
    const float* adj  = (const float*)d_in[0];
    const int*   task = (const int*)d_in[1];
    const float* w[2][4];
    const float* bia[2][4];
    int idx = 2;
    for (int s = 0; s < 2; s++)
        for (int l = 0; l < 4; l++) {
            w[s][l]   = (const float*)d_in[idx++];
            bia[s][l] = (const float*)d_in[idx++];
        }
    const float* wc = (const float*)d_in[18];
    float* out = (float*)d_out;

    float* base = nullptr;
    cudaGetSymbolAddress((void**)&base, g_scratch);
    uint32_t* adjb = nullptr;
    cudaGetSymbolAddress((void**)&adjb, g_adjb);
    float* p_d  = base + OFF_D;
    float* p_H1 = base + OFF_H1;
    float* p_H2 = base + OFF_H2;
    float* p_H3 = base + OFF_H3;
    float* p_H4 = base + OFF_H4;
    float* p_Z  = base + OFF_Z;
    float* p_WB = base + OFF_WB;
    float* p_CC = base + OFF_CC;

    const size_t S1  = (size_t)BB * NN * H1;
    const size_t S2  = (size_t)BB * NN * H2;
    const size_t S3  = (size_t)BB * NN * H3;
    const size_t S4  = (size_t)BB * NN * OUTD;

    // >48KB dynamic smem opt-in for 128x64 split plain GEMM (idempotent)
    cudaFuncSetAttribute(
        (const void*)plain_gemm_kernel<128, 64, 4, 2>,
        cudaFuncAttributeMaxDynamicSharedMemorySize, SMEM_BYTES_SPLIT(128, 64));

    // 1) preprocess: degree factors + adj -> bf16
    prep_kernel<<<NZ * NN / 8, 256>>>(adj, p_d, adjb);

    // 2) layer 1: H1 = leaky(feat @ w1 + b1), Z = w1 shared per-branch
    gcn_bf16_kernel<64, 128, 2, 4, true, true>
        <<<dim3(8, 1, NZ), 256>>>(
            adjb, w[0][0], w[1][0], p_d, bia[0][0], bia[1][0], p_H1, H1);

    // 3) layer 2: Z = H1 @ w2 ; H2 = leaky(feat @ Z + b2)
    plain_gemm_kernel<128, 64, 4, 2>
        <<<dim3(BB * NN / 128, 1, 2), 256, SMEM_BYTES_SPLIT(128, 64)>>>(
            p_H1, w[0][1], w[1][1], p_Z, H1, H2, S1, S2);
    gcn_bf16_kernel<128, 64, 4, 2, true, false>
        <<<dim3(4, 1, NZ), 256>>>(
            adjb, p_Z, nullptr, p_d, bia[0][1], bia[1][1], p_H2, H2);

    // 4) layer 3: Z = H2 @ w3 ; H3 = leaky(feat @ Z + b3)
    plain_gemm_kernel<128, 32, 4, 1>
        <<<dim3(BB * NN / 128, 1, 2), 128, SMEM_BYTES_SPLIT(128, 32)>>>(
            p_H2, w[0][2], w[1][2], p_Z, H2, H3, S2, S3);
    gcn_bf16_kernel<128, 32, 4, 1, true, false>
        <<<dim3(4, 1, NZ), 128>>>(
            adjb, p_Z, nullptr, p_d, bia[0][2], bia[1][2], p_H3, H3);

    // 5) layer 4: Z = H3 @ w4 ; H4 = feat @ Z + b4 (no act)
    plain_gemm_kernel<128, 8, 4, 1>
        <<<dim3(BB * NN / 128, 1, 2), 128, SMEM_BYTES_SPLIT(128, 8)>>>(
            p_H3, w[0][3], w[1][3], p_Z, H3, OUTD, S3, S4);
    gcn_bf16_kernel<128, 8, 4, 1, false, false>
        <<<dim3(4, 1, NZ), 128>>>(
            adjb, p_Z, nullptr, p_d, bia[0][3], bia[1][3], p_H4, OUTD);

    // 6) dynamic head params (uses conv3 = H3)
    dcl_params_kernel<<<NZ, 256>>>(task, wc, p_H3, p_WB);

    // 7) logits + interleave into cc
    cc_kernel<<<NZ, 256>>>(p_H4, p_WB, p_CC);

    // 8) final gram + softplus
    final_kernel<<<dim3(8, 8, NZ), dim3(16, 16)>>>(p_CC, out);

    (void)in_sizes; (void)n_in; (void)out_size;
}

// round 10
// speedup vs baseline: 6.3166x; 1.0635x over previous
#include <cuda_runtime.h>
#include <cuda_bf16.h>
#include <math.h>
#include <stdint.h>

#define NN 512
#define BB 64
#define NZ 128            // B*2 branch instances
#define H1 128
#define H2 64
#define H3 32
#define OUTD 8
#define CLS 16
#define PDIM 72           // OUT*OUT + OUT
#define CDIM 48           // H3 + CLS

// ---------------- scratch (static device buffers, no allocs) ----------------
static const size_t OFF_D   = 0;
static const size_t OFF_H1  = OFF_D   + (size_t)NZ*NN;
static const size_t OFF_H2  = OFF_H1  + (size_t)NZ*NN*H1;
static const size_t OFF_H3  = OFF_H2  + (size_t)NZ*NN*H2;
static const size_t OFF_H4  = OFF_H3  + (size_t)NZ*NN*H3;
static const size_t OFF_Z   = OFF_H4  + (size_t)NZ*NN*OUTD;
static const size_t OFF_WB  = OFF_Z   + (size_t)NZ*NN*H2;
static const size_t OFF_CC  = OFF_WB  + (size_t)NZ*PDIM;
static const size_t TOTAL_SCRATCH = OFF_CC + (size_t)BB*2*NN*OUTD;

__device__ float g_scratch[TOTAL_SCRATCH];
// adj as packed bf16x2 (k-pairs): [b2][512][256] uint32
__device__ uint32_t g_adjb[(size_t)NZ * NN * (NN / 2)];

// ---------------- bf16 helpers ------------------------------------------------
__device__ __forceinline__ uint32_t pack_bf16(float a, float b) {
    __nv_bfloat162 t = __floats2bfloat162_rn(a, b);
    return *reinterpret_cast<uint32_t*>(&t);
}

// ---------------- tf32 split helpers (plain GEMMs) ---------------------------
__device__ __forceinline__ float tf32_rna(float v) {
    uint32_t u;
    asm("cvt.rna.tf32.f32 %0, %1;" : "=r"(u) : "f"(v));
    return __uint_as_float(u);
}
__device__ __forceinline__ void split_tf32(float v, float& hi, float& lo) {
    hi = tf32_rna(v);
    lo = tf32_rna(v - hi);
}
__device__ __forceinline__ void split4(float4 v, float4& h, float4& l) {
    split_tf32(v.x, h.x, l.x);
    split_tf32(v.y, h.y, l.y);
    split_tf32(v.z, h.z, l.z);
    split_tf32(v.w, h.w, l.w);
}
__device__ __forceinline__ void mma_tf32(float c[4],
    uint32_t a0, uint32_t a1, uint32_t a2, uint32_t a3,
    uint32_t b0, uint32_t b1) {
    asm volatile(
        "mma.sync.aligned.m16n8k8.row.col.f32.tf32.tf32.f32 "
        "{%0,%1,%2,%3}, {%4,%5,%6,%7}, {%8,%9}, {%0,%1,%2,%3};"
        : "+f"(c[0]), "+f"(c[1]), "+f"(c[2]), "+f"(c[3])
        : "r"(a0), "r"(a1), "r"(a2), "r"(a3), "r"(b0), "r"(b1));
}
__device__ __forceinline__ void mma_bf16(float c[4],
    uint32_t a0, uint32_t a1, uint32_t a2, uint32_t a3,
    uint32_t b0, uint32_t b1) {
    asm volatile(
        "mma.sync.aligned.m16n8k16.row.col.f32.bf16.bf16.f32 "
        "{%0,%1,%2,%3}, {%4,%5,%6,%7}, {%8,%9}, {%0,%1,%2,%3};"
        : "+f"(c[0]), "+f"(c[1]), "+f"(c[2]), "+f"(c[3])
        : "r"(a0), "r"(a1), "r"(a2), "r"(a3), "r"(b0), "r"(b1));
}

// ---------------- preprocess: rowsum (d) + adj -> packed bf16 -----------------
__global__ void prep_kernel(const float* __restrict__ adj,
                            float* __restrict__ dout,
                            uint32_t* __restrict__ adjb) {
    int gw   = (blockIdx.x * blockDim.x + threadIdx.x) >> 5;
    int lane = threadIdx.x & 31;
    int b2  = gw >> 9;
    int row = gw & 511;
    const float4* r4 = (const float4*)(adj + (size_t)b2 * NN * NN + (size_t)row * NN);
    uint2* w2 = (uint2*)(adjb + (size_t)b2 * NN * (NN / 2) + (size_t)row * (NN / 2));
    float ssum = 0.f;
    #pragma unroll
    for (int j = lane; j < NN / 4; j += 32) {
        float4 v = r4[j];
        ssum += (v.x + v.y) + (v.z + v.w);
        uint2 p;
        p.x = pack_bf16(v.x, v.y);
        p.y = pack_bf16(v.z, v.w);
        w2[j] = p;
    }
    #pragma unroll
    for (int o = 16; o; o >>= 1) ssum += __shfl_xor_sync(0xffffffffu, ssum, o);
    if (lane == 0) {
        int s = b2 & 1, b = b2 >> 1;
        dout[(size_t)(s * BB + b) * NN + row] = rsqrtf(ssum + 1.0f);
    }
}

// ---------------- GCN layer: bf16 MMA (m16n8k16), B hi-only -------------------
// blockIdx.z = z in [0,128): s=z>>6, b=z&63, adjb index b2=b*2+s
// C_z = epi(adj @ (d∘Z)); epilogue adds d_i^2*Z_i + bias (+leaky)
// A = adj bf16 (permuted k-pair layout); B = d∘Z single bf16, paired layout
// (pairs q and q+4 adjacent -> one LDS.64 per fragment). 1 MMA per k16.
template<int BM, int BN, int WGM, int WGN, bool ACT, bool ZSHARED>
__global__ void __launch_bounds__(WGM*WGN*32)
gcn_bf16_kernel(const uint32_t* __restrict__ Adjb,
                const float* __restrict__ B0,
                const float* __restrict__ B1,
                const float* __restrict__ dbase,
                const float* __restrict__ bias0,
                const float* __restrict__ bias1,
                float* __restrict__ Cbase,
                int Ncols)
{
    constexpr int BK = 32;
    constexpr int KP = BK / 2;           // 16 k-pairs per tile
    constexpr int WM = BM / WGM, WN = BN / WGN;
    constexpr int MT = WM / 16, NT = WN / 8;
    constexpr int NTHREADS = WGM * WGN * 32;
    constexpr int ASTRIDE = 24;          // uint32 per A row (16 pairs + 8 pad)
    constexpr int BNP = (BN == 8) ? 20 : BN + 4;   // 8-byte-word stride ≡ 4 mod 16
    constexpr int A_TOTU = BM * 4;       // uint4 loads per tile (4 pairs each)
    constexpr int A_LDU = (A_TOTU + NTHREADS - 1) / NTHREADS;
    constexpr int B_TOTP = KP * BN;      // B k-pair elements per tile
    constexpr int B_LDP = (B_TOTP + NTHREADS - 1) / NTHREADS;

    __shared__ uint32_t Asm[BM][ASTRIDE];
    __shared__ __align__(16) uint32_t Bsm[2][4][BNP][2];   // [kk][t][n][j]

    const int z = blockIdx.z;
    const int s = z >> 6, b = z & 63;
    const uint32_t* A = Adjb + (size_t)(b * 2 + s) * NN * (NN / 2);
    const float* B    = ZSHARED ? (s ? B1 : B0) : B0 + (size_t)z * NN * Ncols;
    const float* bias = s ? bias1 : bias0;
    const float* dz   = dbase + (size_t)z * NN;
    float* C          = Cbase + (size_t)z * NN * Ncols;

    const int m0 = blockIdx.x * BM;
    const int tid = threadIdx.x;
    const int w = tid >> 5, lane = tid & 31;
    const int g = lane >> 2, tig = lane & 3;
    const int wm = (w / WGN) * WM;
    const int wn = (w % WGN) * WN;

    float acc[MT][NT][4] = {};
    uint4  aU[A_LDU];
    float2 bF[B_LDP];

    // prologue: load first k-tile
    #pragma unroll
    for (int i = 0; i < A_LDU; i++) {
        int idx = tid + i * NTHREADS;
        if (idx < A_TOTU) {
            int r = idx >> 2, q = idx & 3;
            aU[i] = *(const uint4*)&A[(size_t)(m0 + r) * (NN / 2) + q * 4];
        }
    }
    #pragma unroll
    for (int i = 0; i < B_LDP; i++) {
        int e = tid + i * NTHREADS;
        if (e < B_TOTP) {
            int p = e / BN, n = e % BN;
            int k = 2 * p;
            bF[i].x = B[(size_t)k * Ncols + n] * dz[k];
            bF[i].y = B[(size_t)(k + 1) * Ncols + n] * dz[k + 1];
        }
    }

    for (int k0 = 0; k0 < NN; k0 += BK) {
        // store A tile with k-pair permutation (pairs tig / tig+4 adjacent cols)
        #pragma unroll
        for (int i = 0; i < A_LDU; i++) {
            int idx = tid + i * NTHREADS;
            if (idx < A_TOTU) {
                int r = idx >> 2, q = idx & 3;
                int base = (q >> 1) * 8 + (q & 1);
                Asm[r][base]     = aU[i].x;
                Asm[r][base + 2] = aU[i].y;
                Asm[r][base + 4] = aU[i].z;
                Asm[r][base + 6] = aU[i].w;
            }
        }
        // store B tile, single bf16, paired layout: pair p -> [p>>3][p&3][n][(p>>2)&1]
        #pragma unroll
        for (int i = 0; i < B_LDP; i++) {
            int e = tid + i * NTHREADS;
            if (e < B_TOTP) {
                int p = e / BN, n = e % BN;
                Bsm[p >> 3][p & 3][n][(p >> 2) & 1] = pack_bf16(bF[i].x, bF[i].y);
            }
        }
        __syncthreads();

        // prefetch next k-tile (overlaps with MMAs below)
        if (k0 + BK < NN) {
            #pragma unroll
            for (int i = 0; i < A_LDU; i++) {
                int idx = tid + i * NTHREADS;
                if (idx < A_TOTU) {
                    int r = idx >> 2, q = idx & 3;
                    aU[i] = *(const uint4*)&A[(size_t)(m0 + r) * (NN / 2) + (k0 + BK) / 2 + q * 4];
                }
            }
            #pragma unroll
            for (int i = 0; i < B_LDP; i++) {
                int e = tid + i * NTHREADS;
                if (e < B_TOTP) {
                    int p = e / BN, n = e % BN;
                    int k = k0 + BK + 2 * p;
                    bF[i].x = B[(size_t)k * Ncols + n] * dz[k];
                    bF[i].y = B[(size_t)(k + 1) * Ncols + n] * dz[k + 1];
                }
            }
        }

        #pragma unroll
        for (int kk = 0; kk < 2; kk++) {        // two k16 steps
            uint32_t a0[MT], a1[MT], a2[MT], a3[MT];
            uint32_t b0[NT], b1[NT];
            #pragma unroll
            for (int mt = 0; mt < MT; mt++) {
                int r0 = wm + mt * 16 + g;
                uint2 u0 = *(const uint2*)&Asm[r0][kk * 8 + 2 * tig];
                uint2 u1 = *(const uint2*)&Asm[r0 + 8][kk * 8 + 2 * tig];
                a0[mt] = u0.x; a2[mt] = u0.y;
                a1[mt] = u1.x; a3[mt] = u1.y;
            }
            #pragma unroll
            for (int nt = 0; nt < NT; nt++) {
                int cb = wn + nt * 8 + g;
                uint2 bb = *(const uint2*)&Bsm[kk][tig][cb][0];
                b0[nt] = bb.x; b1[nt] = bb.y;
            }
            #pragma unroll
            for (int mt = 0; mt < MT; mt++)
                #pragma unroll
                for (int nt = 0; nt < NT; nt++)
                    mma_bf16(acc[mt][nt], a0[mt], a1[mt], a2[mt], a3[mt],
                             b0[nt], b1[nt]);
        }
        __syncthreads();
    }

    // epilogue: v = d_i * acc + d_i^2 * Z_i + bias (+leaky)
    #pragma unroll
    for (int mt = 0; mt < MT; mt++) {
        int r0 = m0 + wm + mt * 16 + g;
        int r1 = r0 + 8;
        float d0 = dz[r0], d1 = dz[r1];
        #pragma unroll
        for (int nt = 0; nt < NT; nt++) {
            int c = wn + nt * 8 + tig * 2;
            float2 z0 = *(const float2*)&B[(size_t)r0 * Ncols + c];
            float2 z1 = *(const float2*)&B[(size_t)r1 * Ncols + c];
            float bc0 = bias[c], bc1 = bias[c + 1];
            float v00 = d0 * acc[mt][nt][0] + d0 * d0 * z0.x + bc0;
            float v01 = d0 * acc[mt][nt][1] + d0 * d0 * z0.y + bc1;
            float v10 = d1 * acc[mt][nt][2] + d1 * d1 * z1.x + bc0;
            float v11 = d1 * acc[mt][nt][3] + d1 * d1 * z1.y + bc1;
            if (ACT) {
                v00 = (v00 >= 0.f) ? v00 : 0.2f * v00;
                v01 = (v01 >= 0.f) ? v01 : 0.2f * v01;
                v10 = (v10 >= 0.f) ? v10 : 0.2f * v10;
                v11 = (v11 >= 0.f) ? v11 : 0.2f * v11;
            }
            *(float2*)&C[(size_t)r0 * Ncols + c] = make_float2(v00, v01);
            *(float2*)&C[(size_t)r1 * Ncols + c] = make_float2(v10, v11);
        }
    }
}

// ---------------- plain split-TF32 MMA GEMM: C = A_s @ W_s --------------------
template<int BM, int BN, int WGM, int WGN>
__global__ void __launch_bounds__(WGM*WGN*32, (WGM*WGN*32 == 256) ? 2 : 4)
plain_gemm_kernel(const float* __restrict__ Abase,
                  const float* __restrict__ B0,
                  const float* __restrict__ B1,
                  float* __restrict__ Cbase,
                  int K, int Ncols, size_t sA, size_t sC)
{
    constexpr int BK = 32;
    constexpr int WM = BM / WGM, WN = BN / WGN;
    constexpr int MT = WM / 16, NT = WN / 8;
    constexpr int NTHREADS = WGM * WGN * 32;
    constexpr int BKP = BK + 4;
    constexpr int BNP = BN + 4;
    constexpr int A_TOT4 = BM * BK / 4;
    constexpr int B_TOT4 = BK * BN / 4;
    constexpr int A_LD4 = (A_TOT4 + NTHREADS - 1) / NTHREADS;
    constexpr int B_LD4 = (B_TOT4 + NTHREADS - 1) / NTHREADS;
    constexpr int A_SM_F = BM * BKP * 2;

    extern __shared__ float smraw[];
    float2 (*Ahl)[BKP] = reinterpret_cast<float2(*)[BKP]>(smraw);
    float2 (*Bhl)[BNP] = reinterpret_cast<float2(*)[BNP]>(smraw + A_SM_F);

    const int z = blockIdx.z;
    const float* A = Abase + (size_t)z * sA;
    const float* B = z ? B1 : B0;
    float* C = Cbase + (size_t)z * sC;

    const int m0 = blockIdx.x * BM;
    const int tid = threadIdx.x;
    const int w = tid >> 5, lane = tid & 31;
    const int g = lane >> 2, tig = lane & 3;
    const int wm = (w / WGN) * WM;
    const int wn = (w % WGN) * WN;

    float acc[MT][NT][4] = {};
    float4 aReg[A_LD4], bReg[B_LD4];

    #pragma unroll
    for (int i = 0; i < A_LD4; i++) {
        int idx = tid + i * NTHREADS;
        if (idx < A_TOT4) {
            int r = idx / (BK / 4), c4 = (idx % (BK / 4)) * 4;
            aReg[i] = *(const float4*)&A[(size_t)(m0 + r) * K + c4];
        }
    }
    #pragma unroll
    for (int i = 0; i < B_LD4; i++) {
        int idx = tid + i * NTHREADS;
        if (idx < B_TOT4) {
            int r = idx / (BN / 4), c4 = (idx % (BN / 4)) * 4;
            bReg[i] = *(const float4*)&B[(size_t)r * Ncols + c4];
        }
    }

    for (int k0 = 0; k0 < K; k0 += BK) {
        #pragma unroll
        for (int i = 0; i < A_LD4; i++) {
            int idx = tid + i * NTHREADS;
            if (idx < A_TOT4) {
                int r = idx / (BK / 4), c4 = (idx % (BK / 4)) * 4;
                float4 h, l; split4(aReg[i], h, l);
                *(float4*)&Ahl[r][c4]     = make_float4(h.x, l.x, h.y, l.y);
                *(float4*)&Ahl[r][c4 + 2] = make_float4(h.z, l.z, h.w, l.w);
            }
        }
        #pragma unroll
        for (int i = 0; i < B_LD4; i++) {
            int idx = tid + i * NTHREADS;
            if (idx < B_TOT4) {
                int r = idx / (BN / 4), c4 = (idx % (BN / 4)) * 4;
                float4 h, l; split4(bReg[i], h, l);
                *(float4*)&Bhl[r][c4]     = make_float4(h.x, l.x, h.y, l.y);
                *(float4*)&Bhl[r][c4 + 2] = make_float4(h.z, l.z, h.w, l.w);
            }
        }
        __syncthreads();

        if (k0 + BK < K) {
            #pragma unroll
            for (int i = 0; i < A_LD4; i++) {
                int idx = tid + i * NTHREADS;
                if (idx < A_TOT4) {
                    int r = idx / (BK / 4), c4 = (idx % (BK / 4)) * 4;
                    aReg[i] = *(const float4*)&A[(size_t)(m0 + r) * K + (k0 + BK) + c4];
                }
            }
            #pragma unroll
            for (int i = 0; i < B_LD4; i++) {
                int idx = tid + i * NTHREADS;
                if (idx < B_TOT4) {
                    int r = idx / (BN / 4), c4 = (idx % (BN / 4)) * 4;
                    bReg[i] = *(const float4*)&B[(size_t)(k0 + BK + r) * Ncols + c4];
                }
            }
        }

        #pragma unroll
        for (int kk = 0; kk < BK; kk += 8) {
            uint32_t ah[MT][4], al[MT][4], bh[NT][2], bl[NT][2];
            #pragma unroll
            for (int mt = 0; mt < MT; mt++) {
                int rb = wm + mt * 16;
                float2 p0 = Ahl[rb + g    ][kk + tig    ];
                float2 p1 = Ahl[rb + g + 8][kk + tig    ];
                float2 p2 = Ahl[rb + g    ][kk + tig + 4];
                float2 p3 = Ahl[rb + g + 8][kk + tig + 4];
                ah[mt][0] = __float_as_uint(p0.x); al[mt][0] = __float_as_uint(p0.y);
                ah[mt][1] = __float_as_uint(p1.x); al[mt][1] = __float_as_uint(p1.y);
                ah[mt][2] = __float_as_uint(p2.x); al[mt][2] = __float_as_uint(p2.y);
                ah[mt][3] = __float_as_uint(p3.x); al[mt][3] = __float_as_uint(p3.y);
            }
            #pragma unroll
            for (int nt = 0; nt < NT; nt++) {
                int cb = wn + nt * 8 + g;
                float2 q0 = Bhl[kk + tig    ][cb];
                float2 q1 = Bhl[kk + tig + 4][cb];
                bh[nt][0] = __float_as_uint(q0.x); bl[nt][0] = __float_as_uint(q0.y);
                bh[nt][1] = __float_as_uint(q1.x); bl[nt][1] = __float_as_uint(q1.y);
            }
            #pragma unroll
            for (int mt = 0; mt < MT; mt++)
                #pragma unroll
                for (int nt = 0; nt < NT; nt++) {
                    mma_tf32(acc[mt][nt], ah[mt][0], ah[mt][1], ah[mt][2], ah[mt][3],
                             bh[nt][0], bh[nt][1]);
                    mma_tf32(acc[mt][nt], ah[mt][0], ah[mt][1], ah[mt][2], ah[mt][3],
                             bl[nt][0], bl[nt][1]);
                    mma_tf32(acc[mt][nt], al[mt][0], al[mt][1], al[mt][2], al[mt][3],
                             bh[nt][0], bh[nt][1]);
                }
        }
        __syncthreads();
    }

    #pragma unroll
    for (int mt = 0; mt < MT; mt++) {
        int r0 = m0 + wm + mt * 16 + g;
        int r1 = r0 + 8;
        #pragma unroll
        for (int nt = 0; nt < NT; nt++) {
            int c = wn + nt * 8 + tig * 2;
            *(float2*)&C[(size_t)r0 * Ncols + c] = make_float2(acc[mt][nt][0], acc[mt][nt][1]);
            *(float2*)&C[(size_t)r1 * Ncols + c] = make_float2(acc[mt][nt][2], acc[mt][nt][3]);
        }
    }
}

// ---------------- dynamic head params ---------------------------------------
__global__ void dcl_params_kernel(const int* __restrict__ task,
                                  const float* __restrict__ wc,
                                  const float* __restrict__ H3b,
                                  float* __restrict__ wb) {
    int z = blockIdx.x;
    int b = z & 63;
    const float* conv3 = H3b + (size_t)z * NN * H3;
    __shared__ float partial[256];
    __shared__ float xc[CDIM];
    int tid = threadIdx.x;
    int col = tid & 31, g = tid >> 5;
    float p = 0.f;
    for (int r = g; r < NN; r += 8) p += conv3[(size_t)r * H3 + col];
    partial[tid] = p;
    __syncthreads();
    if (tid < H3) {
        float sum = 0.f;
        #pragma unroll
        for (int gg = 0; gg < 8; gg++) sum += partial[gg * 32 + tid];
        xc[tid] = sum * (1.0f / (float)NN);
    }
    if (tid >= H3 && tid < CDIM) {
        xc[tid] = (task[b] == tid - H3) ? 1.f : 0.f;
    }
    __syncthreads();
    if (tid < PDIM) {
        float acc = 0.f;
        #pragma unroll
        for (int c = 0; c < CDIM; c++) acc += wc[tid * CDIM + c] * xc[c];
        wb[(size_t)z * PDIM + tid] = acc;
    }
}

// ---------------- cc kernel: logits + interleave scatter --------------------
__global__ void cc_kernel(const float* __restrict__ H4b,
                          const float* __restrict__ wb,
                          float* __restrict__ cc) {
    int z = blockIdx.x;
    int q = z >> 6, b = z & 63;
    __shared__ float flat[NN * OUTD];
    __shared__ float wm[64];
    __shared__ float bv[8];
    int tid = threadIdx.x;
    const float4* src4 = (const float4*)(H4b + (size_t)z * NN * OUTD);
    float4* dst4 = (float4*)flat;
    for (int i = tid; i < NN * OUTD / 4; i += 256) dst4[i] = src4[i];
    if (tid < 64) wm[tid] = wb[(size_t)z * PDIM + tid];
    if (tid < 8)  bv[tid] = wb[(size_t)z * PDIM + 64 + tid];
    __syncthreads();
    for (int f = tid; f < NN * OUTD; f += 256) {
        int r = f >> 9, c = f & 511;
        float v = bv[r];
        #pragma unroll
        for (int i = 0; i < 8; i++) v += wm[r * 8 + i] * flat[i * NN + c];
        int n = f >> 3, o = f & 7;
        int scc = n >> 8;
        int n2 = ((n & 255) << 1) | q;
        cc[(((size_t)(b * 2 + scc) * NN + n2) << 3) + o] = v;
    }
}

// ---------------- final: out = softplus(-(cc @ cc^T)) -----------------------
__global__ void final_kernel(const float* __restrict__ cc, float* __restrict__ out) {
    int zz = blockIdx.z;
    __shared__ float Msm[NN * OUTD];
    int tid = threadIdx.y * 16 + threadIdx.x;
    const float4* src = (const float4*)(cc + (size_t)zz * NN * OUTD);
    float4* dst = (float4*)Msm;
    for (int i = tid; i < NN * OUTD / 4; i += 256) dst[i] = src[i];
    __syncthreads();
    int i0 = blockIdx.y * 64 + threadIdx.y * 4;
    int j0 = blockIdx.x * 64 + threadIdx.x * 4;
    float ai[4][8], aj[4][8];
    #pragma unroll
    for (int m = 0; m < 4; m++)
        #pragma unroll
        for (int o = 0; o < 8; o++) ai[m][o] = Msm[(i0 + m) * 8 + o];
    #pragma unroll
    for (int n = 0; n < 4; n++)
        #pragma unroll
        for (int o = 0; o < 8; o++) aj[n][o] = Msm[(j0 + n) * 8 + o];
    float* ob = out + (size_t)zz * NN * NN;
    #pragma unroll
    for (int m = 0; m < 4; m++) {
        float r[4];
        #pragma unroll
        for (int n = 0; n < 4; n++) {
            float x = 0.f;
            #pragma unroll
            for (int o = 0; o < 8; o++) x += ai[m][o] * aj[n][o];
            r[n] = __logf(1.0f + __expf(-fabsf(x))) + fmaxf(-x, 0.f);
        }
        *(float4*)(ob + (size_t)(i0 + m) * NN + j0) = make_float4(r[0], r[1], r[2], r[3]);
    }
}

// ---------------- host orchestration ----------------------------------------
#define SMEM_BYTES_SPLIT(BM, BN) (((BM) * 36 * 2 + 32 * ((BN) + 4) * 2) * 4)

extern "C" void kernel_launch(void* const* d_in, const int* in_sizes, int n_in,
                              void* d_out, int out_size) {
    const float* adj  = (const float*)d_in[0];
    const int*   task = (const int*)d_in[1];
    const float* w[2][4];
    const float* bia[2][4];
    int idx = 2;
    for (int s = 0; s < 2; s++)
        for (int l = 0; l < 4; l++) {
            w[s][l]   = (const float*)d_in[idx++];
            bia[s][l] = (const float*)d_in[idx++];
        }
    const float* wc = (const float*)d_in[18];
    float* out = (float*)d_out;

    float* base = nullptr;
    cudaGetSymbolAddress((void**)&base, g_scratch);
    uint32_t* adjb = nullptr;
    cudaGetSymbolAddress((void**)&adjb, g_adjb);
    float* p_d  = base + OFF_D;
    float* p_H1 = base + OFF_H1;
    float* p_H2 = base + OFF_H2;
    float* p_H3 = base + OFF_H3;
    float* p_H4 = base + OFF_H4;
    float* p_Z  = base + OFF_Z;
    float* p_WB = base + OFF_WB;
    float* p_CC = base + OFF_CC;

    const size_t S1  = (size_t)BB * NN * H1;
    const size_t S2  = (size_t)BB * NN * H2;
    const size_t S3  = (size_t)BB * NN * H3;
    const size_t S4  = (size_t)BB * NN * OUTD;

    // >48KB dynamic smem opt-in for 128x64 split plain GEMM (idempotent)
    cudaFuncSetAttribute(
        (const void*)plain_gemm_kernel<128, 64, 4, 2>,
        cudaFuncAttributeMaxDynamicSharedMemorySize, SMEM_BYTES_SPLIT(128, 64));

    // 1) preprocess: degree factors + adj -> bf16
    prep_kernel<<<NZ * NN / 8, 256>>>(adj, p_d, adjb);

    // 2) layer 1: H1 = leaky(feat @ w1 + b1), Z = w1 shared per-branch
    gcn_bf16_kernel<64, 128, 2, 4, true, true>
        <<<dim3(8, 1, NZ), 256>>>(
            adjb, w[0][0], w[1][0], p_d, bia[0][0], bia[1][0], p_H1, H1);

    // 3) layer 2: Z = H1 @ w2 ; H2 = leaky(feat @ Z + b2)
    plain_gemm_kernel<128, 64, 4, 2>
        <<<dim3(BB * NN / 128, 1, 2), 256, SMEM_BYTES_SPLIT(128, 64)>>>(
            p_H1, w[0][1], w[1][1], p_Z, H1, H2, S1, S2);
    gcn_bf16_kernel<128, 64, 4, 2, true, false>
        <<<dim3(4, 1, NZ), 256>>>(
            adjb, p_Z, nullptr, p_d, bia[0][1], bia[1][1], p_H2, H2);

    // 4) layer 3: Z = H2 @ w3 ; H3 = leaky(feat @ Z + b3)
    plain_gemm_kernel<128, 32, 4, 1>
        <<<dim3(BB * NN / 128, 1, 2), 128, SMEM_BYTES_SPLIT(128, 32)>>>(
            p_H2, w[0][2], w[1][2], p_Z, H2, H3, S2, S3);
    gcn_bf16_kernel<128, 32, 4, 1, true, false>
        <<<dim3(4, 1, NZ), 128>>>(
            adjb, p_Z, nullptr, p_d, bia[0][2], bia[1][2], p_H3, H3);

    // 5) layer 4: Z = H3 @ w4 ; H4 = feat @ Z + b4 (no act)
    plain_gemm_kernel<128, 8, 4, 1>
        <<<dim3(BB * NN / 128, 1, 2), 128, SMEM_BYTES_SPLIT(128, 8)>>>(
            p_H3, w[0][3], w[1][3], p_Z, H3, OUTD, S3, S4);
    gcn_bf16_kernel<128, 8, 4, 1, false, false>
        <<<dim3(4, 1, NZ), 128>>>(
            adjb, p_Z, nullptr, p_d, bia[0][3], bia[1][3], p_H4, OUTD);

    // 6) dynamic head params (uses conv3 = H3)
    dcl_params_kernel<<<NZ, 256>>>(task, wc, p_H3, p_WB);

    // 7) logits + interleave into cc
    cc_kernel<<<NZ, 256>>>(p_H4, p_WB, p_CC);

    // 8) final gram + softplus
    final_kernel<<<dim3(8, 8, NZ), dim3(16, 16)>>>(p_CC, out);

    (void)in_sizes; (void)n_in; (void)out_size;
}

// round 11
// speedup vs baseline: 6.8692x; 1.0875x over previous
#include <cuda_runtime.h>
#include <cuda_bf16.h>
#include <math.h>
#include <stdint.h>

#define NN 512
#define BB 64
#define NZ 128            // B*2 branch instances
#define H1 128
#define H2 64
#define H3 32
#define OUTD 8
#define CLS 16
#define PDIM 72           // OUT*OUT + OUT
#define CDIM 48           // H3 + CLS

// ---------------- scratch (static device buffers, no allocs) ----------------
static const size_t OFF_D   = 0;
static const size_t OFF_H1  = OFF_D   + (size_t)NZ*NN;
static const size_t OFF_H2  = OFF_H1  + (size_t)NZ*NN*H1;
static const size_t OFF_H3  = OFF_H2  + (size_t)NZ*NN*H2;
static const size_t OFF_H4  = OFF_H3  + (size_t)NZ*NN*H3;
static const size_t OFF_Z   = OFF_H4  + (size_t)NZ*NN*OUTD;
static const size_t OFF_WB  = OFF_Z   + (size_t)NZ*NN*H2;
static const size_t OFF_CC  = OFF_WB  + (size_t)NZ*PDIM;
static const size_t TOTAL_SCRATCH = OFF_CC + (size_t)BB*2*NN*OUTD;

__device__ float g_scratch[TOTAL_SCRATCH];
// adj as packed bf16x2 (k-pairs): [b2][512][256] uint32
__device__ uint32_t g_adjb[(size_t)NZ * NN * (NN / 2)];

// ---------------- bf16 helpers ------------------------------------------------
__device__ __forceinline__ uint32_t pack_bf16(float a, float b) {
    __nv_bfloat162 t = __floats2bfloat162_rn(a, b);
    return *reinterpret_cast<uint32_t*>(&t);
}
__device__ __forceinline__ void split_bf16(float v, float& hi, float& lo) {
    __nv_bfloat16 h = __float2bfloat16(v);
    hi = __bfloat162float(h);
    lo = v - hi;
}
// pair index p (0..15) -> permuted word offset within A row
__device__ __forceinline__ int aperm(int p) {
    int q = p >> 2, j = p & 3;
    return (q >> 1) * 8 + (q & 1) + 2 * j;
}

__device__ __forceinline__ void mma_bf16(float c[4],
    uint32_t a0, uint32_t a1, uint32_t a2, uint32_t a3,
    uint32_t b0, uint32_t b1) {
    asm volatile(
        "mma.sync.aligned.m16n8k16.row.col.f32.bf16.bf16.f32 "
        "{%0,%1,%2,%3}, {%4,%5,%6,%7}, {%8,%9}, {%0,%1,%2,%3};"
        : "+f"(c[0]), "+f"(c[1]), "+f"(c[2]), "+f"(c[3])
        : "r"(a0), "r"(a1), "r"(a2), "r"(a3), "r"(b0), "r"(b1));
}

// ---------------- preprocess: rowsum (d) + adj -> packed bf16 -----------------
__global__ void prep_kernel(const float* __restrict__ adj,
                            float* __restrict__ dout,
                            uint32_t* __restrict__ adjb) {
    int gw   = (blockIdx.x * blockDim.x + threadIdx.x) >> 5;
    int lane = threadIdx.x & 31;
    int b2  = gw >> 9;
    int row = gw & 511;
    const float4* r4 = (const float4*)(adj + (size_t)b2 * NN * NN + (size_t)row * NN);
    uint2* w2 = (uint2*)(adjb + (size_t)b2 * NN * (NN / 2) + (size_t)row * (NN / 2));
    float ssum = 0.f;
    #pragma unroll
    for (int j = lane; j < NN / 4; j += 32) {
        float4 v = r4[j];
        ssum += (v.x + v.y) + (v.z + v.w);
        uint2 p;
        p.x = pack_bf16(v.x, v.y);
        p.y = pack_bf16(v.z, v.w);
        w2[j] = p;
    }
    #pragma unroll
    for (int o = 16; o; o >>= 1) ssum += __shfl_xor_sync(0xffffffffu, ssum, o);
    if (lane == 0) {
        int s = b2 & 1, b = b2 >> 1;
        dout[(size_t)(s * BB + b) * NN + row] = rsqrtf(ssum + 1.0f);
    }
}

// ---------------- GCN layer: bf16 MMA, double-buffered smem -------------------
// blockIdx.z = z in [0,128): s=z>>6, b=z&63, adjb index b2=b*2+s
// C_z = epi(adj @ (d∘Z)); epilogue adds d_i^2*Z_i + bias (+leaky)
// A = adj bf16 (permuted k-pair layout); B = d∘Z single bf16, paired layout.
template<int BM, int BN, int WGM, int WGN, bool ACT, bool ZSHARED>
__global__ void __launch_bounds__(WGM*WGN*32, (WGM*WGN*32 == 256) ? 2 : 4)
gcn_bf16_kernel(const uint32_t* __restrict__ Adjb,
                const float* __restrict__ B0,
                const float* __restrict__ B1,
                const float* __restrict__ dbase,
                const float* __restrict__ bias0,
                const float* __restrict__ bias1,
                float* __restrict__ Cbase,
                int Ncols)
{
    constexpr int BK = 32;
    constexpr int KP = BK / 2;
    constexpr int WM = BM / WGM, WN = BN / WGN;
    constexpr int MT = WM / 16, NT = WN / 8;
    constexpr int NTHREADS = WGM * WGN * 32;
    constexpr int ASTRIDE = 24;
    constexpr int BNP = (BN == 8) ? 20 : BN + 4;
    constexpr int A_TOTU = BM * 4;
    constexpr int A_LDU = (A_TOTU + NTHREADS - 1) / NTHREADS;
    constexpr int B_TOTP = KP * BN;
    constexpr int B_LDP = (B_TOTP + NTHREADS - 1) / NTHREADS;
    constexpr int NTILES = NN / BK;   // 16

    __shared__ uint32_t Asm[2][BM][ASTRIDE];
    __shared__ __align__(16) uint32_t Bsm[2][2][4][BNP][2];

    const int z = blockIdx.z;
    const int s = z >> 6, b = z & 63;
    const uint32_t* A = Adjb + (size_t)(b * 2 + s) * NN * (NN / 2);
    const float* B    = ZSHARED ? (s ? B1 : B0) : B0 + (size_t)z * NN * Ncols;
    const float* bias = s ? bias1 : bias0;
    const float* dz   = dbase + (size_t)z * NN;
    float* C          = Cbase + (size_t)z * NN * Ncols;

    const int m0 = blockIdx.x * BM;
    const int tid = threadIdx.x;
    const int w = tid >> 5, lane = tid & 31;
    const int g = lane >> 2, tig = lane & 3;
    const int wm = (w / WGN) * WM;
    const int wn = (w % WGN) * WN;

    float acc[MT][NT][4] = {};
    uint4  aU[A_LDU];
    float2 bF[B_LDP];

    // stage tile 0 into registers
    #pragma unroll
    for (int i = 0; i < A_LDU; i++) {
        int idx = tid + i * NTHREADS;
        if (idx < A_TOTU) {
            int r = idx >> 2, q = idx & 3;
            aU[i] = *(const uint4*)&A[(size_t)(m0 + r) * (NN / 2) + q * 4];
        }
    }
    #pragma unroll
    for (int i = 0; i < B_LDP; i++) {
        int e = tid + i * NTHREADS;
        if (e < B_TOTP) {
            int p = e / BN, n = e % BN;
            int k = 2 * p;
            bF[i].x = B[(size_t)k * Ncols + n] * dz[k];
            bF[i].y = B[(size_t)(k + 1) * Ncols + n] * dz[k + 1];
        }
    }
    // store tile 0 into buffer 0
    #pragma unroll
    for (int i = 0; i < A_LDU; i++) {
        int idx = tid + i * NTHREADS;
        if (idx < A_TOTU) {
            int r = idx >> 2, q = idx & 3;
            int base = (q >> 1) * 8 + (q & 1);
            Asm[0][r][base]     = aU[i].x;
            Asm[0][r][base + 2] = aU[i].y;
            Asm[0][r][base + 4] = aU[i].z;
            Asm[0][r][base + 6] = aU[i].w;
        }
    }
    #pragma unroll
    for (int i = 0; i < B_LDP; i++) {
        int e = tid + i * NTHREADS;
        if (e < B_TOTP) {
            int p = e / BN, n = e % BN;
            Bsm[0][p >> 3][p & 3][n][(p >> 2) & 1] = pack_bf16(bF[i].x, bF[i].y);
        }
    }
    __syncthreads();

    for (int c = 0; c < NTILES; c++) {
        const int cur = c & 1, nxt = cur ^ 1;
        // stage tile c+1 (global loads overlap with MMAs below)
        if (c + 1 < NTILES) {
            #pragma unroll
            for (int i = 0; i < A_LDU; i++) {
                int idx = tid + i * NTHREADS;
                if (idx < A_TOTU) {
                    int r = idx >> 2, q = idx & 3;
                    aU[i] = *(const uint4*)&A[(size_t)(m0 + r) * (NN / 2) + (c + 1) * KP + q * 4];
                }
            }
            #pragma unroll
            for (int i = 0; i < B_LDP; i++) {
                int e = tid + i * NTHREADS;
                if (e < B_TOTP) {
                    int p = e / BN, n = e % BN;
                    int k = (c + 1) * BK + 2 * p;
                    bF[i].x = B[(size_t)k * Ncols + n] * dz[k];
                    bF[i].y = B[(size_t)(k + 1) * Ncols + n] * dz[k + 1];
                }
            }
        }

        // MMAs from buffer cur
        #pragma unroll
        for (int kk = 0; kk < 2; kk++) {
            uint32_t a0[MT], a1[MT], a2[MT], a3[MT];
            uint32_t b0[NT], b1[NT];
            #pragma unroll
            for (int mt = 0; mt < MT; mt++) {
                int r0 = wm + mt * 16 + g;
                uint2 u0 = *(const uint2*)&Asm[cur][r0][kk * 8 + 2 * tig];
                uint2 u1 = *(const uint2*)&Asm[cur][r0 + 8][kk * 8 + 2 * tig];
                a0[mt] = u0.x; a2[mt] = u0.y;
                a1[mt] = u1.x; a3[mt] = u1.y;
            }
            #pragma unroll
            for (int nt = 0; nt < NT; nt++) {
                int cb = wn + nt * 8 + g;
                uint2 bb = *(const uint2*)&Bsm[cur][kk][tig][cb][0];
                b0[nt] = bb.x; b1[nt] = bb.y;
            }
            #pragma unroll
            for (int mt = 0; mt < MT; mt++)
                #pragma unroll
                for (int nt = 0; nt < NT; nt++)
                    mma_bf16(acc[mt][nt], a0[mt], a1[mt], a2[mt], a3[mt],
                             b0[nt], b1[nt]);
        }

        // store tile c+1 into buffer nxt (overlaps other warps' MMAs on cur)
        if (c + 1 < NTILES) {
            #pragma unroll
            for (int i = 0; i < A_LDU; i++) {
                int idx = tid + i * NTHREADS;
                if (idx < A_TOTU) {
                    int r = idx >> 2, q = idx & 3;
                    int base = (q >> 1) * 8 + (q & 1);
                    Asm[nxt][r][base]     = aU[i].x;
                    Asm[nxt][r][base + 2] = aU[i].y;
                    Asm[nxt][r][base + 4] = aU[i].z;
                    Asm[nxt][r][base + 6] = aU[i].w;
                }
            }
            #pragma unroll
            for (int i = 0; i < B_LDP; i++) {
                int e = tid + i * NTHREADS;
                if (e < B_TOTP) {
                    int p = e / BN, n = e % BN;
                    Bsm[nxt][p >> 3][p & 3][n][(p >> 2) & 1] = pack_bf16(bF[i].x, bF[i].y);
                }
            }
        }
        __syncthreads();
    }

    // epilogue: v = d_i * acc + d_i^2 * Z_i + bias (+leaky)
    #pragma unroll
    for (int mt = 0; mt < MT; mt++) {
        int r0 = m0 + wm + mt * 16 + g;
        int r1 = r0 + 8;
        float d0 = dz[r0], d1 = dz[r1];
        #pragma unroll
        for (int nt = 0; nt < NT; nt++) {
            int c = wn + nt * 8 + tig * 2;
            float2 z0 = *(const float2*)&B[(size_t)r0 * Ncols + c];
            float2 z1 = *(const float2*)&B[(size_t)r1 * Ncols + c];
            float bc0 = bias[c], bc1 = bias[c + 1];
            float v00 = d0 * acc[mt][nt][0] + d0 * d0 * z0.x + bc0;
            float v01 = d0 * acc[mt][nt][1] + d0 * d0 * z0.y + bc1;
            float v10 = d1 * acc[mt][nt][2] + d1 * d1 * z1.x + bc0;
            float v11 = d1 * acc[mt][nt][3] + d1 * d1 * z1.y + bc1;
            if (ACT) {
                v00 = (v00 >= 0.f) ? v00 : 0.2f * v00;
                v01 = (v01 >= 0.f) ? v01 : 0.2f * v01;
                v10 = (v10 >= 0.f) ? v10 : 0.2f * v10;
                v11 = (v11 >= 0.f) ? v11 : 0.2f * v11;
            }
            *(float2*)&C[(size_t)r0 * Ncols + c] = make_float2(v00, v01);
            *(float2*)&C[(size_t)r1 * Ncols + c] = make_float2(v10, v11);
        }
    }
}

// ---------------- plain bf16 split GEMM: C = A_s @ W_s ------------------------
// A, W split bf16 hi+lo; 3 MMAs per k16 (hh, hl, lh); per-term error ~2^-17.
template<int BM, int BN, int WGM, int WGN>
__global__ void __launch_bounds__(WGM*WGN*32, (WGM*WGN*32 == 256) ? 2 : 4)
plain_bf16_kernel(const float* __restrict__ Abase,
                  const float* __restrict__ B0,
                  const float* __restrict__ B1,
                  float* __restrict__ Cbase,
                  int K, int Ncols, size_t sA, size_t sC)
{
    constexpr int BK = 32;
    constexpr int KP = BK / 2;
    constexpr int WM = BM / WGM, WN = BN / WGN;
    constexpr int MT = WM / 16, NT = WN / 8;
    constexpr int NTHREADS = WGM * WGN * 32;
    constexpr int ASTRIDE = 24;
    constexpr int BNP = (BN == 8) ? 20 : BN + 4;
    constexpr int A_TOT4 = BM * BK / 4;
    constexpr int A_LD4 = (A_TOT4 + NTHREADS - 1) / NTHREADS;
    constexpr int B_TOTP = KP * BN;
    constexpr int B_LDP = (B_TOTP + NTHREADS - 1) / NTHREADS;

    __shared__ uint32_t Ah[BM][ASTRIDE], Al[BM][ASTRIDE];
    __shared__ __align__(16) uint32_t Bh[2][4][BNP][2], Bl[2][4][BNP][2];

    const int z = blockIdx.z;
    const float* A = Abase + (size_t)z * sA;
    const float* B = z ? B1 : B0;
    float* C = Cbase + (size_t)z * sC;

    const int m0 = blockIdx.x * BM;
    const int tid = threadIdx.x;
    const int w = tid >> 5, lane = tid & 31;
    const int g = lane >> 2, tig = lane & 3;
    const int wm = (w / WGN) * WM;
    const int wn = (w % WGN) * WN;

    float acc[MT][NT][4] = {};
    float4 aF[A_LD4];
    float2 bF[B_LDP];

    #pragma unroll
    for (int i = 0; i < A_LD4; i++) {
        int idx = tid + i * NTHREADS;
        if (idx < A_TOT4) {
            int r = idx / (BK / 4), c4 = (idx % (BK / 4)) * 4;
            aF[i] = *(const float4*)&A[(size_t)(m0 + r) * K + c4];
        }
    }
    #pragma unroll
    for (int i = 0; i < B_LDP; i++) {
        int e = tid + i * NTHREADS;
        if (e < B_TOTP) {
            int p = e / BN, n = e % BN;
            bF[i].x = B[(size_t)(2 * p) * Ncols + n];
            bF[i].y = B[(size_t)(2 * p + 1) * Ncols + n];
        }
    }

    for (int k0 = 0; k0 < K; k0 += BK) {
        // store split tiles into smem
        #pragma unroll
        for (int i = 0; i < A_LD4; i++) {
            int idx = tid + i * NTHREADS;
            if (idx < A_TOT4) {
                int r = idx / (BK / 4), c4 = (idx % (BK / 4)) * 4;
                int p0 = c4 >> 1;          // even pair index
                float hx, lx, hy, ly, hz, lz, hw, lw;
                split_bf16(aF[i].x, hx, lx); split_bf16(aF[i].y, hy, ly);
                split_bf16(aF[i].z, hz, lz); split_bf16(aF[i].w, hw, lw);
                int w0 = aperm(p0), w1 = aperm(p0 + 1);
                Ah[r][w0] = pack_bf16(hx, hy); Al[r][w0] = pack_bf16(lx, ly);
                Ah[r][w1] = pack_bf16(hz, hw); Al[r][w1] = pack_bf16(lz, lw);
            }
        }
        #pragma unroll
        for (int i = 0; i < B_LDP; i++) {
            int e = tid + i * NTHREADS;
            if (e < B_TOTP) {
                int p = e / BN, n = e % BN;
                float hx, lx, hy, ly;
                split_bf16(bF[i].x, hx, lx); split_bf16(bF[i].y, hy, ly);
                Bh[p >> 3][p & 3][n][(p >> 2) & 1] = pack_bf16(hx, hy);
                Bl[p >> 3][p & 3][n][(p >> 2) & 1] = pack_bf16(lx, ly);
            }
        }
        __syncthreads();

        // prefetch next tile
        if (k0 + BK < K) {
            #pragma unroll
            for (int i = 0; i < A_LD4; i++) {
                int idx = tid + i * NTHREADS;
                if (idx < A_TOT4) {
                    int r = idx / (BK / 4), c4 = (idx % (BK / 4)) * 4;
                    aF[i] = *(const float4*)&A[(size_t)(m0 + r) * K + (k0 + BK) + c4];
                }
            }
            #pragma unroll
            for (int i = 0; i < B_LDP; i++) {
                int e = tid + i * NTHREADS;
                if (e < B_TOTP) {
                    int p = e / BN, n = e % BN;
                    int k = k0 + BK + 2 * p;
                    bF[i].x = B[(size_t)k * Ncols + n];
                    bF[i].y = B[(size_t)(k + 1) * Ncols + n];
                }
            }
        }

        #pragma unroll
        for (int kk = 0; kk < 2; kk++) {
            uint32_t ah0[MT], ah1[MT], ah2[MT], ah3[MT];
            uint32_t al0[MT], al1[MT], al2[MT], al3[MT];
            uint32_t bh0[NT], bh1[NT], bl0[NT], bl1[NT];
            #pragma unroll
            for (int mt = 0; mt < MT; mt++) {
                int r0 = wm + mt * 16 + g;
                uint2 h0 = *(const uint2*)&Ah[r0][kk * 8 + 2 * tig];
                uint2 h1 = *(const uint2*)&Ah[r0 + 8][kk * 8 + 2 * tig];
                uint2 l0 = *(const uint2*)&Al[r0][kk * 8 + 2 * tig];
                uint2 l1 = *(const uint2*)&Al[r0 + 8][kk * 8 + 2 * tig];
                ah0[mt] = h0.x; ah2[mt] = h0.y;
                ah1[mt] = h1.x; ah3[mt] = h1.y;
                al0[mt] = l0.x; al2[mt] = l0.y;
                al1[mt] = l1.x; al3[mt] = l1.y;
            }
            #pragma unroll
            for (int nt = 0; nt < NT; nt++) {
                int cb = wn + nt * 8 + g;
                uint2 bh = *(const uint2*)&Bh[kk][tig][cb][0];
                uint2 bl = *(const uint2*)&Bl[kk][tig][cb][0];
                bh0[nt] = bh.x; bh1[nt] = bh.y;
                bl0[nt] = bl.x; bl1[nt] = bl.y;
            }
            #pragma unroll
            for (int mt = 0; mt < MT; mt++)
                #pragma unroll
                for (int nt = 0; nt < NT; nt++) {
                    mma_bf16(acc[mt][nt], ah0[mt], ah1[mt], ah2[mt], ah3[mt],
                             bh0[nt], bh1[nt]);
                    mma_bf16(acc[mt][nt], ah0[mt], ah1[mt], ah2[mt], ah3[mt],
                             bl0[nt], bl1[nt]);
                    mma_bf16(acc[mt][nt], al0[mt], al1[mt], al2[mt], al3[mt],
                             bh0[nt], bh1[nt]);
                }
        }
        __syncthreads();
    }

    #pragma unroll
    for (int mt = 0; mt < MT; mt++) {
        int r0 = m0 + wm + mt * 16 + g;
        int r1 = r0 + 8;
        #pragma unroll
        for (int nt = 0; nt < NT; nt++) {
            int c = wn + nt * 8 + tig * 2;
            *(float2*)&C[(size_t)r0 * Ncols + c] = make_float2(acc[mt][nt][0], acc[mt][nt][1]);
            *(float2*)&C[(size_t)r1 * Ncols + c] = make_float2(acc[mt][nt][2], acc[mt][nt][3]);
        }
    }
}

// ---------------- dynamic head params ---------------------------------------
__global__ void dcl_params_kernel(const int* __restrict__ task,
                                  const float* __restrict__ wc,
                                  const float* __restrict__ H3b,
                                  float* __restrict__ wb) {
    int z = blockIdx.x;
    int b = z & 63;
    const float* conv3 = H3b + (size_t)z * NN * H3;
    __shared__ float partial[256];
    __shared__ float xc[CDIM];
    int tid = threadIdx.x;
    int col = tid & 31, g = tid >> 5;
    float p = 0.f;
    for (int r = g; r < NN; r += 8) p += conv3[(size_t)r * H3 + col];
    partial[tid] = p;
    __syncthreads();
    if (tid < H3) {
        float sum = 0.f;
        #pragma unroll
        for (int gg = 0; gg < 8; gg++) sum += partial[gg * 32 + tid];
        xc[tid] = sum * (1.0f / (float)NN);
    }
    if (tid >= H3 && tid < CDIM) {
        xc[tid] = (task[b] == tid - H3) ? 1.f : 0.f;
    }
    __syncthreads();
    if (tid < PDIM) {
        float acc = 0.f;
        #pragma unroll
        for (int c = 0; c < CDIM; c++) acc += wc[tid * CDIM + c] * xc[c];
        wb[(size_t)z * PDIM + tid] = acc;
    }
}

// ---------------- cc kernel: logits + interleave scatter --------------------
__global__ void cc_kernel(const float* __restrict__ H4b,
                          const float* __restrict__ wb,
                          float* __restrict__ cc) {
    int z = blockIdx.x;
    int q = z >> 6, b = z & 63;
    __shared__ float flat[NN * OUTD];
    __shared__ float wm[64];
    __shared__ float bv[8];
    int tid = threadIdx.x;
    const float4* src4 = (const float4*)(H4b + (size_t)z * NN * OUTD);
    float4* dst4 = (float4*)flat;
    for (int i = tid; i < NN * OUTD / 4; i += 256) dst4[i] = src4[i];
    if (tid < 64) wm[tid] = wb[(size_t)z * PDIM + tid];
    if (tid < 8)  bv[tid] = wb[(size_t)z * PDIM + 64 + tid];
    __syncthreads();
    for (int f = tid; f < NN * OUTD; f += 256) {
        int r = f >> 9, c = f & 511;
        float v = bv[r];
        #pragma unroll
        for (int i = 0; i < 8; i++) v += wm[r * 8 + i] * flat[i * NN + c];
        int n = f >> 3, o = f & 7;
        int scc = n >> 8;
        int n2 = ((n & 255) << 1) | q;
        cc[(((size_t)(b * 2 + scc) * NN + n2) << 3) + o] = v;
    }
}

// ---------------- final: out = softplus(-(cc @ cc^T)) -----------------------
__global__ void final_kernel(const float* __restrict__ cc, float* __restrict__ out) {
    int zz = blockIdx.z;
    __shared__ float Msm[NN * OUTD];
    int tid = threadIdx.y * 16 + threadIdx.x;
    const float4* src = (const float4*)(cc + (size_t)zz * NN * OUTD);
    float4* dst = (float4*)Msm;
    for (int i = tid; i < NN * OUTD / 4; i += 256) dst[i] = src[i];
    __syncthreads();
    int i0 = blockIdx.y * 64 + threadIdx.y * 4;
    int j0 = blockIdx.x * 64 + threadIdx.x * 4;
    float ai[4][8], aj[4][8];
    #pragma unroll
    for (int m = 0; m < 4; m++)
        #pragma unroll
        for (int o = 0; o < 8; o++) ai[m][o] = Msm[(i0 + m) * 8 + o];
    #pragma unroll
    for (int n = 0; n < 4; n++)
        #pragma unroll
        for (int o = 0; o < 8; o++) aj[n][o] = Msm[(j0 + n) * 8 + o];
    float* ob = out + (size_t)zz * NN * NN;
    #pragma unroll
    for (int m = 0; m < 4; m++) {
        float r[4];
        #pragma unroll
        for (int n = 0; n < 4; n++) {
            float x = 0.f;
            #pragma unroll
            for (int o = 0; o < 8; o++) x += ai[m][o] * aj[n][o];
            r[n] = __logf(1.0f + __expf(-fabsf(x))) + fmaxf(-x, 0.f);
        }
        *(float4*)(ob + (size_t)(i0 + m) * NN + j0) = make_float4(r[0], r[1], r[2], r[3]);
    }
}

// ---------------- host orchestration ----------------------------------------
extern "C" void kernel_launch(void* const* d_in, const int* in_sizes, int n_in,
                              void* d_out, int out_size) {
    const float* adj  = (const float*)d_in[0];
    const int*   task = (const int*)d_in[1];
    const float* w[2][4];
    const float* bia[2][4];
    int idx = 2;
    for (int s = 0; s < 2; s++)
        for (int l = 0; l < 4; l++) {
            w[s][l]   = (const float*)d_in[idx++];
            bia[s][l] = (const float*)d_in[idx++];
        }
    const float* wc = (const float*)d_in[18];
    float* out = (float*)d_out;

    float* base = nullptr;
    cudaGetSymbolAddress((void**)&base, g_scratch);
    uint32_t* adjb = nullptr;
    cudaGetSymbolAddress((void**)&adjb, g_adjb);
    float* p_d  = base + OFF_D;
    float* p_H1 = base + OFF_H1;
    float* p_H2 = base + OFF_H2;
    float* p_H3 = base + OFF_H3;
    float* p_H4 = base + OFF_H4;
    float* p_Z  = base + OFF_Z;
    float* p_WB = base + OFF_WB;
    float* p_CC = base + OFF_CC;

    const size_t S1  = (size_t)BB * NN * H1;
    const size_t S2  = (size_t)BB * NN * H2;
    const size_t S3  = (size_t)BB * NN * H3;
    const size_t S4  = (size_t)BB * NN * OUTD;

    // 1) preprocess: degree factors + adj -> bf16
    prep_kernel<<<NZ * NN / 8, 256>>>(adj, p_d, adjb);

    // 2) layer 1: H1 = leaky(feat @ w1 + b1), Z = w1 shared per-branch
    gcn_bf16_kernel<64, 128, 2, 4, true, true>
        <<<dim3(8, 1, NZ), 256>>>(
            adjb, w[0][0], w[1][0], p_d, bia[0][0], bia[1][0], p_H1, H1);

    // 3) layer 2: Z = H1 @ w2 ; H2 = leaky(feat @ Z + b2)
    plain_bf16_kernel<128, 64, 4, 2>
        <<<dim3(BB * NN / 128, 1, 2), 256>>>(
            p_H1, w[0][1], w[1][1], p_Z, H1, H2, S1, S2);
    gcn_bf16_kernel<128, 64, 4, 2, true, false>
        <<<dim3(4, 1, NZ), 256>>>(
            adjb, p_Z, nullptr, p_d, bia[0][1], bia[1][1], p_H2, H2);

    // 4) layer 3: Z = H2 @ w3 ; H3 = leaky(feat @ Z + b3)
    plain_bf16_kernel<128, 32, 4, 1>
        <<<dim3(BB * NN / 128, 1, 2), 128>>>(
            p_H2, w[0][2], w[1][2], p_Z, H2, H3, S2, S3);
    gcn_bf16_kernel<128, 32, 4, 1, true, false>
        <<<dim3(4, 1, NZ), 128>>>(
            adjb, p_Z, nullptr, p_d, bia[0][2], bia[1][2], p_H3, H3);

    // 5) layer 4: Z = H3 @ w4 ; H4 = feat @ Z + b4 (no act)
    plain_bf16_kernel<128, 8, 4, 1>
        <<<dim3(BB * NN / 128, 1, 2), 128>>>(
            p_H3, w[0][3], w[1][3], p_Z, H3, OUTD, S3, S4);
    gcn_bf16_kernel<128, 8, 4, 1, false, false>
        <<<dim3(4, 1, NZ), 128>>>(
            adjb, p_Z, nullptr, p_d, bia[0][3], bia[1][3], p_H4, OUTD);

    // 6) dynamic head params (uses conv3 = H3)
    dcl_params_kernel<<<NZ, 256>>>(task, wc, p_H3, p_WB);

    // 7) logits + interleave into cc
    cc_kernel<<<NZ, 256>>>(p_H4, p_WB, p_CC);

    // 8) final gram + softplus
    final_kernel<<<dim3(8, 8, NZ), dim3(16, 16)>>>(p_CC, out);

    (void)in_sizes; (void)n_in; (void)out_size;
}

// round 12
// speedup vs baseline: 7.2792x; 1.0597x over previous
#include <cuda_runtime.h>
#include <cuda_bf16.h>
#include <math.h>
#include <stdint.h>

#define NN 512
#define BB 64
#define NZ 128            // B*2 branch instances
#define H1 128
#define H2 64
#define H3 32
#define OUTD 8
#define CLS 16
#define PDIM 72           // OUT*OUT + OUT
#define CDIM 48           // H3 + CLS

// ---------------- scratch (static device buffers, no allocs) ----------------
static const size_t OFF_D   = 0;
static const size_t OFF_H1  = OFF_D   + (size_t)NZ*NN;
static const size_t OFF_H2  = OFF_H1  + (size_t)NZ*NN*H1;
static const size_t OFF_H3  = OFF_H2  + (size_t)NZ*NN*H2;
static const size_t OFF_H4  = OFF_H3  + (size_t)NZ*NN*H3;
static const size_t OFF_Z   = OFF_H4  + (size_t)NZ*NN*OUTD;
static const size_t OFF_WB  = OFF_Z   + (size_t)NZ*NN*H2;
static const size_t OFF_CC  = OFF_WB  + (size_t)NZ*PDIM;
static const size_t TOTAL_SCRATCH = OFF_CC + (size_t)BB*2*NN*OUTD;

__device__ float g_scratch[TOTAL_SCRATCH];
// adj as packed bf16x2 (k-pairs): [b2][512][256] uint32
__device__ uint32_t g_adjb[(size_t)NZ * NN * (NN / 2)];

// ---------------- bf16 helpers ------------------------------------------------
__device__ __forceinline__ uint32_t pack_bf16(float a, float b) {
    __nv_bfloat162 t = __floats2bfloat162_rn(a, b);
    return *reinterpret_cast<uint32_t*>(&t);
}
__device__ __forceinline__ void split_bf16(float v, float& hi, float& lo) {
    __nv_bfloat16 h = __float2bfloat16(v);
    hi = __bfloat162float(h);
    lo = v - hi;
}
// pair index p (0..15) -> permuted word offset within A row (plain kernel layout)
__device__ __forceinline__ int aperm(int p) {
    int q = p >> 2, j = p & 3;
    return (q >> 1) * 8 + (q & 1) + 2 * j;
}
__device__ __forceinline__ uint32_t smem_u32(const void* p) {
    uint32_t a;
    asm("{ .reg .u64 t; cvta.to.shared.u64 t, %1; cvt.u32.u64 %0, t; }" : "=r"(a) : "l"(p));
    return a;
}

__device__ __forceinline__ void mma_bf16(float c[4],
    uint32_t a0, uint32_t a1, uint32_t a2, uint32_t a3,
    uint32_t b0, uint32_t b1) {
    asm volatile(
        "mma.sync.aligned.m16n8k16.row.col.f32.bf16.bf16.f32 "
        "{%0,%1,%2,%3}, {%4,%5,%6,%7}, {%8,%9}, {%0,%1,%2,%3};"
        : "+f"(c[0]), "+f"(c[1]), "+f"(c[2]), "+f"(c[3])
        : "r"(a0), "r"(a1), "r"(a2), "r"(a3), "r"(b0), "r"(b1));
}

// ---------------- preprocess: rowsum (d) + adj -> packed bf16 -----------------
__global__ void prep_kernel(const float* __restrict__ adj,
                            float* __restrict__ dout,
                            uint32_t* __restrict__ adjb) {
    int gw   = (blockIdx.x * blockDim.x + threadIdx.x) >> 5;
    int lane = threadIdx.x & 31;
    int b2  = gw >> 9;
    int row = gw & 511;
    const float4* r4 = (const float4*)(adj + (size_t)b2 * NN * NN + (size_t)row * NN);
    uint2* w2 = (uint2*)(adjb + (size_t)b2 * NN * (NN / 2) + (size_t)row * (NN / 2));
    float ssum = 0.f;
    #pragma unroll
    for (int j = lane; j < NN / 4; j += 32) {
        float4 v = r4[j];
        ssum += (v.x + v.y) + (v.z + v.w);
        uint2 p;
        p.x = pack_bf16(v.x, v.y);
        p.y = pack_bf16(v.z, v.w);
        w2[j] = p;
    }
    #pragma unroll
    for (int o = 16; o; o >>= 1) ssum += __shfl_xor_sync(0xffffffffu, ssum, o);
    if (lane == 0) {
        int s = b2 & 1, b = b2 >> 1;
        dout[(size_t)(s * BB + b) * NN + row] = rsqrtf(ssum + 1.0f);
    }
}

// ---------------- GCN layer: bf16 MMA, cp.async A + double-buffered smem ------
// blockIdx.z = z in [0,128): s=z>>6, b=z&63, adjb index b2=b*2+s
// C_z = epi(adj @ (d∘Z)); epilogue adds d_i^2*Z_i + bias (+leaky)
// A tiles: cp.async, natural k-pair order, row stride 20 words (conflict-free).
// B tiles: register-staged (d∘Z, bf16 pack), paired layout.
template<int BM, int BN, int WGM, int WGN, bool ACT, bool ZSHARED>
__global__ void __launch_bounds__(WGM*WGN*32, (WGM*WGN*32 == 256) ? 3 : 5)
gcn_bf16_kernel(const uint32_t* __restrict__ Adjb,
                const float* __restrict__ B0,
                const float* __restrict__ B1,
                const float* __restrict__ dbase,
                const float* __restrict__ bias0,
                const float* __restrict__ bias1,
                float* __restrict__ Cbase,
                int Ncols)
{
    constexpr int BK = 32;
    constexpr int KP = BK / 2;          // 16 pairs per tile
    constexpr int WM = BM / WGM, WN = BN / WGN;
    constexpr int MT = WM / 16, NT = WN / 8;
    constexpr int NTHREADS = WGM * WGN * 32;
    constexpr int ASTR = 20;            // u32 per A row (16 data + 4 pad)
    constexpr int BNP = (BN == 8) ? 20 : BN + 4;
    constexpr int A_CH = BM * 4 / NTHREADS;  // 16B cp.async chunks per thread
    constexpr int B_TOTP = KP * BN;
    constexpr int B_LDP = (B_TOTP + NTHREADS - 1) / NTHREADS;
    constexpr int NTILES = NN / BK;     // 16

    __shared__ uint32_t Asm[2][BM][ASTR];
    __shared__ __align__(16) uint32_t Bsm[2][2][4][BNP][2];

    const int z = blockIdx.z;
    const int s = z >> 6, b = z & 63;
    const uint32_t* A = Adjb + (size_t)(b * 2 + s) * NN * (NN / 2);
    const float* B    = ZSHARED ? (s ? B1 : B0) : B0 + (size_t)z * NN * Ncols;
    const float* bias = s ? bias1 : bias0;
    const float* dz   = dbase + (size_t)z * NN;
    float* C          = Cbase + (size_t)z * NN * Ncols;

    const int m0 = blockIdx.x * BM;
    const int tid = threadIdx.x;
    const int w = tid >> 5, lane = tid & 31;
    const int g = lane >> 2, tig = lane & 3;
    const int wm = (w / WGN) * WM;
    const int wn = (w % WGN) * WN;

    float acc[MT][NT][4] = {};
    float2 bF[B_LDP];

    // A tile loader: cp.async 16B chunks, natural pair order, commit group
    auto cpasync_a = [&](int c, int buf) {
        #pragma unroll
        for (int i = 0; i < A_CH; i++) {
            int idx = tid + i * NTHREADS;
            int r = idx >> 2, q = idx & 3;
            uint32_t dst = smem_u32(&Asm[buf][r][q * 4]);
            const uint32_t* src = &A[(size_t)(m0 + r) * (NN / 2) + c * KP + q * 4];
            asm volatile("cp.async.cg.shared.global [%0], [%1], 16;"
                         :: "r"(dst), "l"(src));
        }
        asm volatile("cp.async.commit_group;");
    };
    auto ldg_b = [&](int c) {
        #pragma unroll
        for (int i = 0; i < B_LDP; i++) {
            int e = tid + i * NTHREADS;
            if (e < B_TOTP) {
                int p = e / BN, n = e % BN;
                int k = c * BK + 2 * p;
                bF[i].x = B[(size_t)k * Ncols + n] * dz[k];
                bF[i].y = B[(size_t)(k + 1) * Ncols + n] * dz[k + 1];
            }
        }
    };
    auto sts_b = [&](int buf) {
        #pragma unroll
        for (int i = 0; i < B_LDP; i++) {
            int e = tid + i * NTHREADS;
            if (e < B_TOTP) {
                int p = e / BN, n = e % BN;
                Bsm[buf][p >> 3][p & 3][n][(p >> 2) & 1] = pack_bf16(bF[i].x, bF[i].y);
            }
        }
    };

    // prologue
    cpasync_a(0, 0);
    ldg_b(0);
    sts_b(0);
    asm volatile("cp.async.wait_group 0;");
    __syncthreads();

    for (int c = 0; c < NTILES; c++) {
        const int cur = c & 1, nxt = cur ^ 1;
        if (c + 1 < NTILES) {
            cpasync_a(c + 1, nxt);
            ldg_b(c + 1);
        }

        // MMAs from buffer cur
        #pragma unroll
        for (int kk = 0; kk < 2; kk++) {
            uint32_t a0[MT], a1[MT], a2[MT], a3[MT];
            uint32_t b0[NT], b1[NT];
            #pragma unroll
            for (int mt = 0; mt < MT; mt++) {
                int r0 = wm + mt * 16 + g;
                a0[mt] = Asm[cur][r0][kk * 8 + tig];
                a2[mt] = Asm[cur][r0][kk * 8 + 4 + tig];
                a1[mt] = Asm[cur][r0 + 8][kk * 8 + tig];
                a3[mt] = Asm[cur][r0 + 8][kk * 8 + 4 + tig];
            }
            #pragma unroll
            for (int nt = 0; nt < NT; nt++) {
                int cb = wn + nt * 8 + g;
                uint2 bb = *(const uint2*)&Bsm[cur][kk][tig][cb][0];
                b0[nt] = bb.x; b1[nt] = bb.y;
            }
            #pragma unroll
            for (int mt = 0; mt < MT; mt++)
                #pragma unroll
                for (int nt = 0; nt < NT; nt++)
                    mma_bf16(acc[mt][nt], a0[mt], a1[mt], a2[mt], a3[mt],
                             b0[nt], b1[nt]);
        }

        if (c + 1 < NTILES) {
            sts_b(nxt);
            asm volatile("cp.async.wait_group 0;");
        }
        __syncthreads();
    }

    // epilogue: v = d_i * acc + d_i^2 * Z_i + bias (+leaky)
    #pragma unroll
    for (int mt = 0; mt < MT; mt++) {
        int r0 = m0 + wm + mt * 16 + g;
        int r1 = r0 + 8;
        float d0 = dz[r0], d1 = dz[r1];
        #pragma unroll
        for (int nt = 0; nt < NT; nt++) {
            int c = wn + nt * 8 + tig * 2;
            float2 z0 = *(const float2*)&B[(size_t)r0 * Ncols + c];
            float2 z1 = *(const float2*)&B[(size_t)r1 * Ncols + c];
            float bc0 = bias[c], bc1 = bias[c + 1];
            float v00 = d0 * acc[mt][nt][0] + d0 * d0 * z0.x + bc0;
            float v01 = d0 * acc[mt][nt][1] + d0 * d0 * z0.y + bc1;
            float v10 = d1 * acc[mt][nt][2] + d1 * d1 * z1.x + bc0;
            float v11 = d1 * acc[mt][nt][3] + d1 * d1 * z1.y + bc1;
            if (ACT) {
                v00 = (v00 >= 0.f) ? v00 : 0.2f * v00;
                v01 = (v01 >= 0.f) ? v01 : 0.2f * v01;
                v10 = (v10 >= 0.f) ? v10 : 0.2f * v10;
                v11 = (v11 >= 0.f) ? v11 : 0.2f * v11;
            }
            *(float2*)&C[(size_t)r0 * Ncols + c] = make_float2(v00, v01);
            *(float2*)&C[(size_t)r1 * Ncols + c] = make_float2(v10, v11);
        }
    }
}

// ---------------- plain bf16 split GEMM: C = A_s @ W_s ------------------------
// A, W split bf16 hi+lo; 3 MMAs per k16 (hh, hl, lh); per-term error ~2^-17.
template<int BM, int BN, int WGM, int WGN>
__global__ void __launch_bounds__(WGM*WGN*32, (WGM*WGN*32 == 256) ? 2 : 4)
plain_bf16_kernel(const float* __restrict__ Abase,
                  const float* __restrict__ B0,
                  const float* __restrict__ B1,
                  float* __restrict__ Cbase,
                  int K, int Ncols, size_t sA, size_t sC)
{
    constexpr int BK = 32;
    constexpr int KP = BK / 2;
    constexpr int WM = BM / WGM, WN = BN / WGN;
    constexpr int MT = WM / 16, NT = WN / 8;
    constexpr int NTHREADS = WGM * WGN * 32;
    constexpr int ASTRIDE = 24;
    constexpr int BNP = (BN == 8) ? 20 : BN + 4;
    constexpr int A_TOT4 = BM * BK / 4;
    constexpr int A_LD4 = (A_TOT4 + NTHREADS - 1) / NTHREADS;
    constexpr int B_TOTP = KP * BN;
    constexpr int B_LDP = (B_TOTP + NTHREADS - 1) / NTHREADS;

    __shared__ uint32_t Ah[BM][ASTRIDE], Al[BM][ASTRIDE];
    __shared__ __align__(16) uint32_t Bh[2][4][BNP][2], Bl[2][4][BNP][2];

    const int z = blockIdx.z;
    const float* A = Abase + (size_t)z * sA;
    const float* B = z ? B1 : B0;
    float* C = Cbase + (size_t)z * sC;

    const int m0 = blockIdx.x * BM;
    const int tid = threadIdx.x;
    const int w = tid >> 5, lane = tid & 31;
    const int g = lane >> 2, tig = lane & 3;
    const int wm = (w / WGN) * WM;
    const int wn = (w % WGN) * WN;

    float acc[MT][NT][4] = {};
    float4 aF[A_LD4];
    float2 bF[B_LDP];

    #pragma unroll
    for (int i = 0; i < A_LD4; i++) {
        int idx = tid + i * NTHREADS;
        if (idx < A_TOT4) {
            int r = idx / (BK / 4), c4 = (idx % (BK / 4)) * 4;
            aF[i] = *(const float4*)&A[(size_t)(m0 + r) * K + c4];
        }
    }
    #pragma unroll
    for (int i = 0; i < B_LDP; i++) {
        int e = tid + i * NTHREADS;
        if (e < B_TOTP) {
            int p = e / BN, n = e % BN;
            bF[i].x = B[(size_t)(2 * p) * Ncols + n];
            bF[i].y = B[(size_t)(2 * p + 1) * Ncols + n];
        }
    }

    for (int k0 = 0; k0 < K; k0 += BK) {
        // store split tiles into smem
        #pragma unroll
        for (int i = 0; i < A_LD4; i++) {
            int idx = tid + i * NTHREADS;
            if (idx < A_TOT4) {
                int r = idx / (BK / 4), c4 = (idx % (BK / 4)) * 4;
                int p0 = c4 >> 1;
                float hx, lx, hy, ly, hz, lz, hw, lw;
                split_bf16(aF[i].x, hx, lx); split_bf16(aF[i].y, hy, ly);
                split_bf16(aF[i].z, hz, lz); split_bf16(aF[i].w, hw, lw);
                int w0 = aperm(p0), w1 = aperm(p0 + 1);
                Ah[r][w0] = pack_bf16(hx, hy); Al[r][w0] = pack_bf16(lx, ly);
                Ah[r][w1] = pack_bf16(hz, hw); Al[r][w1] = pack_bf16(lz, lw);
            }
        }
        #pragma unroll
        for (int i = 0; i < B_LDP; i++) {
            int e = tid + i * NTHREADS;
            if (e < B_TOTP) {
                int p = e / BN, n = e % BN;
                float hx, lx, hy, ly;
                split_bf16(bF[i].x, hx, lx); split_bf16(bF[i].y, hy, ly);
                Bh[p >> 3][p & 3][n][(p >> 2) & 1] = pack_bf16(hx, hy);
                Bl[p >> 3][p & 3][n][(p >> 2) & 1] = pack_bf16(lx, ly);
            }
        }
        __syncthreads();

        // prefetch next tile
        if (k0 + BK < K) {
            #pragma unroll
            for (int i = 0; i < A_LD4; i++) {
                int idx = tid + i * NTHREADS;
                if (idx < A_TOT4) {
                    int r = idx / (BK / 4), c4 = (idx % (BK / 4)) * 4;
                    aF[i] = *(const float4*)&A[(size_t)(m0 + r) * K + (k0 + BK) + c4];
                }
            }
            #pragma unroll
            for (int i = 0; i < B_LDP; i++) {
                int e = tid + i * NTHREADS;
                if (e < B_TOTP) {
                    int p = e / BN, n = e % BN;
                    int k = k0 + BK + 2 * p;
                    bF[i].x = B[(size_t)k * Ncols + n];
                    bF[i].y = B[(size_t)(k + 1) * Ncols + n];
                }
            }
        }

        #pragma unroll
        for (int kk = 0; kk < 2; kk++) {
            uint32_t ah0[MT], ah1[MT], ah2[MT], ah3[MT];
            uint32_t al0[MT], al1[MT], al2[MT], al3[MT];
            uint32_t bh0[NT], bh1[NT], bl0[NT], bl1[NT];
            #pragma unroll
            for (int mt = 0; mt < MT; mt++) {
                int r0 = wm + mt * 16 + g;
                uint2 h0 = *(const uint2*)&Ah[r0][kk * 8 + 2 * tig];
                uint2 h1 = *(const uint2*)&Ah[r0 + 8][kk * 8 + 2 * tig];
                uint2 l0 = *(const uint2*)&Al[r0][kk * 8 + 2 * tig];
                uint2 l1 = *(const uint2*)&Al[r0 + 8][kk * 8 + 2 * tig];
                ah0[mt] = h0.x; ah2[mt] = h0.y;
                ah1[mt] = h1.x; ah3[mt] = h1.y;
                al0[mt] = l0.x; al2[mt] = l0.y;
                al1[mt] = l1.x; al3[mt] = l1.y;
            }
            #pragma unroll
            for (int nt = 0; nt < NT; nt++) {
                int cb = wn + nt * 8 + g;
                uint2 bh = *(const uint2*)&Bh[kk][tig][cb][0];
                uint2 bl = *(const uint2*)&Bl[kk][tig][cb][0];
                bh0[nt] = bh.x; bh1[nt] = bh.y;
                bl0[nt] = bl.x; bl1[nt] = bl.y;
            }
            #pragma unroll
            for (int mt = 0; mt < MT; mt++)
                #pragma unroll
                for (int nt = 0; nt < NT; nt++) {
                    mma_bf16(acc[mt][nt], ah0[mt], ah1[mt], ah2[mt], ah3[mt],
                             bh0[nt], bh1[nt]);
                    mma_bf16(acc[mt][nt], ah0[mt], ah1[mt], ah2[mt], ah3[mt],
                             bl0[nt], bl1[nt]);
                    mma_bf16(acc[mt][nt], al0[mt], al1[mt], al2[mt], al3[mt],
                             bh0[nt], bh1[nt]);
                }
        }
        __syncthreads();
    }

    #pragma unroll
    for (int mt = 0; mt < MT; mt++) {
        int r0 = m0 + wm + mt * 16 + g;
        int r1 = r0 + 8;
        #pragma unroll
        for (int nt = 0; nt < NT; nt++) {
            int c = wn + nt * 8 + tig * 2;
            *(float2*)&C[(size_t)r0 * Ncols + c] = make_float2(acc[mt][nt][0], acc[mt][nt][1]);
            *(float2*)&C[(size_t)r1 * Ncols + c] = make_float2(acc[mt][nt][2], acc[mt][nt][3]);
        }
    }
}

// ---------------- dynamic head params ---------------------------------------
__global__ void dcl_params_kernel(const int* __restrict__ task,
                                  const float* __restrict__ wc,
                                  const float* __restrict__ H3b,
                                  float* __restrict__ wb) {
    int z = blockIdx.x;
    int b = z & 63;
    const float* conv3 = H3b + (size_t)z * NN * H3;
    __shared__ float partial[256];
    __shared__ float xc[CDIM];
    int tid = threadIdx.x;
    int col = tid & 31, g = tid >> 5;
    float p = 0.f;
    for (int r = g; r < NN; r += 8) p += conv3[(size_t)r * H3 + col];
    partial[tid] = p;
    __syncthreads();
    if (tid < H3) {
        float sum = 0.f;
        #pragma unroll
        for (int gg = 0; gg < 8; gg++) sum += partial[gg * 32 + tid];
        xc[tid] = sum * (1.0f / (float)NN);
    }
    if (tid >= H3 && tid < CDIM) {
        xc[tid] = (task[b] == tid - H3) ? 1.f : 0.f;
    }
    __syncthreads();
    if (tid < PDIM) {
        float acc = 0.f;
        #pragma unroll
        for (int c = 0; c < CDIM; c++) acc += wc[tid * CDIM + c] * xc[c];
        wb[(size_t)z * PDIM + tid] = acc;
    }
}

// ---------------- cc kernel: logits + interleave scatter --------------------
__global__ void cc_kernel(const float* __restrict__ H4b,
                          const float* __restrict__ wb,
                          float* __restrict__ cc) {
    int z = blockIdx.x;
    int q = z >> 6, b = z & 63;
    __shared__ float flat[NN * OUTD];
    __shared__ float wm[64];
    __shared__ float bv[8];
    int tid = threadIdx.x;
    const float4* src4 = (const float4*)(H4b + (size_t)z * NN * OUTD);
    float4* dst4 = (float4*)flat;
    for (int i = tid; i < NN * OUTD / 4; i += 256) dst4[i] = src4[i];
    if (tid < 64) wm[tid] = wb[(size_t)z * PDIM + tid];
    if (tid < 8)  bv[tid] = wb[(size_t)z * PDIM + 64 + tid];
    __syncthreads();
    for (int f = tid; f < NN * OUTD; f += 256) {
        int r = f >> 9, c = f & 511;
        float v = bv[r];
        #pragma unroll
        for (int i = 0; i < 8; i++) v += wm[r * 8 + i] * flat[i * NN + c];
        int n = f >> 3, o = f & 7;
        int scc = n >> 8;
        int n2 = ((n & 255) << 1) | q;
        cc[(((size_t)(b * 2 + scc) * NN + n2) << 3) + o] = v;
    }
}

// ---------------- final: out = softplus(-(cc @ cc^T)) -----------------------
__global__ void final_kernel(const float* __restrict__ cc, float* __restrict__ out) {
    int zz = blockIdx.z;
    __shared__ float Msm[NN * OUTD];
    int tid = threadIdx.y * 16 + threadIdx.x;
    const float4* src = (const float4*)(cc + (size_t)zz * NN * OUTD);
    float4* dst = (float4*)Msm;
    for (int i = tid; i < NN * OUTD / 4; i += 256) dst[i] = src[i];
    __syncthreads();
    int i0 = blockIdx.y * 64 + threadIdx.y * 4;
    int j0 = blockIdx.x * 64 + threadIdx.x * 4;
    float ai[4][8], aj[4][8];
    #pragma unroll
    for (int m = 0; m < 4; m++)
        #pragma unroll
        for (int o = 0; o < 8; o++) ai[m][o] = Msm[(i0 + m) * 8 + o];
    #pragma unroll
    for (int n = 0; n < 4; n++)
        #pragma unroll
        for (int o = 0; o < 8; o++) aj[n][o] = Msm[(j0 + n) * 8 + o];
    float* ob = out + (size_t)zz * NN * NN;
    #pragma unroll
    for (int m = 0; m < 4; m++) {
        float r[4];
        #pragma unroll
        for (int n = 0; n < 4; n++) {
            float x = 0.f;
            #pragma unroll
            for (int o = 0; o < 8; o++) x += ai[m][o] * aj[n][o];
            r[n] = __logf(1.0f + __expf(-fabsf(x))) + fmaxf(-x, 0.f);
        }
        *(float4*)(ob + (size_t)(i0 + m) * NN + j0) = make_float4(r[0], r[1], r[2], r[3]);
    }
}

// ---------------- host orchestration ----------------------------------------
extern "C" void kernel_launch(void* const* d_in, const int* in_sizes, int n_in,
                              void* d_out, int out_size) {
    const float* adj  = (const float*)d_in[0];
    const int*   task = (const int*)d_in[1];
    const float* w[2][4];
    const float* bia[2][4];
    int idx = 2;
    for (int s = 0; s < 2; s++)
        for (int l = 0; l < 4; l++) {
            w[s][l]   = (const float*)d_in[idx++];
            bia[s][l] = (const float*)d_in[idx++];
        }
    const float* wc = (const float*)d_in[18];
    float* out = (float*)d_out;

    float* base = nullptr;
    cudaGetSymbolAddress((void**)&base, g_scratch);
    uint32_t* adjb = nullptr;
    cudaGetSymbolAddress((void**)&adjb, g_adjb);
    float* p_d  = base + OFF_D;
    float* p_H1 = base + OFF_H1;
    float* p_H2 = base + OFF_H2;
    float* p_H3 = base + OFF_H3;
    float* p_H4 = base + OFF_H4;
    float* p_Z  = base + OFF_Z;
    float* p_WB = base + OFF_WB;
    float* p_CC = base + OFF_CC;

    const size_t S1  = (size_t)BB * NN * H1;
    const size_t S2  = (size_t)BB * NN * H2;
    const size_t S3  = (size_t)BB * NN * H3;
    const size_t S4  = (size_t)BB * NN * OUTD;

    // 1) preprocess: degree factors + adj -> bf16
    prep_kernel<<<NZ * NN / 8, 256>>>(adj, p_d, adjb);

    // 2) layer 1: H1 = leaky(feat @ w1 + b1), Z = w1 shared per-branch
    gcn_bf16_kernel<64, 128, 2, 4, true, true>
        <<<dim3(8, 1, NZ), 256>>>(
            adjb, w[0][0], w[1][0], p_d, bia[0][0], bia[1][0], p_H1, H1);

    // 3) layer 2: Z = H1 @ w2 ; H2 = leaky(feat @ Z + b2)
    plain_bf16_kernel<128, 64, 4, 2>
        <<<dim3(BB * NN / 128, 1, 2), 256>>>(
            p_H1, w[0][1], w[1][1], p_Z, H1, H2, S1, S2);
    gcn_bf16_kernel<128, 64, 4, 2, true, false>
        <<<dim3(4, 1, NZ), 256>>>(
            adjb, p_Z, nullptr, p_d, bia[0][1], bia[1][1], p_H2, H2);

    // 4) layer 3: Z = H2 @ w3 ; H3 = leaky(feat @ Z + b3)
    plain_bf16_kernel<128, 32, 4, 1>
        <<<dim3(BB * NN / 128, 1, 2), 128>>>(
            p_H2, w[0][2], w[1][2], p_Z, H2, H3, S2, S3);
    gcn_bf16_kernel<128, 32, 4, 1, true, false>
        <<<dim3(4, 1, NZ), 128>>>(
            adjb, p_Z, nullptr, p_d, bia[0][2], bia[1][2], p_H3, H3);

    // 5) layer 4: Z = H3 @ w4 ; H4 = feat @ Z + b4 (no act)
    plain_bf16_kernel<128, 8, 4, 1>
        <<<dim3(BB * NN / 128, 1, 2), 128>>>(
            p_H3, w[0][3], w[1][3], p_Z, H3, OUTD, S3, S4);
    gcn_bf16_kernel<128, 8, 4, 1, false, false>
        <<<dim3(4, 1, NZ), 128>>>(
            adjb, p_Z, nullptr, p_d, bia[0][3], bia[1][3], p_H4, OUTD);

    // 6) dynamic head params (uses conv3 = H3)
    dcl_params_kernel<<<NZ, 256>>>(task, wc, p_H3, p_WB);

    // 7) logits + interleave into cc
    cc_kernel<<<NZ, 256>>>(p_H4, p_WB, p_CC);

    // 8) final gram + softplus
    final_kernel<<<dim3(8, 8, NZ), dim3(16, 16)>>>(p_CC, out);

    (void)in_sizes; (void)n_in; (void)out_size;
}

// round 13
// speedup vs baseline: 8.0736x; 1.1091x over previous
#include <cuda_runtime.h>
#include <cuda_bf16.h>
#include <math.h>
#include <stdint.h>

#define NN 512
#define BB 64
#define NZ 128            // B*2 branch instances
#define H1 128
#define H2 64
#define H3 32
#define OUTD 8
#define CLS 16
#define PDIM 72           // OUT*OUT + OUT
#define CDIM 48           // H3 + CLS

// ---------------- scratch (static device buffers, no allocs) ----------------
static const size_t OFF_D   = 0;
static const size_t OFF_H1  = OFF_D   + (size_t)NZ*NN;
static const size_t OFF_H2  = OFF_H1  + (size_t)NZ*NN*H1;
static const size_t OFF_H3  = OFF_H2  + (size_t)NZ*NN*H2;
static const size_t OFF_H4  = OFF_H3  + (size_t)NZ*NN*H3;
static const size_t OFF_Z   = OFF_H4  + (size_t)NZ*NN*OUTD;
static const size_t OFF_WB  = OFF_Z   + (size_t)NZ*NN*H2;
static const size_t OFF_CC  = OFF_WB  + (size_t)NZ*PDIM;
static const size_t TOTAL_SCRATCH = OFF_CC + (size_t)BB*2*NN*OUTD;

__device__ float g_scratch[TOTAL_SCRATCH];
// adj as packed bf16x2 (k-pairs): [b2][512][256] uint32
__device__ uint32_t g_adjb[(size_t)NZ * NN * (NN / 2)];

// ---------------- bf16 helpers ------------------------------------------------
__device__ __forceinline__ uint32_t pack_bf16(float a, float b) {
    __nv_bfloat162 t = __floats2bfloat162_rn(a, b);
    return *reinterpret_cast<uint32_t*>(&t);
}
__device__ __forceinline__ void split_bf16(float v, float& hi, float& lo) {
    __nv_bfloat16 h = __float2bfloat16(v);
    hi = __bfloat162float(h);
    lo = v - hi;
}
// pair index p (0..15) -> permuted word offset within A row (plain kernel layout)
__device__ __forceinline__ int aperm(int p) {
    int q = p >> 2, j = p & 3;
    return (q >> 1) * 8 + (q & 1) + 2 * j;
}
__device__ __forceinline__ uint32_t smem_u32(const void* p) {
    uint32_t a;
    asm("{ .reg .u64 t; cvta.to.shared.u64 t, %1; cvt.u32.u64 %0, t; }" : "=r"(a) : "l"(p));
    return a;
}

__device__ __forceinline__ void mma_bf16(float c[4],
    uint32_t a0, uint32_t a1, uint32_t a2, uint32_t a3,
    uint32_t b0, uint32_t b1) {
    asm volatile(
        "mma.sync.aligned.m16n8k16.row.col.f32.bf16.bf16.f32 "
        "{%0,%1,%2,%3}, {%4,%5,%6,%7}, {%8,%9}, {%0,%1,%2,%3};"
        : "+f"(c[0]), "+f"(c[1]), "+f"(c[2]), "+f"(c[3])
        : "r"(a0), "r"(a1), "r"(a2), "r"(a3), "r"(b0), "r"(b1));
}

// ---------------- preprocess: rowsum (d) + adj -> packed bf16 -----------------
__global__ void prep_kernel(const float* __restrict__ adj,
                            float* __restrict__ dout,
                            uint32_t* __restrict__ adjb) {
    int gw   = (blockIdx.x * blockDim.x + threadIdx.x) >> 5;
    int lane = threadIdx.x & 31;
    int b2  = gw >> 9;
    int row = gw & 511;
    const float4* r4 = (const float4*)(adj + (size_t)b2 * NN * NN + (size_t)row * NN);
    uint2* w2 = (uint2*)(adjb + (size_t)b2 * NN * (NN / 2) + (size_t)row * (NN / 2));
    float ssum = 0.f;
    #pragma unroll
    for (int j = lane; j < NN / 4; j += 32) {
        float4 v = r4[j];
        ssum += (v.x + v.y) + (v.z + v.w);
        uint2 p;
        p.x = pack_bf16(v.x, v.y);
        p.y = pack_bf16(v.z, v.w);
        w2[j] = p;
    }
    #pragma unroll
    for (int o = 16; o; o >>= 1) ssum += __shfl_xor_sync(0xffffffffu, ssum, o);
    if (lane == 0) {
        int s = b2 & 1, b = b2 >> 1;
        dout[(size_t)(s * BB + b) * NN + row] = rsqrtf(ssum + 1.0f);
    }
}

// ---------------- GCN layer: bf16 MMA, BK=64, cp.async A, dyn smem ------------
// blockIdx.z = z in [0,128): s=z>>6, b=z&63, adjb index b2=b*2+s
// blockIdx.y = n-tile (only >0 for layer 1 ZSHARED)
// C_z = epi(adj @ (d∘Z)); epilogue adds d_i^2*Z_i + bias (+leaky)
template<int BM, int BN, int WGM, int WGN, bool ACT, bool ZSHARED>
__global__ void __launch_bounds__(WGM*WGN*32, (WGM*WGN*32 == 256) ? 3 : 4)
gcn_bf16_kernel(const uint32_t* __restrict__ Adjb,
                const float* __restrict__ B0,
                const float* __restrict__ B1,
                const float* __restrict__ dbase,
                const float* __restrict__ bias0,
                const float* __restrict__ bias1,
                float* __restrict__ Cbase,
                int Ncols)
{
    constexpr int BK = 64;
    constexpr int KP = BK / 2;          // 32 pairs per tile
    constexpr int KKS = BK / 16;        // 4 k16 steps
    constexpr int WM = BM / WGM, WN = BN / WGN;
    constexpr int MT = WM / 16, NT = WN / 8;
    constexpr int NTHREADS = WGM * WGN * 32;
    constexpr int ASTR = KP + 4;        // 36 u32 per A row
    constexpr int BNP = (BN == 8) ? 20 : BN + 4;
    constexpr int A_CH = BM * (KP / 4) / NTHREADS;  // 16B chunks per thread
    constexpr int B_TOTP = KP * BN;
    constexpr int B_LDP = (B_TOTP + NTHREADS - 1) / NTHREADS;
    constexpr int NTILES = NN / BK;     // 8
    constexpr int A_WORDS = 2 * BM * ASTR;

    extern __shared__ uint32_t smg[];
    uint32_t* Bbase = smg + A_WORDS;
    // A word: buf*BM*ASTR + r*ASTR + w ; B word: (((buf*KKS+kk)*4+t)*BNP+n)*2+j

    const int z = blockIdx.z;
    const int s = z >> 6, b = z & 63;
    const int n0 = blockIdx.y * BN;
    const uint32_t* A = Adjb + (size_t)(b * 2 + s) * NN * (NN / 2);
    const float* B    = ZSHARED ? (s ? B1 : B0) : B0 + (size_t)z * NN * Ncols;
    const float* bias = s ? bias1 : bias0;
    const float* dz   = dbase + (size_t)z * NN;
    float* C          = Cbase + (size_t)z * NN * Ncols;

    const int m0 = blockIdx.x * BM;
    const int tid = threadIdx.x;
    const int w = tid >> 5, lane = tid & 31;
    const int g = lane >> 2, tig = lane & 3;
    const int wm = (w / WGN) * WM;
    const int wn = (w % WGN) * WN;

    float acc[MT][NT][4] = {};
    float2 bF[B_LDP];

    auto cpasync_a = [&](int c, int buf) {
        #pragma unroll
        for (int i = 0; i < A_CH; i++) {
            int idx = tid + i * NTHREADS;
            int r = idx / (KP / 4), q = idx % (KP / 4);
            uint32_t dst = smem_u32(&smg[buf * BM * ASTR + r * ASTR + q * 4]);
            const uint32_t* src = &A[(size_t)(m0 + r) * (NN / 2) + c * KP + q * 4];
            asm volatile("cp.async.cg.shared.global [%0], [%1], 16;"
                         :: "r"(dst), "l"(src));
        }
        asm volatile("cp.async.commit_group;");
    };
    auto ldg_b = [&](int c) {
        #pragma unroll
        for (int i = 0; i < B_LDP; i++) {
            int e = tid + i * NTHREADS;
            if (e < B_TOTP) {
                int p = e / BN, n = e % BN;
                int k = c * BK + 2 * p;
                bF[i].x = B[(size_t)k * Ncols + n0 + n] * dz[k];
                bF[i].y = B[(size_t)(k + 1) * Ncols + n0 + n] * dz[k + 1];
            }
        }
    };
    auto sts_b = [&](int buf) {
        #pragma unroll
        for (int i = 0; i < B_LDP; i++) {
            int e = tid + i * NTHREADS;
            if (e < B_TOTP) {
                int p = e / BN, n = e % BN;
                int kk = p >> 3, t = p & 3, j = (p >> 2) & 1;
                Bbase[((((buf * KKS + kk) * 4 + t) * BNP + n) << 1) + j] =
                    pack_bf16(bF[i].x, bF[i].y);
            }
        }
    };

    // prologue
    cpasync_a(0, 0);
    ldg_b(0);
    sts_b(0);
    asm volatile("cp.async.wait_group 0;");
    __syncthreads();

    for (int c = 0; c < NTILES; c++) {
        const int cur = c & 1, nxt = cur ^ 1;
        if (c + 1 < NTILES) {
            cpasync_a(c + 1, nxt);
            ldg_b(c + 1);
        }

        // MMAs from buffer cur (4 k16 steps)
        #pragma unroll
        for (int kk = 0; kk < KKS; kk++) {
            uint32_t a0[MT], a1[MT], a2[MT], a3[MT];
            uint32_t b0[NT], b1[NT];
            #pragma unroll
            for (int mt = 0; mt < MT; mt++) {
                int r0 = wm + mt * 16 + g;
                const uint32_t* ar0 = &smg[cur * BM * ASTR + r0 * ASTR];
                const uint32_t* ar1 = ar0 + 8 * ASTR;
                a0[mt] = ar0[kk * 8 + tig];
                a2[mt] = ar0[kk * 8 + 4 + tig];
                a1[mt] = ar1[kk * 8 + tig];
                a3[mt] = ar1[kk * 8 + 4 + tig];
            }
            #pragma unroll
            for (int nt = 0; nt < NT; nt++) {
                int cb = wn + nt * 8 + g;
                uint2 bb = *(const uint2*)&Bbase[((((cur * KKS + kk) * 4 + tig) * BNP + cb) << 1)];
                b0[nt] = bb.x; b1[nt] = bb.y;
            }
            #pragma unroll
            for (int mt = 0; mt < MT; mt++)
                #pragma unroll
                for (int nt = 0; nt < NT; nt++)
                    mma_bf16(acc[mt][nt], a0[mt], a1[mt], a2[mt], a3[mt],
                             b0[nt], b1[nt]);
        }

        if (c + 1 < NTILES) {
            sts_b(nxt);
            asm volatile("cp.async.wait_group 0;");
        }
        __syncthreads();
    }

    // epilogue: v = d_i * acc + d_i^2 * Z_i + bias (+leaky)
    #pragma unroll
    for (int mt = 0; mt < MT; mt++) {
        int r0 = m0 + wm + mt * 16 + g;
        int r1 = r0 + 8;
        float d0 = dz[r0], d1 = dz[r1];
        #pragma unroll
        for (int nt = 0; nt < NT; nt++) {
            int c = n0 + wn + nt * 8 + tig * 2;
            float2 z0 = *(const float2*)&B[(size_t)r0 * Ncols + c];
            float2 z1 = *(const float2*)&B[(size_t)r1 * Ncols + c];
            float bc0 = bias[c], bc1 = bias[c + 1];
            float v00 = d0 * acc[mt][nt][0] + d0 * d0 * z0.x + bc0;
            float v01 = d0 * acc[mt][nt][1] + d0 * d0 * z0.y + bc1;
            float v10 = d1 * acc[mt][nt][2] + d1 * d1 * z1.x + bc0;
            float v11 = d1 * acc[mt][nt][3] + d1 * d1 * z1.y + bc1;
            if (ACT) {
                v00 = (v00 >= 0.f) ? v00 : 0.2f * v00;
                v01 = (v01 >= 0.f) ? v01 : 0.2f * v01;
                v10 = (v10 >= 0.f) ? v10 : 0.2f * v10;
                v11 = (v11 >= 0.f) ? v11 : 0.2f * v11;
            }
            *(float2*)&C[(size_t)r0 * Ncols + c] = make_float2(v00, v01);
            *(float2*)&C[(size_t)r1 * Ncols + c] = make_float2(v10, v11);
        }
    }
}

// gcn smem bytes
#define GCN_SMEM(BM, BN) ((2 * (BM) * 36 + 2 * 4 * 4 * (((BN) == 8) ? 20 : (BN) + 4) * 2) * 4)

// ---------------- plain bf16 split GEMM: C = A_s @ W_s ------------------------
// A, W split bf16 hi+lo; 3 MMAs per k16 (hh, hl, lh); per-term error ~2^-17.
template<int BM, int BN, int WGM, int WGN>
__global__ void __launch_bounds__(WGM*WGN*32, (WGM*WGN*32 == 256) ? 2 : 4)
plain_bf16_kernel(const float* __restrict__ Abase,
                  const float* __restrict__ B0,
                  const float* __restrict__ B1,
                  float* __restrict__ Cbase,
                  int K, int Ncols, size_t sA, size_t sC)
{
    constexpr int BK = 32;
    constexpr int KP = BK / 2;
    constexpr int WM = BM / WGM, WN = BN / WGN;
    constexpr int MT = WM / 16, NT = WN / 8;
    constexpr int NTHREADS = WGM * WGN * 32;
    constexpr int ASTRIDE = 24;
    constexpr int BNP = (BN == 8) ? 20 : BN + 4;
    constexpr int A_TOT4 = BM * BK / 4;
    constexpr int A_LD4 = (A_TOT4 + NTHREADS - 1) / NTHREADS;
    constexpr int B_TOTP = KP * BN;
    constexpr int B_LDP = (B_TOTP + NTHREADS - 1) / NTHREADS;

    __shared__ uint32_t Ah[BM][ASTRIDE], Al[BM][ASTRIDE];
    __shared__ __align__(16) uint32_t Bh[2][4][BNP][2], Bl[2][4][BNP][2];

    const int z = blockIdx.z;
    const float* A = Abase + (size_t)z * sA;
    const float* B = z ? B1 : B0;
    float* C = Cbase + (size_t)z * sC;

    const int m0 = blockIdx.x * BM;
    const int tid = threadIdx.x;
    const int w = tid >> 5, lane = tid & 31;
    const int g = lane >> 2, tig = lane & 3;
    const int wm = (w / WGN) * WM;
    const int wn = (w % WGN) * WN;

    float acc[MT][NT][4] = {};
    float4 aF[A_LD4];
    float2 bF[B_LDP];

    #pragma unroll
    for (int i = 0; i < A_LD4; i++) {
        int idx = tid + i * NTHREADS;
        if (idx < A_TOT4) {
            int r = idx / (BK / 4), c4 = (idx % (BK / 4)) * 4;
            aF[i] = *(const float4*)&A[(size_t)(m0 + r) * K + c4];
        }
    }
    #pragma unroll
    for (int i = 0; i < B_LDP; i++) {
        int e = tid + i * NTHREADS;
        if (e < B_TOTP) {
            int p = e / BN, n = e % BN;
            bF[i].x = B[(size_t)(2 * p) * Ncols + n];
            bF[i].y = B[(size_t)(2 * p + 1) * Ncols + n];
        }
    }

    for (int k0 = 0; k0 < K; k0 += BK) {
        #pragma unroll
        for (int i = 0; i < A_LD4; i++) {
            int idx = tid + i * NTHREADS;
            if (idx < A_TOT4) {
                int r = idx / (BK / 4), c4 = (idx % (BK / 4)) * 4;
                int p0 = c4 >> 1;
                float hx, lx, hy, ly, hz, lz, hw, lw;
                split_bf16(aF[i].x, hx, lx); split_bf16(aF[i].y, hy, ly);
                split_bf16(aF[i].z, hz, lz); split_bf16(aF[i].w, hw, lw);
                int w0 = aperm(p0), w1 = aperm(p0 + 1);
                Ah[r][w0] = pack_bf16(hx, hy); Al[r][w0] = pack_bf16(lx, ly);
                Ah[r][w1] = pack_bf16(hz, hw); Al[r][w1] = pack_bf16(lz, lw);
            }
        }
        #pragma unroll
        for (int i = 0; i < B_LDP; i++) {
            int e = tid + i * NTHREADS;
            if (e < B_TOTP) {
                int p = e / BN, n = e % BN;
                float hx, lx, hy, ly;
                split_bf16(bF[i].x, hx, lx); split_bf16(bF[i].y, hy, ly);
                Bh[p >> 3][p & 3][n][(p >> 2) & 1] = pack_bf16(hx, hy);
                Bl[p >> 3][p & 3][n][(p >> 2) & 1] = pack_bf16(lx, ly);
            }
        }
        __syncthreads();

        if (k0 + BK < K) {
            #pragma unroll
            for (int i = 0; i < A_LD4; i++) {
                int idx = tid + i * NTHREADS;
                if (idx < A_TOT4) {
                    int r = idx / (BK / 4), c4 = (idx % (BK / 4)) * 4;
                    aF[i] = *(const float4*)&A[(size_t)(m0 + r) * K + (k0 + BK) + c4];
                }
            }
            #pragma unroll
            for (int i = 0; i < B_LDP; i++) {
                int e = tid + i * NTHREADS;
                if (e < B_TOTP) {
                    int p = e / BN, n = e % BN;
                    int k = k0 + BK + 2 * p;
                    bF[i].x = B[(size_t)k * Ncols + n];
                    bF[i].y = B[(size_t)(k + 1) * Ncols + n];
                }
            }
        }

        #pragma unroll
        for (int kk = 0; kk < 2; kk++) {
            uint32_t ah0[MT], ah1[MT], ah2[MT], ah3[MT];
            uint32_t al0[MT], al1[MT], al2[MT], al3[MT];
            uint32_t bh0[NT], bh1[NT], bl0[NT], bl1[NT];
            #pragma unroll
            for (int mt = 0; mt < MT; mt++) {
                int r0 = wm + mt * 16 + g;
                uint2 h0 = *(const uint2*)&Ah[r0][kk * 8 + 2 * tig];
                uint2 h1 = *(const uint2*)&Ah[r0 + 8][kk * 8 + 2 * tig];
                uint2 l0 = *(const uint2*)&Al[r0][kk * 8 + 2 * tig];
                uint2 l1 = *(const uint2*)&Al[r0 + 8][kk * 8 + 2 * tig];
                ah0[mt] = h0.x; ah2[mt] = h0.y;
                ah1[mt] = h1.x; ah3[mt] = h1.y;
                al0[mt] = l0.x; al2[mt] = l0.y;
                al1[mt] = l1.x; al3[mt] = l1.y;
            }
            #pragma unroll
            for (int nt = 0; nt < NT; nt++) {
                int cb = wn + nt * 8 + g;
                uint2 bh = *(const uint2*)&Bh[kk][tig][cb][0];
                uint2 bl = *(const uint2*)&Bl[kk][tig][cb][0];
                bh0[nt] = bh.x; bh1[nt] = bh.y;
                bl0[nt] = bl.x; bl1[nt] = bl.y;
            }
            #pragma unroll
            for (int mt = 0; mt < MT; mt++)
                #pragma unroll
                for (int nt = 0; nt < NT; nt++) {
                    mma_bf16(acc[mt][nt], ah0[mt], ah1[mt], ah2[mt], ah3[mt],
                             bh0[nt], bh1[nt]);
                    mma_bf16(acc[mt][nt], ah0[mt], ah1[mt], ah2[mt], ah3[mt],
                             bl0[nt], bl1[nt]);
                    mma_bf16(acc[mt][nt], al0[mt], al1[mt], al2[mt], al3[mt],
                             bh0[nt], bh1[nt]);
                }
        }
        __syncthreads();
    }

    #pragma unroll
    for (int mt = 0; mt < MT; mt++) {
        int r0 = m0 + wm + mt * 16 + g;
        int r1 = r0 + 8;
        #pragma unroll
        for (int nt = 0; nt < NT; nt++) {
            int c = wn + nt * 8 + tig * 2;
            *(float2*)&C[(size_t)r0 * Ncols + c] = make_float2(acc[mt][nt][0], acc[mt][nt][1]);
            *(float2*)&C[(size_t)r1 * Ncols + c] = make_float2(acc[mt][nt][2], acc[mt][nt][3]);
        }
    }
}

// ---------------- dynamic head params ---------------------------------------
__global__ void dcl_params_kernel(const int* __restrict__ task,
                                  const float* __restrict__ wc,
                                  const float* __restrict__ H3b,
                                  float* __restrict__ wb) {
    int z = blockIdx.x;
    int b = z & 63;
    const float* conv3 = H3b + (size_t)z * NN * H3;
    __shared__ float partial[256];
    __shared__ float xc[CDIM];
    int tid = threadIdx.x;
    int col = tid & 31, g = tid >> 5;
    float p = 0.f;
    for (int r = g; r < NN; r += 8) p += conv3[(size_t)r * H3 + col];
    partial[tid] = p;
    __syncthreads();
    if (tid < H3) {
        float sum = 0.f;
        #pragma unroll
        for (int gg = 0; gg < 8; gg++) sum += partial[gg * 32 + tid];
        xc[tid] = sum * (1.0f / (float)NN);
    }
    if (tid >= H3 && tid < CDIM) {
        xc[tid] = (task[b] == tid - H3) ? 1.f : 0.f;
    }
    __syncthreads();
    if (tid < PDIM) {
        float acc = 0.f;
        #pragma unroll
        for (int c = 0; c < CDIM; c++) acc += wc[tid * CDIM + c] * xc[c];
        wb[(size_t)z * PDIM + tid] = acc;
    }
}

// ---------------- cc kernel: logits + interleave scatter --------------------
__global__ void cc_kernel(const float* __restrict__ H4b,
                          const float* __restrict__ wb,
                          float* __restrict__ cc) {
    int z = blockIdx.x;
    int q = z >> 6, b = z & 63;
    __shared__ float flat[NN * OUTD];
    __shared__ float wm[64];
    __shared__ float bv[8];
    int tid = threadIdx.x;
    const float4* src4 = (const float4*)(H4b + (size_t)z * NN * OUTD);
    float4* dst4 = (float4*)flat;
    for (int i = tid; i < NN * OUTD / 4; i += 256) dst4[i] = src4[i];
    if (tid < 64) wm[tid] = wb[(size_t)z * PDIM + tid];
    if (tid < 8)  bv[tid] = wb[(size_t)z * PDIM + 64 + tid];
    __syncthreads();
    for (int f = tid; f < NN * OUTD; f += 256) {
        int r = f >> 9, c = f & 511;
        float v = bv[r];
        #pragma unroll
        for (int i = 0; i < 8; i++) v += wm[r * 8 + i] * flat[i * NN + c];
        int n = f >> 3, o = f & 7;
        int scc = n >> 8;
        int n2 = ((n & 255) << 1) | q;
        cc[(((size_t)(b * 2 + scc) * NN + n2) << 3) + o] = v;
    }
}

// ---------------- final: out = softplus(-(cc @ cc^T)) -----------------------
__global__ void final_kernel(const float* __restrict__ cc, float* __restrict__ out) {
    int zz = blockIdx.z;
    __shared__ float Msm[NN * OUTD];
    int tid = threadIdx.y * 16 + threadIdx.x;
    const float4* src = (const float4*)(cc + (size_t)zz * NN * OUTD);
    float4* dst = (float4*)Msm;
    for (int i = tid; i < NN * OUTD / 4; i += 256) dst[i] = src[i];
    __syncthreads();
    int i0 = blockIdx.y * 64 + threadIdx.y * 4;
    int j0 = blockIdx.x * 64 + threadIdx.x * 4;
    float ai[4][8], aj[4][8];
    #pragma unroll
    for (int m = 0; m < 4; m++)
        #pragma unroll
        for (int o = 0; o < 8; o++) ai[m][o] = Msm[(i0 + m) * 8 + o];
    #pragma unroll
    for (int n = 0; n < 4; n++)
        #pragma unroll
        for (int o = 0; o < 8; o++) aj[n][o] = Msm[(j0 + n) * 8 + o];
    float* ob = out + (size_t)zz * NN * NN;
    #pragma unroll
    for (int m = 0; m < 4; m++) {
        float r[4];
        #pragma unroll
        for (int n = 0; n < 4; n++) {
            float x = 0.f;
            #pragma unroll
            for (int o = 0; o < 8; o++) x += ai[m][o] * aj[n][o];
            r[n] = __logf(1.0f + __expf(-fabsf(x))) + fmaxf(-x, 0.f);
        }
        *(float4*)(ob + (size_t)(i0 + m) * NN + j0) = make_float4(r[0], r[1], r[2], r[3]);
    }
}

// ---------------- host orchestration ----------------------------------------
extern "C" void kernel_launch(void* const* d_in, const int* in_sizes, int n_in,
                              void* d_out, int out_size) {
    const float* adj  = (const float*)d_in[0];
    const int*   task = (const int*)d_in[1];
    const float* w[2][4];
    const float* bia[2][4];
    int idx = 2;
    for (int s = 0; s < 2; s++)
        for (int l = 0; l < 4; l++) {
            w[s][l]   = (const float*)d_in[idx++];
            bia[s][l] = (const float*)d_in[idx++];
        }
    const float* wc = (const float*)d_in[18];
    float* out = (float*)d_out;

    float* base = nullptr;
    cudaGetSymbolAddress((void**)&base, g_scratch);
    uint32_t* adjb = nullptr;
    cudaGetSymbolAddress((void**)&adjb, g_adjb);
    float* p_d  = base + OFF_D;
    float* p_H1 = base + OFF_H1;
    float* p_H2 = base + OFF_H2;
    float* p_H3 = base + OFF_H3;
    float* p_H4 = base + OFF_H4;
    float* p_Z  = base + OFF_Z;
    float* p_WB = base + OFF_WB;
    float* p_CC = base + OFF_CC;

    const size_t S1  = (size_t)BB * NN * H1;
    const size_t S2  = (size_t)BB * NN * H2;
    const size_t S3  = (size_t)BB * NN * H3;
    const size_t S4  = (size_t)BB * NN * OUTD;

    // dynamic smem opt-ins for the >48KB gcn configs (idempotent)
    cudaFuncSetAttribute(
        (const void*)gcn_bf16_kernel<128, 64, 4, 2, true, true>,
        cudaFuncAttributeMaxDynamicSharedMemorySize, GCN_SMEM(128, 64));
    cudaFuncSetAttribute(
        (const void*)gcn_bf16_kernel<128, 64, 4, 2, true, false>,
        cudaFuncAttributeMaxDynamicSharedMemorySize, GCN_SMEM(128, 64));

    // 1) preprocess: degree factors + adj -> bf16
    prep_kernel<<<NZ * NN / 8, 256>>>(adj, p_d, adjb);

    // 2) layer 1: H1 = leaky(feat @ w1 + b1), Z = w1 shared per-branch
    gcn_bf16_kernel<128, 64, 4, 2, true, true>
        <<<dim3(4, 2, NZ), 256, GCN_SMEM(128, 64)>>>(
            adjb, w[0][0], w[1][0], p_d, bia[0][0], bia[1][0], p_H1, H1);

    // 3) layer 2: Z = H1 @ w2 ; H2 = leaky(feat @ Z + b2)
    plain_bf16_kernel<128, 64, 4, 2>
        <<<dim3(BB * NN / 128, 1, 2), 256>>>(
            p_H1, w[0][1], w[1][1], p_Z, H1, H2, S1, S2);
    gcn_bf16_kernel<128, 64, 4, 2, true, false>
        <<<dim3(4, 1, NZ), 256, GCN_SMEM(128, 64)>>>(
            adjb, p_Z, nullptr, p_d, bia[0][1], bia[1][1], p_H2, H2);

    // 4) layer 3: Z = H2 @ w3 ; H3 = leaky(feat @ Z + b3)
    plain_bf16_kernel<128, 32, 4, 1>
        <<<dim3(BB * NN / 128, 1, 2), 128>>>(
            p_H2, w[0][2], w[1][2], p_Z, H2, H3, S2, S3);
    gcn_bf16_kernel<128, 32, 4, 1, true, false>
        <<<dim3(4, 1, NZ), 128, GCN_SMEM(128, 32)>>>(
            adjb, p_Z, nullptr, p_d, bia[0][2], bia[1][2], p_H3, H3);

    // 5) layer 4: Z = H3 @ w4 ; H4 = feat @ Z + b4 (no act)
    plain_bf16_kernel<128, 8, 4, 1>
        <<<dim3(BB * NN / 128, 1, 2), 128>>>(
            p_H3, w[0][3], w[1][3], p_Z, H3, OUTD, S3, S4);
    gcn_bf16_kernel<128, 8, 4, 1, false, false>
        <<<dim3(4, 1, NZ), 128, GCN_SMEM(128, 8)>>>(
            adjb, p_Z, nullptr, p_d, bia[0][3], bia[1][3], p_H4, OUTD);

    // 6) dynamic head params (uses conv3 = H3)
    dcl_params_kernel<<<NZ, 256>>>(task, wc, p_H3, p_WB);

    // 7) logits + interleave into cc
    cc_kernel<<<NZ, 256>>>(p_H4, p_WB, p_CC);

    // 8) final gram + softplus
    final_kernel<<<dim3(8, 8, NZ), dim3(16, 16)>>>(p_CC, out);

    (void)in_sizes; (void)n_in; (void)out_size;
}

// round 14
// speedup vs baseline: 8.4548x; 1.0472x over previous
#include <cuda_runtime.h>
#include <cuda_bf16.h>
#include <math.h>
#include <stdint.h>

#define NN 512
#define BB 64
#define NZ 128            // B*2 branch instances
#define H1 128
#define H2 64
#define H3 32
#define OUTD 8
#define CLS 16
#define PDIM 72           // OUT*OUT + OUT
#define CDIM 48           // H3 + CLS

// ---------------- scratch (static device buffers, no allocs) ----------------
static const size_t OFF_D   = 0;
static const size_t OFF_H1  = OFF_D   + (size_t)NZ*NN;
static const size_t OFF_H2  = OFF_H1  + (size_t)NZ*NN*H1;
static const size_t OFF_H3  = OFF_H2  + (size_t)NZ*NN*H2;
static const size_t OFF_H4  = OFF_H3  + (size_t)NZ*NN*H3;
static const size_t OFF_WB  = OFF_H4  + (size_t)NZ*NN*OUTD;
static const size_t OFF_CC  = OFF_WB  + (size_t)NZ*PDIM;
static const size_t TOTAL_SCRATCH = OFF_CC + (size_t)BB*2*NN*OUTD;

__device__ float g_scratch[TOTAL_SCRATCH];
// adj as packed bf16x2 (k-pairs): [b2][512][256] uint32 (16B aligned for cp.async)
__device__ __align__(128) uint32_t g_adjb[(size_t)NZ * NN * (NN / 2)];
// packed bf16 (d∘Z) per layer: [z][pair p][n], max layer-1 size 128*256*128
__device__ __align__(128) uint32_t g_zb16[(size_t)NZ * (NN / 2) * H1];

// ---------------- bf16 helpers ------------------------------------------------
__device__ __forceinline__ uint32_t pack_bf16(float a, float b) {
    __nv_bfloat162 t = __floats2bfloat162_rn(a, b);
    return *reinterpret_cast<uint32_t*>(&t);
}
__device__ __forceinline__ void split_bf16(float v, float& hi, float& lo) {
    __nv_bfloat16 h = __float2bfloat16(v);
    hi = __bfloat162float(h);
    lo = v - hi;
}
__device__ __forceinline__ float bf16_get(uint32_t w, int comp) {
    __nv_bfloat162 t = *reinterpret_cast<__nv_bfloat162*>(&w);
    return comp ? __bfloat162float(t.y) : __bfloat162float(t.x);
}
// pair index p (0..15) -> permuted word offset within A row (plain kernel layout)
__device__ __forceinline__ int aperm(int p) {
    int q = p >> 2, j = p & 3;
    return (q >> 1) * 8 + (q & 1) + 2 * j;
}
__device__ __forceinline__ uint32_t smem_u32(const void* p) {
    uint32_t a;
    asm("{ .reg .u64 t; cvta.to.shared.u64 t, %1; cvt.u32.u64 %0, t; }" : "=r"(a) : "l"(p));
    return a;
}

__device__ __forceinline__ void mma_bf16(float c[4],
    uint32_t a0, uint32_t a1, uint32_t a2, uint32_t a3,
    uint32_t b0, uint32_t b1) {
    asm volatile(
        "mma.sync.aligned.m16n8k16.row.col.f32.bf16.bf16.f32 "
        "{%0,%1,%2,%3}, {%4,%5,%6,%7}, {%8,%9}, {%0,%1,%2,%3};"
        : "+f"(c[0]), "+f"(c[1]), "+f"(c[2]), "+f"(c[3])
        : "r"(a0), "r"(a1), "r"(a2), "r"(a3), "r"(b0), "r"(b1));
}

// ---------------- preprocess: rowsum (d) + adj -> packed bf16 -----------------
__global__ void prep_kernel(const float* __restrict__ adj,
                            float* __restrict__ dout,
                            uint32_t* __restrict__ adjb) {
    int gw   = (blockIdx.x * blockDim.x + threadIdx.x) >> 5;
    int lane = threadIdx.x & 31;
    int b2  = gw >> 9;
    int row = gw & 511;
    const float4* r4 = (const float4*)(adj + (size_t)b2 * NN * NN + (size_t)row * NN);
    uint2* w2 = (uint2*)(adjb + (size_t)b2 * NN * (NN / 2) + (size_t)row * (NN / 2));
    float ssum = 0.f;
    #pragma unroll
    for (int j = lane; j < NN / 4; j += 32) {
        float4 v = r4[j];
        ssum += (v.x + v.y) + (v.z + v.w);
        uint2 p;
        p.x = pack_bf16(v.x, v.y);
        p.y = pack_bf16(v.z, v.w);
        w2[j] = p;
    }
    #pragma unroll
    for (int o = 16; o; o >>= 1) ssum += __shfl_xor_sync(0xffffffffu, ssum, o);
    if (lane == 0) {
        int s = b2 & 1, b = b2 >> 1;
        dout[(size_t)(s * BB + b) * NN + row] = rsqrtf(ssum + 1.0f);
    }
}

// ---------------- pack layer-1 B: Zb[z][p][n] = bf16x2(d∘w1) ------------------
__global__ void pack1_kernel(const float* __restrict__ w0,
                             const float* __restrict__ w1,
                             const float* __restrict__ dbase,
                             uint32_t* __restrict__ Zb) {
    size_t idx = (size_t)blockIdx.x * 256 + threadIdx.x;   // NZ*256*H1 total
    int n = idx & (H1 - 1);
    int p = (idx >> 7) & 255;
    int z = (int)(idx >> 15);
    const float* w = (z >= BB) ? w1 : w0;
    const float* dz = dbase + (size_t)z * NN;
    float v0 = dz[2 * p]     * w[(size_t)(2 * p) * H1 + n];
    float v1 = dz[2 * p + 1] * w[(size_t)(2 * p + 1) * H1 + n];
    Zb[idx] = pack_bf16(v0, v1);
}

// ---------------- GCN layer: bf16 MMA, BK=64, all-cp.async --------------------
// blockIdx.z = z in [0,128): s=z>>6, b=z&63, adjb index b2=b*2+s
// B = packed bf16 (d∘Z) from g_zb16 [z][p][n].
// C = leaky?(d_i*(acc + packedZ_i) + bias)
template<int BM, int BN, int WGM, int WGN, bool ACT>
__global__ void __launch_bounds__(WGM*WGN*32, (WGM*WGN*32 == 256) ? 3 : 4)
gcn_bf16_kernel(const uint32_t* __restrict__ Adjb,
                const uint32_t* __restrict__ Zb16,
                const float* __restrict__ dbase,
                const float* __restrict__ bias0,
                const float* __restrict__ bias1,
                float* __restrict__ Cbase,
                int Ncols)
{
    constexpr int BK = 64;
    constexpr int KP = BK / 2;          // 32 pairs per tile
    constexpr int KKS = BK / 16;        // 4 k16 steps
    constexpr int WM = BM / WGM, WN = BN / WGN;
    constexpr int MT = WM / 16, NT = WN / 8;
    constexpr int NTHREADS = WGM * WGN * 32;
    constexpr int ASTR = KP + 4;        // 36 u32 per A row (bank-safe)
    constexpr int BNP = (BN == 64) ? 72 : ((BN == 32) ? 40 : 8);
    constexpr int A_CH = BM * (KP / 4) / NTHREADS;
    constexpr int B_TOT = KP * BN / 4;  // 16B chunks per B tile
    constexpr int NTILES = NN / BK;     // 8
    constexpr int A_WORDS = 2 * BM * ASTR;

    extern __shared__ uint32_t smg[];
    uint32_t* Bb = smg + A_WORDS;       // 2 bufs x KP x BNP

    const int z = blockIdx.z;
    const int s = z >> 6, b = z & 63;
    const int n0 = blockIdx.y * BN;
    const uint32_t* A  = Adjb + (size_t)(b * 2 + s) * NN * (NN / 2);
    const uint32_t* zb = Zb16 + (size_t)z * (NN / 2) * Ncols;
    const float* bias = s ? bias1 : bias0;
    const float* dz   = dbase + (size_t)z * NN;
    float* C          = Cbase + (size_t)z * NN * Ncols;

    const int m0 = blockIdx.x * BM;
    const int tid = threadIdx.x;
    const int w = tid >> 5, lane = tid & 31;
    const int g = lane >> 2, tig = lane & 3;
    const int wm = (w / WGN) * WM;
    const int wn = (w % WGN) * WN;

    float acc[MT][NT][4] = {};

    auto cpasync_tile = [&](int c, int buf) {
        #pragma unroll
        for (int i = 0; i < A_CH; i++) {
            int idx = tid + i * NTHREADS;
            int r = idx / (KP / 4), q = idx % (KP / 4);
            uint32_t dst = smem_u32(&smg[buf * BM * ASTR + r * ASTR + q * 4]);
            const uint32_t* src = &A[(size_t)(m0 + r) * (NN / 2) + c * KP + q * 4];
            asm volatile("cp.async.cg.shared.global [%0], [%1], 16;"
                         :: "r"(dst), "l"(src));
        }
        #pragma unroll
        for (int i = 0; i < (B_TOT + NTHREADS - 1) / NTHREADS; i++) {
            int e = tid + i * NTHREADS;
            if (B_TOT % NTHREADS == 0 || e < B_TOT) {
                int p = e / (BN / 4), n4 = (e % (BN / 4)) * 4;
                uint32_t dst = smem_u32(&Bb[buf * KP * BNP + p * BNP + n4]);
                const uint32_t* src = &zb[(size_t)(c * KP + p) * Ncols + n0 + n4];
                asm volatile("cp.async.cg.shared.global [%0], [%1], 16;"
                             :: "r"(dst), "l"(src));
            }
        }
        asm volatile("cp.async.commit_group;");
    };

    // prologue
    cpasync_tile(0, 0);
    asm volatile("cp.async.wait_group 0;");
    __syncthreads();

    for (int c = 0; c < NTILES; c++) {
        const int cur = c & 1, nxt = cur ^ 1;
        if (c + 1 < NTILES) cpasync_tile(c + 1, nxt);

        const uint32_t* Ac = &smg[cur * BM * ASTR];
        const uint32_t* Bc = &Bb[cur * KP * BNP];
        #pragma unroll
        for (int kk = 0; kk < KKS; kk++) {
            uint32_t a0[MT], a1[MT], a2[MT], a3[MT];
            uint32_t b0[NT], b1[NT];
            #pragma unroll
            for (int mt = 0; mt < MT; mt++) {
                int r0 = wm + mt * 16 + g;
                const uint32_t* ar0 = Ac + r0 * ASTR;
                const uint32_t* ar1 = ar0 + 8 * ASTR;
                a0[mt] = ar0[kk * 8 + tig];
                a2[mt] = ar0[kk * 8 + 4 + tig];
                a1[mt] = ar1[kk * 8 + tig];
                a3[mt] = ar1[kk * 8 + 4 + tig];
            }
            #pragma unroll
            for (int nt = 0; nt < NT; nt++) {
                int cb = wn + nt * 8 + g;
                b0[nt] = Bc[(kk * 8 + tig) * BNP + cb];
                b1[nt] = Bc[(kk * 8 + 4 + tig) * BNP + cb];
            }
            #pragma unroll
            for (int mt = 0; mt < MT; mt++)
                #pragma unroll
                for (int nt = 0; nt < NT; nt++)
                    mma_bf16(acc[mt][nt], a0[mt], a1[mt], a2[mt], a3[mt],
                             b0[nt], b1[nt]);
        }

        if (c + 1 < NTILES) asm volatile("cp.async.wait_group 0;");
        __syncthreads();
    }

    // epilogue: v = d_i * (acc + packedZ_i) + bias (+leaky)
    const int comp = g & 1;
    #pragma unroll
    for (int mt = 0; mt < MT; mt++) {
        int r0 = m0 + wm + mt * 16 + g;
        int r1 = r0 + 8;
        float d0 = dz[r0], d1 = dz[r1];
        #pragma unroll
        for (int nt = 0; nt < NT; nt++) {
            int c = n0 + wn + nt * 8 + tig * 2;
            uint2 w0 = *(const uint2*)&zb[(size_t)(r0 >> 1) * Ncols + c];
            uint2 w1v = *(const uint2*)&zb[(size_t)(r1 >> 1) * Ncols + c];
            float bc0 = bias[c], bc1 = bias[c + 1];
            float v00 = d0 * (acc[mt][nt][0] + bf16_get(w0.x, comp)) + bc0;
            float v01 = d0 * (acc[mt][nt][1] + bf16_get(w0.y, comp)) + bc1;
            float v10 = d1 * (acc[mt][nt][2] + bf16_get(w1v.x, comp)) + bc0;
            float v11 = d1 * (acc[mt][nt][3] + bf16_get(w1v.y, comp)) + bc1;
            if (ACT) {
                v00 = (v00 >= 0.f) ? v00 : 0.2f * v00;
                v01 = (v01 >= 0.f) ? v01 : 0.2f * v01;
                v10 = (v10 >= 0.f) ? v10 : 0.2f * v10;
                v11 = (v11 >= 0.f) ? v11 : 0.2f * v11;
            }
            *(float2*)&C[(size_t)r0 * Ncols + c] = make_float2(v00, v01);
            *(float2*)&C[(size_t)r1 * Ncols + c] = make_float2(v10, v11);
        }
    }
}

// gcn smem bytes
#define GCN_SMEM(BM, BN) ((2 * (BM) * 36 + 2 * 32 * (((BN) == 64) ? 72 : (((BN) == 32) ? 40 : 8))) * 4)

// ---------------- plain bf16 split GEMM -> packed bf16 (d∘C) ------------------
// A, W split bf16 hi+lo; 3 MMAs per k16 (hh, hl, lh).
// Output: ONLY packed bf16x2 words Zb[(s*64+b)*256 + pair][n] = (d*C paired rows).
template<int BM, int BN, int WGM, int WGN>
__global__ void __launch_bounds__(WGM*WGN*32, (WGM*WGN*32 == 256) ? 2 : 4)
plain_bf16_kernel(const float* __restrict__ Abase,
                  const float* __restrict__ B0,
                  const float* __restrict__ B1,
                  const float* __restrict__ dbase,
                  uint32_t* __restrict__ Zb,
                  int K, int Ncols, size_t sA)
{
    constexpr int BK = 32;
    constexpr int KP = BK / 2;
    constexpr int WM = BM / WGM, WN = BN / WGN;
    constexpr int MT = WM / 16, NT = WN / 8;
    constexpr int NTHREADS = WGM * WGN * 32;
    constexpr int ASTRIDE = 24;
    constexpr int BNP = (BN == 8) ? 20 : BN + 4;
    constexpr int A_TOT4 = BM * BK / 4;
    constexpr int A_LD4 = (A_TOT4 + NTHREADS - 1) / NTHREADS;
    constexpr int B_TOTP = KP * BN;
    constexpr int B_LDP = (B_TOTP + NTHREADS - 1) / NTHREADS;
    constexpr int SMW_MAIN = 2 * BM * ASTRIDE + 2 * 16 * BNP;
    constexpr int SMW_EPI  = BM * (BN + 1);
    constexpr int SMW = (SMW_MAIN > SMW_EPI) ? SMW_MAIN : SMW_EPI;

    __shared__ __align__(16) uint32_t psm[SMW];
    uint32_t (*Ah)[ASTRIDE] = reinterpret_cast<uint32_t(*)[ASTRIDE]>(psm);
    uint32_t (*Al)[ASTRIDE] = reinterpret_cast<uint32_t(*)[ASTRIDE]>(psm + BM * ASTRIDE);
    uint32_t (*Bh)[4][BNP][2] = reinterpret_cast<uint32_t(*)[4][BNP][2]>(psm + 2 * BM * ASTRIDE);
    uint32_t (*Bl)[4][BNP][2] = reinterpret_cast<uint32_t(*)[4][BNP][2]>(psm + 2 * BM * ASTRIDE + 16 * BNP);

    const int z = blockIdx.z;   // s
    const float* A = Abase + (size_t)z * sA;
    const float* B = z ? B1 : B0;
    const float* d_s = dbase + (size_t)z * BB * NN;
    const size_t zoff = (size_t)z * BB * (NN / 2);

    const int m0 = blockIdx.x * BM;
    const int tid = threadIdx.x;
    const int w = tid >> 5, lane = tid & 31;
    const int g = lane >> 2, tig = lane & 3;
    const int wm = (w / WGN) * WM;
    const int wn = (w % WGN) * WN;

    float acc[MT][NT][4] = {};
    float4 aF[A_LD4];
    float2 bF[B_LDP];

    #pragma unroll
    for (int i = 0; i < A_LD4; i++) {
        int idx = tid + i * NTHREADS;
        if (idx < A_TOT4) {
            int r = idx / (BK / 4), c4 = (idx % (BK / 4)) * 4;
            aF[i] = *(const float4*)&A[(size_t)(m0 + r) * K + c4];
        }
    }
    #pragma unroll
    for (int i = 0; i < B_LDP; i++) {
        int e = tid + i * NTHREADS;
        if (e < B_TOTP) {
            int p = e / BN, n = e % BN;
            bF[i].x = B[(size_t)(2 * p) * Ncols + n];
            bF[i].y = B[(size_t)(2 * p + 1) * Ncols + n];
        }
    }

    for (int k0 = 0; k0 < K; k0 += BK) {
        #pragma unroll
        for (int i = 0; i < A_LD4; i++) {
            int idx = tid + i * NTHREADS;
            if (idx < A_TOT4) {
                int r = idx / (BK / 4), c4 = (idx % (BK / 4)) * 4;
                int p0 = c4 >> 1;
                float hx, lx, hy, ly, hz, lz, hw, lw;
                split_bf16(aF[i].x, hx, lx); split_bf16(aF[i].y, hy, ly);
                split_bf16(aF[i].z, hz, lz); split_bf16(aF[i].w, hw, lw);
                int w0 = aperm(p0), w1 = aperm(p0 + 1);
                Ah[r][w0] = pack_bf16(hx, hy); Al[r][w0] = pack_bf16(lx, ly);
                Ah[r][w1] = pack_bf16(hz, hw); Al[r][w1] = pack_bf16(lz, lw);
            }
        }
        #pragma unroll
        for (int i = 0; i < B_LDP; i++) {
            int e = tid + i * NTHREADS;
            if (e < B_TOTP) {
                int p = e / BN, n = e % BN;
                float hx, lx, hy, ly;
                split_bf16(bF[i].x, hx, lx); split_bf16(bF[i].y, hy, ly);
                Bh[p >> 3][p & 3][n][(p >> 2) & 1] = pack_bf16(hx, hy);
                Bl[p >> 3][p & 3][n][(p >> 2) & 1] = pack_bf16(lx, ly);
            }
        }
        __syncthreads();

        if (k0 + BK < K) {
            #pragma unroll
            for (int i = 0; i < A_LD4; i++) {
                int idx = tid + i * NTHREADS;
                if (idx < A_TOT4) {
                    int r = idx / (BK / 4), c4 = (idx % (BK / 4)) * 4;
                    aF[i] = *(const float4*)&A[(size_t)(m0 + r) * K + (k0 + BK) + c4];
                }
            }
            #pragma unroll
            for (int i = 0; i < B_LDP; i++) {
                int e = tid + i * NTHREADS;
                if (e < B_TOTP) {
                    int p = e / BN, n = e % BN;
                    int k = k0 + BK + 2 * p;
                    bF[i].x = B[(size_t)k * Ncols + n];
                    bF[i].y = B[(size_t)(k + 1) * Ncols + n];
                }
            }
        }

        #pragma unroll
        for (int kk = 0; kk < 2; kk++) {
            uint32_t ah0[MT], ah1[MT], ah2[MT], ah3[MT];
            uint32_t al0[MT], al1[MT], al2[MT], al3[MT];
            uint32_t bh0[NT], bh1[NT], bl0[NT], bl1[NT];
            #pragma unroll
            for (int mt = 0; mt < MT; mt++) {
                int r0 = wm + mt * 16 + g;
                uint2 h0 = *(const uint2*)&Ah[r0][kk * 8 + 2 * tig];
                uint2 h1 = *(const uint2*)&Ah[r0 + 8][kk * 8 + 2 * tig];
                uint2 l0 = *(const uint2*)&Al[r0][kk * 8 + 2 * tig];
                uint2 l1 = *(const uint2*)&Al[r0 + 8][kk * 8 + 2 * tig];
                ah0[mt] = h0.x; ah2[mt] = h0.y;
                ah1[mt] = h1.x; ah3[mt] = h1.y;
                al0[mt] = l0.x; al2[mt] = l0.y;
                al1[mt] = l1.x; al3[mt] = l1.y;
            }
            #pragma unroll
            for (int nt = 0; nt < NT; nt++) {
                int cb = wn + nt * 8 + g;
                uint2 bh = *(const uint2*)&Bh[kk][tig][cb][0];
                uint2 bl = *(const uint2*)&Bl[kk][tig][cb][0];
                bh0[nt] = bh.x; bh1[nt] = bh.y;
                bl0[nt] = bl.x; bl1[nt] = bl.y;
            }
            #pragma unroll
            for (int mt = 0; mt < MT; mt++)
                #pragma unroll
                for (int nt = 0; nt < NT; nt++) {
                    mma_bf16(acc[mt][nt], ah0[mt], ah1[mt], ah2[mt], ah3[mt],
                             bh0[nt], bh1[nt]);
                    mma_bf16(acc[mt][nt], ah0[mt], ah1[mt], ah2[mt], ah3[mt],
                             bl0[nt], bl1[nt]);
                    mma_bf16(acc[mt][nt], al0[mt], al1[mt], al2[mt], al3[mt],
                             bh0[nt], bh1[nt]);
                }
        }
        __syncthreads();
    }

    // epilogue: route tile through smem, pair rows, scale by d, write packed bf16
    float* Ct = reinterpret_cast<float*>(psm);
    #pragma unroll
    for (int mt = 0; mt < MT; mt++) {
        int rr0 = wm + mt * 16 + g;
        #pragma unroll
        for (int nt = 0; nt < NT; nt++) {
            int n = wn + nt * 8 + tig * 2;
            Ct[rr0 * (BN + 1) + n]       = acc[mt][nt][0];
            Ct[rr0 * (BN + 1) + n + 1]   = acc[mt][nt][1];
            Ct[(rr0 + 8) * (BN + 1) + n]     = acc[mt][nt][2];
            Ct[(rr0 + 8) * (BN + 1) + n + 1] = acc[mt][nt][3];
        }
    }
    __syncthreads();
    for (int e = tid; e < BM / 2 * BN; e += NTHREADS) {
        int pr = e / BN, n = e % BN;
        float f0 = Ct[(2 * pr) * (BN + 1) + n];
        float f1 = Ct[(2 * pr + 1) * (BN + 1) + n];
        int gr = m0 + 2 * pr;
        Zb[(zoff + (gr >> 1)) * Ncols + n] = pack_bf16(d_s[gr] * f0, d_s[gr + 1] * f1);
    }
}

// ---------------- dynamic head params ---------------------------------------
__global__ void dcl_params_kernel(const int* __restrict__ task,
                                  const float* __restrict__ wc,
                                  const float* __restrict__ H3b,
                                  float* __restrict__ wb) {
    int z = blockIdx.x;
    int b = z & 63;
    const float* conv3 = H3b + (size_t)z * NN * H3;
    __shared__ float partial[256];
    __shared__ float xc[CDIM];
    int tid = threadIdx.x;
    int col = tid & 31, g = tid >> 5;
    float p = 0.f;
    for (int r = g; r < NN; r += 8) p += conv3[(size_t)r * H3 + col];
    partial[tid] = p;
    __syncthreads();
    if (tid < H3) {
        float sum = 0.f;
        #pragma unroll
        for (int gg = 0; gg < 8; gg++) sum += partial[gg * 32 + tid];
        xc[tid] = sum * (1.0f / (float)NN);
    }
    if (tid >= H3 && tid < CDIM) {
        xc[tid] = (task[b] == tid - H3) ? 1.f : 0.f;
    }
    __syncthreads();
    if (tid < PDIM) {
        float acc = 0.f;
        #pragma unroll
        for (int c = 0; c < CDIM; c++) acc += wc[tid * CDIM + c] * xc[c];
        wb[(size_t)z * PDIM + tid] = acc;
    }
}

// ---------------- cc kernel: logits + interleave scatter --------------------
__global__ void cc_kernel(const float* __restrict__ H4b,
                          const float* __restrict__ wb,
                          float* __restrict__ cc) {
    int z = blockIdx.x;
    int q = z >> 6, b = z & 63;
    __shared__ float flat[NN * OUTD];
    __shared__ float wm[64];
    __shared__ float bv[8];
    int tid = threadIdx.x;
    const float4* src4 = (const float4*)(H4b + (size_t)z * NN * OUTD);
    float4* dst4 = (float4*)flat;
    for (int i = tid; i < NN * OUTD / 4; i += 256) dst4[i] = src4[i];
    if (tid < 64) wm[tid] = wb[(size_t)z * PDIM + tid];
    if (tid < 8)  bv[tid] = wb[(size_t)z * PDIM + 64 + tid];
    __syncthreads();
    for (int f = tid; f < NN * OUTD; f += 256) {
        int r = f >> 9, c = f & 511;
        float v = bv[r];
        #pragma unroll
        for (int i = 0; i < 8; i++) v += wm[r * 8 + i] * flat[i * NN + c];
        int n = f >> 3, o = f & 7;
        int scc = n >> 8;
        int n2 = ((n & 255) << 1) | q;
        cc[(((size_t)(b * 2 + scc) * NN + n2) << 3) + o] = v;
    }
}

// ---------------- final: out = softplus(-(cc @ cc^T)) -----------------------
__global__ void final_kernel(const float* __restrict__ cc, float* __restrict__ out) {
    int zz = blockIdx.z;
    __shared__ float Msm[NN * OUTD];
    int tid = threadIdx.y * 16 + threadIdx.x;
    const float4* src = (const float4*)(cc + (size_t)zz * NN * OUTD);
    float4* dst = (float4*)Msm;
    for (int i = tid; i < NN * OUTD / 4; i += 256) dst[i] = src[i];
    __syncthreads();
    int i0 = blockIdx.y * 64 + threadIdx.y * 4;
    int j0 = blockIdx.x * 64 + threadIdx.x * 4;
    float ai[4][8], aj[4][8];
    #pragma unroll
    for (int m = 0; m < 4; m++)
        #pragma unroll
        for (int o = 0; o < 8; o++) ai[m][o] = Msm[(i0 + m) * 8 + o];
    #pragma unroll
    for (int n = 0; n < 4; n++)
        #pragma unroll
        for (int o = 0; o < 8; o++) aj[n][o] = Msm[(j0 + n) * 8 + o];
    float* ob = out + (size_t)zz * NN * NN;
    #pragma unroll
    for (int m = 0; m < 4; m++) {
        float r[4];
        #pragma unroll
        for (int n = 0; n < 4; n++) {
            float x = 0.f;
            #pragma unroll
            for (int o = 0; o < 8; o++) x += ai[m][o] * aj[n][o];
            r[n] = __logf(1.0f + __expf(-fabsf(x))) + fmaxf(-x, 0.f);
        }
        *(float4*)(ob + (size_t)(i0 + m) * NN + j0) = make_float4(r[0], r[1], r[2], r[3]);
    }
}

// ---------------- host orchestration ----------------------------------------
extern "C" void kernel_launch(void* const* d_in, const int* in_sizes, int n_in,
                              void* d_out, int out_size) {
    const float* adj  = (const float*)d_in[0];
    const int*   task = (const int*)d_in[1];
    const float* w[2][4];
    const float* bia[2][4];
    int idx = 2;
    for (int s = 0; s < 2; s++)
        for (int l = 0; l < 4; l++) {
            w[s][l]   = (const float*)d_in[idx++];
            bia[s][l] = (const float*)d_in[idx++];
        }
    const float* wc = (const float*)d_in[18];
    float* out = (float*)d_out;

    float* base = nullptr;
    cudaGetSymbolAddress((void**)&base, g_scratch);
    uint32_t* adjb = nullptr;
    cudaGetSymbolAddress((void**)&adjb, g_adjb);
    uint32_t* zb16 = nullptr;
    cudaGetSymbolAddress((void**)&zb16, g_zb16);
    float* p_d  = base + OFF_D;
    float* p_H1 = base + OFF_H1;
    float* p_H2 = base + OFF_H2;
    float* p_H3 = base + OFF_H3;
    float* p_H4 = base + OFF_H4;
    float* p_WB = base + OFF_WB;
    float* p_CC = base + OFF_CC;

    const size_t S1 = (size_t)BB * NN * H1;
    const size_t S2 = (size_t)BB * NN * H2;
    const size_t S3 = (size_t)BB * NN * H3;

    // dynamic smem opt-in for the 55KB gcn BN=64 config (idempotent)
    cudaFuncSetAttribute(
        (const void*)gcn_bf16_kernel<128, 64, 4, 2, true>,
        cudaFuncAttributeMaxDynamicSharedMemorySize, GCN_SMEM(128, 64));

    // 1) preprocess: degree factors + adj -> bf16
    prep_kernel<<<NZ * NN / 8, 256>>>(adj, p_d, adjb);

    // 2) layer 1: pack d∘w1 per z, then gcn
    pack1_kernel<<<NZ * (NN / 2) * H1 / 256, 256>>>(w[0][0], w[1][0], p_d, zb16);
    gcn_bf16_kernel<128, 64, 4, 2, true>
        <<<dim3(4, 2, NZ), 256, GCN_SMEM(128, 64)>>>(
            adjb, zb16, p_d, bia[0][0], bia[1][0], p_H1, H1);

    // 3) layer 2: Zb16 = packed d∘(H1 @ w2) ; H2 = gcn
    plain_bf16_kernel<128, 64, 4, 2>
        <<<dim3(BB * NN / 128, 1, 2), 256>>>(
            p_H1, w[0][1], w[1][1], p_d, zb16, H1, H2, S1);
    gcn_bf16_kernel<128, 64, 4, 2, true>
        <<<dim3(4, 1, NZ), 256, GCN_SMEM(128, 64)>>>(
            adjb, zb16, p_d, bia[0][1], bia[1][1], p_H2, H2);

    // 4) layer 3
    plain_bf16_kernel<128, 32, 4, 1>
        <<<dim3(BB * NN / 128, 1, 2), 128>>>(
            p_H2, w[0][2], w[1][2], p_d, zb16, H2, H3, S2);
    gcn_bf16_kernel<128, 32, 4, 1, true>
        <<<dim3(4, 1, NZ), 128, GCN_SMEM(128, 32)>>>(
            adjb, zb16, p_d, bia[0][2], bia[1][2], p_H3, H3);

    // 5) layer 4 (no act)
    plain_bf16_kernel<128, 8, 4, 1>
        <<<dim3(BB * NN / 128, 1, 2), 128>>>(
            p_H3, w[0][3], w[1][3], p_d, zb16, H3, OUTD, S3);
    gcn_bf16_kernel<128, 8, 4, 1, false>
        <<<dim3(4, 1, NZ), 128, GCN_SMEM(128, 8)>>>(
            adjb, zb16, p_d, bia[0][3], bia[1][3], p_H4, OUTD);

    // 6) dynamic head params (uses conv3 = H3)
    dcl_params_kernel<<<NZ, 256>>>(task, wc, p_H3, p_WB);

    // 7) logits + interleave into cc
    cc_kernel<<<NZ, 256>>>(p_H4, p_WB, p_CC);

    // 8) final gram + softplus
    final_kernel<<<dim3(8, 8, NZ), dim3(16, 16)>>>(p_CC, out);

    (void)in_sizes; (void)n_in; (void)out_size;
}

// round 15
// speedup vs baseline: 8.6545x; 1.0236x over previous
#include <cuda_runtime.h>
#include <cuda_bf16.h>
#include <math.h>
#include <stdint.h>

#define NN 512
#define BB 64
#define NZ 128            // B*2 branch instances
#define H1 128
#define H2 64
#define H3 32
#define OUTD 8
#define CLS 16
#define PDIM 72           // OUT*OUT + OUT
#define CDIM 48           // H3 + CLS

// ---------------- scratch (static device buffers, no allocs) ----------------
static const size_t OFF_D   = 0;
static const size_t OFF_H1  = OFF_D   + (size_t)NZ*NN;
static const size_t OFF_H2  = OFF_H1  + (size_t)NZ*NN*H1;
static const size_t OFF_H3  = OFF_H2  + (size_t)NZ*NN*H2;
static const size_t OFF_H4  = OFF_H3  + (size_t)NZ*NN*H3;
static const size_t OFF_WB  = OFF_H4  + (size_t)NZ*NN*OUTD;
static const size_t OFF_CC  = OFF_WB  + (size_t)NZ*PDIM;
static const size_t TOTAL_SCRATCH = OFF_CC + (size_t)BB*2*NN*OUTD;

__device__ float g_scratch[TOTAL_SCRATCH];
// adj as packed bf16x2 (k-pairs): [b2][512][256] uint32 (16B aligned for cp.async)
__device__ __align__(128) uint32_t g_adjb[(size_t)NZ * NN * (NN / 2)];
// packed bf16 (d∘Z) per layer: [z][pair p][n], max layer-1 size 128*256*128
__device__ __align__(128) uint32_t g_zb16[(size_t)NZ * (NN / 2) * H1];

// ---------------- bf16 helpers ------------------------------------------------
__device__ __forceinline__ uint32_t pack_bf16(float a, float b) {
    __nv_bfloat162 t = __floats2bfloat162_rn(a, b);
    return *reinterpret_cast<uint32_t*>(&t);
}
__device__ __forceinline__ float bf16_get(uint32_t w, int comp) {
    __nv_bfloat162 t = *reinterpret_cast<__nv_bfloat162*>(&w);
    return comp ? __bfloat162float(t.y) : __bfloat162float(t.x);
}
// pair index p (0..15) -> permuted word offset within A row (plain kernel layout)
__device__ __forceinline__ int aperm(int p) {
    int q = p >> 2, j = p & 3;
    return (q >> 1) * 8 + (q & 1) + 2 * j;
}
__device__ __forceinline__ uint32_t smem_u32(const void* p) {
    uint32_t a;
    asm("{ .reg .u64 t; cvta.to.shared.u64 t, %1; cvt.u32.u64 %0, t; }" : "=r"(a) : "l"(p));
    return a;
}

__device__ __forceinline__ void mma_bf16(float c[4],
    uint32_t a0, uint32_t a1, uint32_t a2, uint32_t a3,
    uint32_t b0, uint32_t b1) {
    asm volatile(
        "mma.sync.aligned.m16n8k16.row.col.f32.bf16.bf16.f32 "
        "{%0,%1,%2,%3}, {%4,%5,%6,%7}, {%8,%9}, {%0,%1,%2,%3};"
        : "+f"(c[0]), "+f"(c[1]), "+f"(c[2]), "+f"(c[3])
        : "r"(a0), "r"(a1), "r"(a2), "r"(a3), "r"(b0), "r"(b1));
}

// ---------------- preprocess: rowsum (d) + adj -> packed bf16 -----------------
__global__ void prep_kernel(const float* __restrict__ adj,
                            float* __restrict__ dout,
                            uint32_t* __restrict__ adjb) {
    int gw   = (blockIdx.x * blockDim.x + threadIdx.x) >> 5;
    int lane = threadIdx.x & 31;
    int b2  = gw >> 9;
    int row = gw & 511;
    const float4* r4 = (const float4*)(adj + (size_t)b2 * NN * NN + (size_t)row * NN);
    uint2* w2 = (uint2*)(adjb + (size_t)b2 * NN * (NN / 2) + (size_t)row * (NN / 2));
    float ssum = 0.f;
    #pragma unroll
    for (int j = lane; j < NN / 4; j += 32) {
        float4 v = r4[j];
        ssum += (v.x + v.y) + (v.z + v.w);
        uint2 p;
        p.x = pack_bf16(v.x, v.y);
        p.y = pack_bf16(v.z, v.w);
        w2[j] = p;
    }
    #pragma unroll
    for (int o = 16; o; o >>= 1) ssum += __shfl_xor_sync(0xffffffffu, ssum, o);
    if (lane == 0) {
        int s = b2 & 1, b = b2 >> 1;
        dout[(size_t)(s * BB + b) * NN + row] = rsqrtf(ssum + 1.0f);
    }
}

// ---------------- pack layer-1 B: Zb[z][p][n] = bf16x2(d∘w1) ------------------
__global__ void pack1_kernel(const float* __restrict__ w0,
                             const float* __restrict__ w1,
                             const float* __restrict__ dbase,
                             uint32_t* __restrict__ Zb) {
    size_t idx = (size_t)blockIdx.x * 256 + threadIdx.x;   // NZ*256*H1 total
    int n = idx & (H1 - 1);
    int p = (idx >> 7) & 255;
    int z = (int)(idx >> 15);
    const float* w = (z >= BB) ? w1 : w0;
    const float* dz = dbase + (size_t)z * NN;
    float v0 = dz[2 * p]     * w[(size_t)(2 * p) * H1 + n];
    float v1 = dz[2 * p + 1] * w[(size_t)(2 * p + 1) * H1 + n];
    Zb[idx] = pack_bf16(v0, v1);
}

// ---------------- GCN layer: bf16 MMA, BK=64, all-cp.async --------------------
// blockIdx.z = z in [0,128): s=z>>6, b=z&63, adjb index b2=b*2+s
// B = packed bf16 (d∘Z) from g_zb16 [z][p][n].
// C = leaky?(d_i*(acc + packedZ_i) + bias)
template<int BM, int BN, int WGM, int WGN, bool ACT>
__global__ void __launch_bounds__(WGM*WGN*32, (WGM*WGN*32 == 256) ? 3 : 4)
gcn_bf16_kernel(const uint32_t* __restrict__ Adjb,
                const uint32_t* __restrict__ Zb16,
                const float* __restrict__ dbase,
                const float* __restrict__ bias0,
                const float* __restrict__ bias1,
                float* __restrict__ Cbase,
                int Ncols)
{
    constexpr int BK = 64;
    constexpr int KP = BK / 2;          // 32 pairs per tile
    constexpr int KKS = BK / 16;        // 4 k16 steps
    constexpr int WM = BM / WGM, WN = BN / WGN;
    constexpr int MT = WM / 16, NT = WN / 8;
    constexpr int NTHREADS = WGM * WGN * 32;
    constexpr int ASTR = KP + 4;        // 36 u32 per A row (bank-safe)
    constexpr int BNP = (BN == 64) ? 72 : ((BN == 32) ? 40 : 8);
    constexpr int A_CH = BM * (KP / 4) / NTHREADS;
    constexpr int B_TOT = KP * BN / 4;  // 16B chunks per B tile
    constexpr int NTILES = NN / BK;     // 8
    constexpr int A_WORDS = 2 * BM * ASTR;

    extern __shared__ uint32_t smg[];
    uint32_t* Bb = smg + A_WORDS;       // 2 bufs x KP x BNP

    const int z = blockIdx.z;
    const int s = z >> 6, b = z & 63;
    const int n0 = blockIdx.y * BN;
    const uint32_t* A  = Adjb + (size_t)(b * 2 + s) * NN * (NN / 2);
    const uint32_t* zb = Zb16 + (size_t)z * (NN / 2) * Ncols;
    const float* bias = s ? bias1 : bias0;
    const float* dz   = dbase + (size_t)z * NN;
    float* C          = Cbase + (size_t)z * NN * Ncols;

    const int m0 = blockIdx.x * BM;
    const int tid = threadIdx.x;
    const int w = tid >> 5, lane = tid & 31;
    const int g = lane >> 2, tig = lane & 3;
    const int wm = (w / WGN) * WM;
    const int wn = (w % WGN) * WN;

    float acc[MT][NT][4] = {};

    auto cpasync_tile = [&](int c, int buf) {
        #pragma unroll
        for (int i = 0; i < A_CH; i++) {
            int idx = tid + i * NTHREADS;
            int r = idx / (KP / 4), q = idx % (KP / 4);
            uint32_t dst = smem_u32(&smg[buf * BM * ASTR + r * ASTR + q * 4]);
            const uint32_t* src = &A[(size_t)(m0 + r) * (NN / 2) + c * KP + q * 4];
            asm volatile("cp.async.cg.shared.global [%0], [%1], 16;"
                         :: "r"(dst), "l"(src));
        }
        #pragma unroll
        for (int i = 0; i < (B_TOT + NTHREADS - 1) / NTHREADS; i++) {
            int e = tid + i * NTHREADS;
            if (B_TOT % NTHREADS == 0 || e < B_TOT) {
                int p = e / (BN / 4), n4 = (e % (BN / 4)) * 4;
                uint32_t dst = smem_u32(&Bb[buf * KP * BNP + p * BNP + n4]);
                const uint32_t* src = &zb[(size_t)(c * KP + p) * Ncols + n0 + n4];
                asm volatile("cp.async.cg.shared.global [%0], [%1], 16;"
                             :: "r"(dst), "l"(src));
            }
        }
        asm volatile("cp.async.commit_group;");
    };

    // prologue
    cpasync_tile(0, 0);
    asm volatile("cp.async.wait_group 0;");
    __syncthreads();

    for (int c = 0; c < NTILES; c++) {
        const int cur = c & 1, nxt = cur ^ 1;
        if (c + 1 < NTILES) cpasync_tile(c + 1, nxt);

        const uint32_t* Ac = &smg[cur * BM * ASTR];
        const uint32_t* Bc = &Bb[cur * KP * BNP];
        #pragma unroll
        for (int kk = 0; kk < KKS; kk++) {
            uint32_t a0[MT], a1[MT], a2[MT], a3[MT];
            uint32_t b0[NT], b1[NT];
            #pragma unroll
            for (int mt = 0; mt < MT; mt++) {
                int r0 = wm + mt * 16 + g;
                const uint32_t* ar0 = Ac + r0 * ASTR;
                const uint32_t* ar1 = ar0 + 8 * ASTR;
                a0[mt] = ar0[kk * 8 + tig];
                a2[mt] = ar0[kk * 8 + 4 + tig];
                a1[mt] = ar1[kk * 8 + tig];
                a3[mt] = ar1[kk * 8 + 4 + tig];
            }
            #pragma unroll
            for (int nt = 0; nt < NT; nt++) {
                int cb = wn + nt * 8 + g;
                b0[nt] = Bc[(kk * 8 + tig) * BNP + cb];
                b1[nt] = Bc[(kk * 8 + 4 + tig) * BNP + cb];
            }
            #pragma unroll
            for (int mt = 0; mt < MT; mt++)
                #pragma unroll
                for (int nt = 0; nt < NT; nt++)
                    mma_bf16(acc[mt][nt], a0[mt], a1[mt], a2[mt], a3[mt],
                             b0[nt], b1[nt]);
        }

        if (c + 1 < NTILES) asm volatile("cp.async.wait_group 0;");
        __syncthreads();
    }

    // epilogue: v = d_i * (acc + packedZ_i) + bias (+leaky)
    const int comp = g & 1;
    #pragma unroll
    for (int mt = 0; mt < MT; mt++) {
        int r0 = m0 + wm + mt * 16 + g;
        int r1 = r0 + 8;
        float d0 = dz[r0], d1 = dz[r1];
        #pragma unroll
        for (int nt = 0; nt < NT; nt++) {
            int c = n0 + wn + nt * 8 + tig * 2;
            uint2 w0 = *(const uint2*)&zb[(size_t)(r0 >> 1) * Ncols + c];
            uint2 w1v = *(const uint2*)&zb[(size_t)(r1 >> 1) * Ncols + c];
            float bc0 = bias[c], bc1 = bias[c + 1];
            float v00 = d0 * (acc[mt][nt][0] + bf16_get(w0.x, comp)) + bc0;
            float v01 = d0 * (acc[mt][nt][1] + bf16_get(w0.y, comp)) + bc1;
            float v10 = d1 * (acc[mt][nt][2] + bf16_get(w1v.x, comp)) + bc0;
            float v11 = d1 * (acc[mt][nt][3] + bf16_get(w1v.y, comp)) + bc1;
            if (ACT) {
                v00 = (v00 >= 0.f) ? v00 : 0.2f * v00;
                v01 = (v01 >= 0.f) ? v01 : 0.2f * v01;
                v10 = (v10 >= 0.f) ? v10 : 0.2f * v10;
                v11 = (v11 >= 0.f) ? v11 : 0.2f * v11;
            }
            *(float2*)&C[(size_t)r0 * Ncols + c] = make_float2(v00, v01);
            *(float2*)&C[(size_t)r1 * Ncols + c] = make_float2(v10, v11);
        }
    }
}

// gcn smem bytes
#define GCN_SMEM(BM, BN) ((2 * (BM) * 36 + 2 * 32 * (((BN) == 64) ? 72 : (((BN) == 32) ? 40 : 8))) * 4)

// ---------------- plain bf16 GEMM (single hh MMA) -> packed bf16 (d∘C) --------
// A, W rounded to single bf16; Z output noise ~ the bf16 pack rounding it
// already suffers downstream (measured-justified).
// Output: ONLY packed bf16x2 words Zb[(s*64+b)*256 + pair][n].
template<int BM, int BN, int WGM, int WGN>
__global__ void __launch_bounds__(WGM*WGN*32, (WGM*WGN*32 == 256) ? 3 : 5)
plain_bf16_kernel(const float* __restrict__ Abase,
                  const float* __restrict__ B0,
                  const float* __restrict__ B1,
                  const float* __restrict__ dbase,
                  uint32_t* __restrict__ Zb,
                  int K, int Ncols, size_t sA)
{
    constexpr int BK = 32;
    constexpr int KP = BK / 2;
    constexpr int WM = BM / WGM, WN = BN / WGN;
    constexpr int MT = WM / 16, NT = WN / 8;
    constexpr int NTHREADS = WGM * WGN * 32;
    constexpr int ASTRIDE = 24;
    constexpr int BNP = (BN == 8) ? 20 : BN + 4;
    constexpr int A_TOT4 = BM * BK / 4;
    constexpr int A_LD4 = (A_TOT4 + NTHREADS - 1) / NTHREADS;
    constexpr int B_TOTP = KP * BN;
    constexpr int B_LDP = (B_TOTP + NTHREADS - 1) / NTHREADS;
    constexpr int SMW_MAIN = BM * ASTRIDE + 16 * BNP * 2;
    constexpr int SMW_EPI  = BM * (BN + 1);
    constexpr int SMW = (SMW_MAIN > SMW_EPI) ? SMW_MAIN : SMW_EPI;

    __shared__ __align__(16) uint32_t psm[SMW];
    uint32_t (*Ah)[ASTRIDE] = reinterpret_cast<uint32_t(*)[ASTRIDE]>(psm);
    uint32_t (*Bh)[4][BNP][2] = reinterpret_cast<uint32_t(*)[4][BNP][2]>(psm + BM * ASTRIDE);

    const int z = blockIdx.z;   // s
    const float* A = Abase + (size_t)z * sA;
    const float* B = z ? B1 : B0;
    const float* d_s = dbase + (size_t)z * BB * NN;
    const size_t zoff = (size_t)z * BB * (NN / 2);

    const int m0 = blockIdx.x * BM;
    const int tid = threadIdx.x;
    const int w = tid >> 5, lane = tid & 31;
    const int g = lane >> 2, tig = lane & 3;
    const int wm = (w / WGN) * WM;
    const int wn = (w % WGN) * WN;

    float acc[MT][NT][4] = {};
    float4 aF[A_LD4];
    float2 bF[B_LDP];

    #pragma unroll
    for (int i = 0; i < A_LD4; i++) {
        int idx = tid + i * NTHREADS;
        if (idx < A_TOT4) {
            int r = idx / (BK / 4), c4 = (idx % (BK / 4)) * 4;
            aF[i] = *(const float4*)&A[(size_t)(m0 + r) * K + c4];
        }
    }
    #pragma unroll
    for (int i = 0; i < B_LDP; i++) {
        int e = tid + i * NTHREADS;
        if (e < B_TOTP) {
            int p = e / BN, n = e % BN;
            bF[i].x = B[(size_t)(2 * p) * Ncols + n];
            bF[i].y = B[(size_t)(2 * p + 1) * Ncols + n];
        }
    }

    for (int k0 = 0; k0 < K; k0 += BK) {
        #pragma unroll
        for (int i = 0; i < A_LD4; i++) {
            int idx = tid + i * NTHREADS;
            if (idx < A_TOT4) {
                int r = idx / (BK / 4), c4 = (idx % (BK / 4)) * 4;
                int p0 = c4 >> 1;
                Ah[r][aperm(p0)]     = pack_bf16(aF[i].x, aF[i].y);
                Ah[r][aperm(p0 + 1)] = pack_bf16(aF[i].z, aF[i].w);
            }
        }
        #pragma unroll
        for (int i = 0; i < B_LDP; i++) {
            int e = tid + i * NTHREADS;
            if (e < B_TOTP) {
                int p = e / BN, n = e % BN;
                Bh[p >> 3][p & 3][n][(p >> 2) & 1] = pack_bf16(bF[i].x, bF[i].y);
            }
        }
        __syncthreads();

        if (k0 + BK < K) {
            #pragma unroll
            for (int i = 0; i < A_LD4; i++) {
                int idx = tid + i * NTHREADS;
                if (idx < A_TOT4) {
                    int r = idx / (BK / 4), c4 = (idx % (BK / 4)) * 4;
                    aF[i] = *(const float4*)&A[(size_t)(m0 + r) * K + (k0 + BK) + c4];
                }
            }
            #pragma unroll
            for (int i = 0; i < B_LDP; i++) {
                int e = tid + i * NTHREADS;
                if (e < B_TOTP) {
                    int p = e / BN, n = e % BN;
                    int k = k0 + BK + 2 * p;
                    bF[i].x = B[(size_t)k * Ncols + n];
                    bF[i].y = B[(size_t)(k + 1) * Ncols + n];
                }
            }
        }

        #pragma unroll
        for (int kk = 0; kk < 2; kk++) {
            uint32_t a0[MT], a1[MT], a2[MT], a3[MT];
            uint32_t b0[NT], b1[NT];
            #pragma unroll
            for (int mt = 0; mt < MT; mt++) {
                int r0 = wm + mt * 16 + g;
                uint2 h0 = *(const uint2*)&Ah[r0][kk * 8 + 2 * tig];
                uint2 h1 = *(const uint2*)&Ah[r0 + 8][kk * 8 + 2 * tig];
                a0[mt] = h0.x; a2[mt] = h0.y;
                a1[mt] = h1.x; a3[mt] = h1.y;
            }
            #pragma unroll
            for (int nt = 0; nt < NT; nt++) {
                int cb = wn + nt * 8 + g;
                uint2 bb = *(const uint2*)&Bh[kk][tig][cb][0];
                b0[nt] = bb.x; b1[nt] = bb.y;
            }
            #pragma unroll
            for (int mt = 0; mt < MT; mt++)
                #pragma unroll
                for (int nt = 0; nt < NT; nt++)
                    mma_bf16(acc[mt][nt], a0[mt], a1[mt], a2[mt], a3[mt],
                             b0[nt], b1[nt]);
        }
        __syncthreads();
    }

    // epilogue: route tile through smem, pair rows, scale by d, write packed bf16
    float* Ct = reinterpret_cast<float*>(psm);
    #pragma unroll
    for (int mt = 0; mt < MT; mt++) {
        int rr0 = wm + mt * 16 + g;
        #pragma unroll
        for (int nt = 0; nt < NT; nt++) {
            int n = wn + nt * 8 + tig * 2;
            Ct[rr0 * (BN + 1) + n]       = acc[mt][nt][0];
            Ct[rr0 * (BN + 1) + n + 1]   = acc[mt][nt][1];
            Ct[(rr0 + 8) * (BN + 1) + n]     = acc[mt][nt][2];
            Ct[(rr0 + 8) * (BN + 1) + n + 1] = acc[mt][nt][3];
        }
    }
    __syncthreads();
    for (int e = tid; e < BM / 2 * BN; e += NTHREADS) {
        int pr = e / BN, n = e % BN;
        float f0 = Ct[(2 * pr) * (BN + 1) + n];
        float f1 = Ct[(2 * pr + 1) * (BN + 1) + n];
        int gr = m0 + 2 * pr;
        Zb[(zoff + (gr >> 1)) * Ncols + n] = pack_bf16(d_s[gr] * f0, d_s[gr + 1] * f1);
    }
}

// ---------------- dynamic head params ---------------------------------------
__global__ void dcl_params_kernel(const int* __restrict__ task,
                                  const float* __restrict__ wc,
                                  const float* __restrict__ H3b,
                                  float* __restrict__ wb) {
    int z = blockIdx.x;
    int b = z & 63;
    const float* conv3 = H3b + (size_t)z * NN * H3;
    __shared__ float partial[256];
    __shared__ float xc[CDIM];
    int tid = threadIdx.x;
    int col = tid & 31, g = tid >> 5;
    float p = 0.f;
    for (int r = g; r < NN; r += 8) p += conv3[(size_t)r * H3 + col];
    partial[tid] = p;
    __syncthreads();
    if (tid < H3) {
        float sum = 0.f;
        #pragma unroll
        for (int gg = 0; gg < 8; gg++) sum += partial[gg * 32 + tid];
        xc[tid] = sum * (1.0f / (float)NN);
    }
    if (tid >= H3 && tid < CDIM) {
        xc[tid] = (task[b] == tid - H3) ? 1.f : 0.f;
    }
    __syncthreads();
    if (tid < PDIM) {
        float acc = 0.f;
        #pragma unroll
        for (int c = 0; c < CDIM; c++) acc += wc[tid * CDIM + c] * xc[c];
        wb[(size_t)z * PDIM + tid] = acc;
    }
}

// ---------------- cc kernel: logits + interleave scatter --------------------
__global__ void cc_kernel(const float* __restrict__ H4b,
                          const float* __restrict__ wb,
                          float* __restrict__ cc) {
    int z = blockIdx.x;
    int q = z >> 6, b = z & 63;
    __shared__ float flat[NN * OUTD];
    __shared__ float wm[64];
    __shared__ float bv[8];
    int tid = threadIdx.x;
    const float4* src4 = (const float4*)(H4b + (size_t)z * NN * OUTD);
    float4* dst4 = (float4*)flat;
    for (int i = tid; i < NN * OUTD / 4; i += 256) dst4[i] = src4[i];
    if (tid < 64) wm[tid] = wb[(size_t)z * PDIM + tid];
    if (tid < 8)  bv[tid] = wb[(size_t)z * PDIM + 64 + tid];
    __syncthreads();
    for (int f = tid; f < NN * OUTD; f += 256) {
        int r = f >> 9, c = f & 511;
        float v = bv[r];
        #pragma unroll
        for (int i = 0; i < 8; i++) v += wm[r * 8 + i] * flat[i * NN + c];
        int n = f >> 3, o = f & 7;
        int scc = n >> 8;
        int n2 = ((n & 255) << 1) | q;
        cc[(((size_t)(b * 2 + scc) * NN + n2) << 3) + o] = v;
    }
}

// ---------------- final: out = softplus(-(cc @ cc^T)) -----------------------
__global__ void final_kernel(const float* __restrict__ cc, float* __restrict__ out) {
    int zz = blockIdx.z;
    __shared__ float Msm[NN * OUTD];
    int tid = threadIdx.y * 16 + threadIdx.x;
    const float4* src = (const float4*)(cc + (size_t)zz * NN * OUTD);
    float4* dst = (float4*)Msm;
    for (int i = tid; i < NN * OUTD / 4; i += 256) dst[i] = src[i];
    __syncthreads();
    int i0 = blockIdx.y * 64 + threadIdx.y * 4;
    int j0 = blockIdx.x * 64 + threadIdx.x * 4;
    float ai[4][8], aj[4][8];
    #pragma unroll
    for (int m = 0; m < 4; m++)
        #pragma unroll
        for (int o = 0; o < 8; o++) ai[m][o] = Msm[(i0 + m) * 8 + o];
    #pragma unroll
    for (int n = 0; n < 4; n++)
        #pragma unroll
        for (int o = 0; o < 8; o++) aj[n][o] = Msm[(j0 + n) * 8 + o];
    float* ob = out + (size_t)zz * NN * NN;
    #pragma unroll
    for (int m = 0; m < 4; m++) {
        float r[4];
        #pragma unroll
        for (int n = 0; n < 4; n++) {
            float x = 0.f;
            #pragma unroll
            for (int o = 0; o < 8; o++) x += ai[m][o] * aj[n][o];
            r[n] = __logf(1.0f + __expf(-fabsf(x))) + fmaxf(-x, 0.f);
        }
        *(float4*)(ob + (size_t)(i0 + m) * NN + j0) = make_float4(r[0], r[1], r[2], r[3]);
    }
}

// ---------------- host orchestration ----------------------------------------
extern "C" void kernel_launch(void* const* d_in, const int* in_sizes, int n_in,
                              void* d_out, int out_size) {
    const float* adj  = (const float*)d_in[0];
    const int*   task = (const int*)d_in[1];
    const float* w[2][4];
    const float* bia[2][4];
    int idx = 2;
    for (int s = 0; s < 2; s++)
        for (int l = 0; l < 4; l++) {
            w[s][l]   = (const float*)d_in[idx++];
            bia[s][l] = (const float*)d_in[idx++];
        }
    const float* wc = (const float*)d_in[18];
    float* out = (float*)d_out;

    float* base = nullptr;
    cudaGetSymbolAddress((void**)&base, g_scratch);
    uint32_t* adjb = nullptr;
    cudaGetSymbolAddress((void**)&adjb, g_adjb);
    uint32_t* zb16 = nullptr;
    cudaGetSymbolAddress((void**)&zb16, g_zb16);
    float* p_d  = base + OFF_D;
    float* p_H1 = base + OFF_H1;
    float* p_H2 = base + OFF_H2;
    float* p_H3 = base + OFF_H3;
    float* p_H4 = base + OFF_H4;
    float* p_WB = base + OFF_WB;
    float* p_CC = base + OFF_CC;

    const size_t S1 = (size_t)BB * NN * H1;
    const size_t S2 = (size_t)BB * NN * H2;
    const size_t S3 = (size_t)BB * NN * H3;

    // dynamic smem opt-in for the 55KB gcn BN=64 config (idempotent)
    cudaFuncSetAttribute(
        (const void*)gcn_bf16_kernel<128, 64, 4, 2, true>,
        cudaFuncAttributeMaxDynamicSharedMemorySize, GCN_SMEM(128, 64));

    // 1) preprocess: degree factors + adj -> bf16
    prep_kernel<<<NZ * NN / 8, 256>>>(adj, p_d, adjb);

    // 2) layer 1: pack d∘w1 per z, then gcn
    pack1_kernel<<<NZ * (NN / 2) * H1 / 256, 256>>>(w[0][0], w[1][0], p_d, zb16);
    gcn_bf16_kernel<128, 64, 4, 2, true>
        <<<dim3(4, 2, NZ), 256, GCN_SMEM(128, 64)>>>(
            adjb, zb16, p_d, bia[0][0], bia[1][0], p_H1, H1);

    // 3) layer 2: Zb16 = packed d∘(H1 @ w2) ; H2 = gcn
    plain_bf16_kernel<128, 64, 4, 2>
        <<<dim3(BB * NN / 128, 1, 2), 256>>>(
            p_H1, w[0][1], w[1][1], p_d, zb16, H1, H2, S1);
    gcn_bf16_kernel<128, 64, 4, 2, true>
        <<<dim3(4, 1, NZ), 256, GCN_SMEM(128, 64)>>>(
            adjb, zb16, p_d, bia[0][1], bia[1][1], p_H2, H2);

    // 4) layer 3
    plain_bf16_kernel<128, 32, 4, 1>
        <<<dim3(BB * NN / 128, 1, 2), 128>>>(
            p_H2, w[0][2], w[1][2], p_d, zb16, H2, H3, S2);
    gcn_bf16_kernel<128, 32, 4, 1, true>
        <<<dim3(4, 1, NZ), 128, GCN_SMEM(128, 32)>>>(
            adjb, zb16, p_d, bia[0][2], bia[1][2], p_H3, H3);

    // 5) layer 4 (no act)
    plain_bf16_kernel<128, 8, 4, 1>
        <<<dim3(BB * NN / 128, 1, 2), 128>>>(
            p_H3, w[0][3], w[1][3], p_d, zb16, H3, OUTD, S3);
    gcn_bf16_kernel<128, 8, 4, 1, false>
        <<<dim3(4, 1, NZ), 128, GCN_SMEM(128, 8)>>>(
            adjb, zb16, p_d, bia[0][3], bia[1][3], p_H4, OUTD);

    // 6) dynamic head params (uses conv3 = H3)
    dcl_params_kernel<<<NZ, 256>>>(task, wc, p_H3, p_WB);

    // 7) logits + interleave into cc
    cc_kernel<<<NZ, 256>>>(p_H4, p_WB, p_CC);

    // 8) final gram + softplus
    final_kernel<<<dim3(8, 8, NZ), dim3(16, 16)>>>(p_CC, out);

    (void)in_sizes; (void)n_in; (void)out_size;
}

// round 16
// speedup vs baseline: 8.8638x; 1.0242x over previous
#include <cuda_runtime.h>
#include <cuda_bf16.h>
#include <math.h>
#include <stdint.h>

#define NN 512
#define BB 64
#define NZ 128            // B*2 branch instances
#define H1 128
#define H2 64
#define H3 32
#define OUTD 8
#define CLS 16
#define PDIM 72           // OUT*OUT + OUT
#define CDIM 48           // H3 + CLS

// ---------------- scratch (static device buffers, no allocs) ----------------
static const size_t OFF_D   = 0;
static const size_t OFF_H4  = OFF_D  + (size_t)NZ*NN;
static const size_t OFF_WB  = OFF_H4 + (size_t)NZ*NN*OUTD;
static const size_t OFF_CC  = OFF_WB + (size_t)NZ*PDIM;
static const size_t TOTAL_SCRATCH = OFF_CC + (size_t)BB*2*NN*OUTD;

__device__ float g_scratch[TOTAL_SCRATCH];
// adj as packed bf16x2 (k-pairs): [b2][512][256] uint32
__device__ __align__(128) uint32_t g_adjb[(size_t)NZ * NN * (NN / 2)];
// packed bf16 (d∘Z): [z][k-pair][n], max 128*256*128
__device__ __align__(128) uint32_t g_zb16[(size_t)NZ * (NN / 2) * H1];
// packed bf16 H (k-pairs along columns): [z][row][colpair], max 128*512*64
__device__ __align__(128) uint32_t g_hb16[(size_t)NZ * NN * (H1 / 2)];

// ---------------- bf16 helpers ------------------------------------------------
__device__ __forceinline__ uint32_t pack_bf16(float a, float b) {
    __nv_bfloat162 t = __floats2bfloat162_rn(a, b);
    return *reinterpret_cast<uint32_t*>(&t);
}
__device__ __forceinline__ float bf16_get(uint32_t w, int comp) {
    __nv_bfloat162 t = *reinterpret_cast<__nv_bfloat162*>(&w);
    return comp ? __bfloat162float(t.y) : __bfloat162float(t.x);
}
__device__ __forceinline__ uint32_t smem_u32(const void* p) {
    uint32_t a;
    asm("{ .reg .u64 t; cvta.to.shared.u64 t, %1; cvt.u32.u64 %0, t; }" : "=r"(a) : "l"(p));
    return a;
}

__device__ __forceinline__ void mma_bf16(float c[4],
    uint32_t a0, uint32_t a1, uint32_t a2, uint32_t a3,
    uint32_t b0, uint32_t b1) {
    asm volatile(
        "mma.sync.aligned.m16n8k16.row.col.f32.bf16.bf16.f32 "
        "{%0,%1,%2,%3}, {%4,%5,%6,%7}, {%8,%9}, {%0,%1,%2,%3};"
        : "+f"(c[0]), "+f"(c[1]), "+f"(c[2]), "+f"(c[3])
        : "r"(a0), "r"(a1), "r"(a2), "r"(a3), "r"(b0), "r"(b1));
}

// ---------------- preprocess: rowsum (d) + adj -> packed bf16 -----------------
__global__ void prep_kernel(const float* __restrict__ adj,
                            float* __restrict__ dout,
                            uint32_t* __restrict__ adjb) {
    int gw   = (blockIdx.x * blockDim.x + threadIdx.x) >> 5;
    int lane = threadIdx.x & 31;
    int b2  = gw >> 9;
    int row = gw & 511;
    const float4* r4 = (const float4*)(adj + (size_t)b2 * NN * NN + (size_t)row * NN);
    uint2* w2 = (uint2*)(adjb + (size_t)b2 * NN * (NN / 2) + (size_t)row * (NN / 2));
    float ssum = 0.f;
    #pragma unroll
    for (int j = lane; j < NN / 4; j += 32) {
        float4 v = r4[j];
        ssum += (v.x + v.y) + (v.z + v.w);
        uint2 p;
        p.x = pack_bf16(v.x, v.y);
        p.y = pack_bf16(v.z, v.w);
        w2[j] = p;
    }
    #pragma unroll
    for (int o = 16; o; o >>= 1) ssum += __shfl_xor_sync(0xffffffffu, ssum, o);
    if (lane == 0) {
        int s = b2 & 1, b = b2 >> 1;
        dout[(size_t)(s * BB + b) * NN + row] = rsqrtf(ssum + 1.0f);
    }
}

// ---------------- pack layer-1 B: Zb[z][p][n] = bf16x2(d∘w1) ------------------
__global__ void pack1_kernel(const float* __restrict__ w0,
                             const float* __restrict__ w1,
                             const float* __restrict__ dbase,
                             uint32_t* __restrict__ Zb) {
    size_t idx = (size_t)blockIdx.x * 256 + threadIdx.x;
    int n = idx & (H1 - 1);
    int p = (idx >> 7) & 255;
    int z = (int)(idx >> 15);
    const float* w = (z >= BB) ? w1 : w0;
    const float* dz = dbase + (size_t)z * NN;
    float v0 = dz[2 * p]     * w[(size_t)(2 * p) * H1 + n];
    float v1 = dz[2 * p + 1] * w[(size_t)(2 * p + 1) * H1 + n];
    Zb[idx] = pack_bf16(v0, v1);
}

// ---------------- GCN layer: bf16 MMA, BK=64, all-cp.async --------------------
// OUTBF=1: write H packed bf16 (k-pairs along columns) into Hout16
// OUTBF=0: write H fp32 into Cbase
template<int BM, int BN, int WGM, int WGN, bool ACT, int OUTBF>
__global__ void __launch_bounds__(WGM*WGN*32, (WGM*WGN*32 == 256) ? 3 : 4)
gcn_bf16_kernel(const uint32_t* __restrict__ Adjb,
                const uint32_t* __restrict__ Zb16,
                const float* __restrict__ dbase,
                const float* __restrict__ bias0,
                const float* __restrict__ bias1,
                float* __restrict__ Cbase,
                uint32_t* __restrict__ Hout16,
                int Ncols)
{
    constexpr int BK = 64;
    constexpr int KP = BK / 2;
    constexpr int KKS = BK / 16;
    constexpr int WM = BM / WGM, WN = BN / WGN;
    constexpr int MT = WM / 16, NT = WN / 8;
    constexpr int NTHREADS = WGM * WGN * 32;
    constexpr int ASTR = KP + 4;
    constexpr int BNP = (BN == 64) ? 72 : ((BN == 32) ? 40 : 8);
    constexpr int A_CH = BM * (KP / 4) / NTHREADS;
    constexpr int B_TOT = KP * BN / 4;
    constexpr int NTILES = NN / BK;
    constexpr int A_WORDS = 2 * BM * ASTR;

    extern __shared__ uint32_t smg[];
    uint32_t* Bb = smg + A_WORDS;

    const int z = blockIdx.z;
    const int s = z >> 6, b = z & 63;
    const int n0 = blockIdx.y * BN;
    const uint32_t* A  = Adjb + (size_t)(b * 2 + s) * NN * (NN / 2);
    const uint32_t* zb = Zb16 + (size_t)z * (NN / 2) * Ncols;
    const float* bias = s ? bias1 : bias0;
    const float* dz   = dbase + (size_t)z * NN;

    const int m0 = blockIdx.x * BM;
    const int tid = threadIdx.x;
    const int w = tid >> 5, lane = tid & 31;
    const int g = lane >> 2, tig = lane & 3;
    const int wm = (w / WGN) * WM;
    const int wn = (w % WGN) * WN;

    float acc[MT][NT][4] = {};

    auto cpasync_tile = [&](int c, int buf) {
        #pragma unroll
        for (int i = 0; i < A_CH; i++) {
            int idx = tid + i * NTHREADS;
            int r = idx / (KP / 4), q = idx % (KP / 4);
            uint32_t dst = smem_u32(&smg[buf * BM * ASTR + r * ASTR + q * 4]);
            const uint32_t* src = &A[(size_t)(m0 + r) * (NN / 2) + c * KP + q * 4];
            asm volatile("cp.async.cg.shared.global [%0], [%1], 16;"
                         :: "r"(dst), "l"(src));
        }
        #pragma unroll
        for (int i = 0; i < (B_TOT + NTHREADS - 1) / NTHREADS; i++) {
            int e = tid + i * NTHREADS;
            if (B_TOT % NTHREADS == 0 || e < B_TOT) {
                int p = e / (BN / 4), n4 = (e % (BN / 4)) * 4;
                uint32_t dst = smem_u32(&Bb[buf * KP * BNP + p * BNP + n4]);
                const uint32_t* src = &zb[(size_t)(c * KP + p) * Ncols + n0 + n4];
                asm volatile("cp.async.cg.shared.global [%0], [%1], 16;"
                             :: "r"(dst), "l"(src));
            }
        }
        asm volatile("cp.async.commit_group;");
    };

    cpasync_tile(0, 0);
    asm volatile("cp.async.wait_group 0;");
    __syncthreads();

    for (int c = 0; c < NTILES; c++) {
        const int cur = c & 1, nxt = cur ^ 1;
        if (c + 1 < NTILES) cpasync_tile(c + 1, nxt);

        const uint32_t* Ac = &smg[cur * BM * ASTR];
        const uint32_t* Bc = &Bb[cur * KP * BNP];
        #pragma unroll
        for (int kk = 0; kk < KKS; kk++) {
            uint32_t a0[MT], a1[MT], a2[MT], a3[MT];
            uint32_t b0[NT], b1[NT];
            #pragma unroll
            for (int mt = 0; mt < MT; mt++) {
                int r0 = wm + mt * 16 + g;
                const uint32_t* ar0 = Ac + r0 * ASTR;
                const uint32_t* ar1 = ar0 + 8 * ASTR;
                a0[mt] = ar0[kk * 8 + tig];
                a2[mt] = ar0[kk * 8 + 4 + tig];
                a1[mt] = ar1[kk * 8 + tig];
                a3[mt] = ar1[kk * 8 + 4 + tig];
            }
            #pragma unroll
            for (int nt = 0; nt < NT; nt++) {
                int cb = wn + nt * 8 + g;
                b0[nt] = Bc[(kk * 8 + tig) * BNP + cb];
                b1[nt] = Bc[(kk * 8 + 4 + tig) * BNP + cb];
            }
            #pragma unroll
            for (int mt = 0; mt < MT; mt++)
                #pragma unroll
                for (int nt = 0; nt < NT; nt++)
                    mma_bf16(acc[mt][nt], a0[mt], a1[mt], a2[mt], a3[mt],
                             b0[nt], b1[nt]);
        }

        if (c + 1 < NTILES) asm volatile("cp.async.wait_group 0;");
        __syncthreads();
    }

    // epilogue: v = d_i * (acc + packedZ_i) + bias (+leaky)
    const int comp = g & 1;
    const int NW = Ncols >> 1;
    #pragma unroll
    for (int mt = 0; mt < MT; mt++) {
        int r0 = m0 + wm + mt * 16 + g;
        int r1 = r0 + 8;
        float d0 = dz[r0], d1 = dz[r1];
        #pragma unroll
        for (int nt = 0; nt < NT; nt++) {
            int c = n0 + wn + nt * 8 + tig * 2;
            uint2 w0 = *(const uint2*)&zb[(size_t)(r0 >> 1) * Ncols + c];
            uint2 w1v = *(const uint2*)&zb[(size_t)(r1 >> 1) * Ncols + c];
            float bc0 = bias[c], bc1 = bias[c + 1];
            float v00 = d0 * (acc[mt][nt][0] + bf16_get(w0.x, comp)) + bc0;
            float v01 = d0 * (acc[mt][nt][1] + bf16_get(w0.y, comp)) + bc1;
            float v10 = d1 * (acc[mt][nt][2] + bf16_get(w1v.x, comp)) + bc0;
            float v11 = d1 * (acc[mt][nt][3] + bf16_get(w1v.y, comp)) + bc1;
            if (ACT) {
                v00 = (v00 >= 0.f) ? v00 : 0.2f * v00;
                v01 = (v01 >= 0.f) ? v01 : 0.2f * v01;
                v10 = (v10 >= 0.f) ? v10 : 0.2f * v10;
                v11 = (v11 >= 0.f) ? v11 : 0.2f * v11;
            }
            if (OUTBF) {
                Hout16[(size_t)z * NN * NW + (size_t)r0 * NW + (c >> 1)] = pack_bf16(v00, v01);
                Hout16[(size_t)z * NN * NW + (size_t)r1 * NW + (c >> 1)] = pack_bf16(v10, v11);
            } else {
                float* C = Cbase + (size_t)z * NN * Ncols;
                *(float2*)&C[(size_t)r0 * Ncols + c] = make_float2(v00, v01);
                *(float2*)&C[(size_t)r1 * Ncols + c] = make_float2(v10, v11);
            }
        }
    }
}

#define GCN_SMEM(BM, BN) ((2 * (BM) * 36 + 2 * 32 * (((BN) == 64) ? 72 : (((BN) == 32) ? 40 : 8))) * 4)

// ---------------- plain resident GEMM: zb16 = packed d∘(Hb16 @ W) -------------
// Entire K resident: A (bf16 k-pairs, cp.async) + W (fp32 -> bf16 pack, once).
// No k-loop, single barrier. BM = 128 rows per CTA.
template<int K, int BN, int WGM, int WGN>
__global__ void __launch_bounds__(WGM*WGN*32, 2)
plain_res_kernel(const uint32_t* __restrict__ Hb,
                 const float* __restrict__ W0,
                 const float* __restrict__ W1,
                 const float* __restrict__ dbase,
                 uint32_t* __restrict__ Zb)
{
    constexpr int BM = 128;
    constexpr int KW = K / 2;
    constexpr int KKS = K / 16;
    constexpr int ASTR = KW + 4;
    constexpr int BNP = (BN == 64) ? 72 : ((BN == 32) ? 40 : 8);
    constexpr int WM = BM / WGM, WN = BN / WGN;
    constexpr int MT = WM / 16, NT = WN / 8;
    constexpr int NTHREADS = WGM * WGN * 32;
    constexpr int A_CH = BM * (KW / 4) / NTHREADS;
    constexpr int B_TOTP = KW * BN;
    constexpr int SMW_MAIN = BM * ASTR + KW * BNP;
    constexpr int SMW_EPI  = BM * (BN + 1);
    constexpr int SMW = (SMW_MAIN > SMW_EPI) ? SMW_MAIN : SMW_EPI;

    extern __shared__ uint32_t psm[];
    uint32_t* As = psm;
    uint32_t* Bh = psm + BM * ASTR;

    const int z = blockIdx.z;   // s
    const uint32_t* A = Hb + (size_t)z * BB * NN * KW;
    const float* W = z ? W1 : W0;
    const float* d_s = dbase + (size_t)z * BB * NN;
    const size_t zoff = (size_t)z * BB * (NN / 2);

    const int m0 = blockIdx.x * BM;
    const int tid = threadIdx.x;
    const int w = tid >> 5, lane = tid & 31;
    const int g = lane >> 2, tig = lane & 3;
    const int wm = (w / WGN) * WM;
    const int wn = (w % WGN) * WN;

    // A: entire 128 x KW words via cp.async
    #pragma unroll
    for (int i = 0; i < A_CH; i++) {
        int idx = tid + i * NTHREADS;
        int r = idx / (KW / 4), q = idx % (KW / 4);
        uint32_t dst = smem_u32(&As[r * ASTR + q * 4]);
        const uint32_t* src = &A[(size_t)(m0 + r) * KW + q * 4];
        asm volatile("cp.async.cg.shared.global [%0], [%1], 16;"
                     :: "r"(dst), "l"(src));
    }
    asm volatile("cp.async.commit_group;");
    // W: fp32 -> packed bf16 in smem (once)
    #pragma unroll
    for (int i = 0; i < (B_TOTP + NTHREADS - 1) / NTHREADS; i++) {
        int e = tid + i * NTHREADS;
        if (B_TOTP % NTHREADS == 0 || e < B_TOTP) {
            int p = e / BN, n = e % BN;
            float f0 = W[(size_t)(2 * p) * BN + n];
            float f1 = W[(size_t)(2 * p + 1) * BN + n];
            Bh[p * BNP + n] = pack_bf16(f0, f1);
        }
    }
    asm volatile("cp.async.wait_group 0;");
    __syncthreads();

    float acc[MT][NT][4] = {};
    #pragma unroll
    for (int kk = 0; kk < KKS; kk++) {
        uint32_t a0[MT], a1[MT], a2[MT], a3[MT];
        uint32_t b0[NT], b1[NT];
        #pragma unroll
        for (int mt = 0; mt < MT; mt++) {
            int r0 = wm + mt * 16 + g;
            const uint32_t* ar0 = As + r0 * ASTR;
            const uint32_t* ar1 = ar0 + 8 * ASTR;
            a0[mt] = ar0[kk * 8 + tig];
            a2[mt] = ar0[kk * 8 + 4 + tig];
            a1[mt] = ar1[kk * 8 + tig];
            a3[mt] = ar1[kk * 8 + 4 + tig];
        }
        #pragma unroll
        for (int nt = 0; nt < NT; nt++) {
            int cb = wn + nt * 8 + g;
            b0[nt] = Bh[(kk * 8 + tig) * BNP + cb];
            b1[nt] = Bh[(kk * 8 + 4 + tig) * BNP + cb];
        }
        #pragma unroll
        for (int mt = 0; mt < MT; mt++)
            #pragma unroll
            for (int nt = 0; nt < NT; nt++)
                mma_bf16(acc[mt][nt], a0[mt], a1[mt], a2[mt], a3[mt],
                         b0[nt], b1[nt]);
    }
    __syncthreads();

    // epilogue: route tile through smem, pair rows, scale by d, write packed bf16
    float* Ct = reinterpret_cast<float*>(psm);
    #pragma unroll
    for (int mt = 0; mt < MT; mt++) {
        int rr0 = wm + mt * 16 + g;
        #pragma unroll
        for (int nt = 0; nt < NT; nt++) {
            int n = wn + nt * 8 + tig * 2;
            Ct[rr0 * (BN + 1) + n]       = acc[mt][nt][0];
            Ct[rr0 * (BN + 1) + n + 1]   = acc[mt][nt][1];
            Ct[(rr0 + 8) * (BN + 1) + n]     = acc[mt][nt][2];
            Ct[(rr0 + 8) * (BN + 1) + n + 1] = acc[mt][nt][3];
        }
    }
    __syncthreads();
    for (int e = tid; e < BM / 2 * BN; e += NTHREADS) {
        int pr = e / BN, n = e % BN;
        float f0 = Ct[(2 * pr) * (BN + 1) + n];
        float f1 = Ct[(2 * pr + 1) * (BN + 1) + n];
        int gr = m0 + 2 * pr;
        Zb[(zoff + (gr >> 1)) * BN + n] = pack_bf16(d_s[gr] * f0, d_s[gr + 1] * f1);
    }
}

#define PLAIN_SMW(K, BN) \
    (((128 * ((K)/2 + 4) + ((K)/2) * (((BN)==64)?72:(((BN)==32)?40:8))) > (128 * ((BN)+1))) ? \
     (128 * ((K)/2 + 4) + ((K)/2) * (((BN)==64)?72:(((BN)==32)?40:8))) : (128 * ((BN)+1)))
#define PLAIN_SMEM(K, BN) (PLAIN_SMW(K, BN) * 4)

// ---------------- dynamic head params (conv3 = Hb16, stride 16 words) ---------
__global__ void dcl_params_kernel(const int* __restrict__ task,
                                  const float* __restrict__ wc,
                                  const uint32_t* __restrict__ H3b,
                                  float* __restrict__ wb) {
    int z = blockIdx.x;
    int b = z & 63;
    const uint32_t* conv3 = H3b + (size_t)z * NN * (H3 / 2);
    __shared__ float partial[256];
    __shared__ float xc[CDIM];
    int tid = threadIdx.x;
    int col = tid & 31, g = tid >> 5;
    int wofs = col >> 1, comp = col & 1;
    float p = 0.f;
    for (int r = g; r < NN; r += 8)
        p += bf16_get(conv3[(size_t)r * (H3 / 2) + wofs], comp);
    partial[tid] = p;
    __syncthreads();
    if (tid < H3) {
        float sum = 0.f;
        #pragma unroll
        for (int gg = 0; gg < 8; gg++) sum += partial[gg * 32 + tid];
        xc[tid] = sum * (1.0f / (float)NN);
    }
    if (tid >= H3 && tid < CDIM) {
        xc[tid] = (task[b] == tid - H3) ? 1.f : 0.f;
    }
    __syncthreads();
    if (tid < PDIM) {
        float acc = 0.f;
        #pragma unroll
        for (int c = 0; c < CDIM; c++) acc += wc[tid * CDIM + c] * xc[c];
        wb[(size_t)z * PDIM + tid] = acc;
    }
}

// ---------------- cc kernel: logits + interleave scatter --------------------
__global__ void cc_kernel(const float* __restrict__ H4b,
                          const float* __restrict__ wb,
                          float* __restrict__ cc) {
    int z = blockIdx.x;
    int q = z >> 6, b = z & 63;
    __shared__ float flat[NN * OUTD];
    __shared__ float wm[64];
    __shared__ float bv[8];
    int tid = threadIdx.x;
    const float4* src4 = (const float4*)(H4b + (size_t)z * NN * OUTD);
    float4* dst4 = (float4*)flat;
    for (int i = tid; i < NN * OUTD / 4; i += 256) dst4[i] = src4[i];
    if (tid < 64) wm[tid] = wb[(size_t)z * PDIM + tid];
    if (tid < 8)  bv[tid] = wb[(size_t)z * PDIM + 64 + tid];
    __syncthreads();
    for (int f = tid; f < NN * OUTD; f += 256) {
        int r = f >> 9, c = f & 511;
        float v = bv[r];
        #pragma unroll
        for (int i = 0; i < 8; i++) v += wm[r * 8 + i] * flat[i * NN + c];
        int n = f >> 3, o = f & 7;
        int scc = n >> 8;
        int n2 = ((n & 255) << 1) | q;
        cc[(((size_t)(b * 2 + scc) * NN + n2) << 3) + o] = v;
    }
}

// ---------------- final: out = softplus(-(cc @ cc^T)) -----------------------
__global__ void final_kernel(const float* __restrict__ cc, float* __restrict__ out) {
    int zz = blockIdx.z;
    __shared__ float Msm[NN * OUTD];
    int tid = threadIdx.y * 16 + threadIdx.x;
    const float4* src = (const float4*)(cc + (size_t)zz * NN * OUTD);
    float4* dst = (float4*)Msm;
    for (int i = tid; i < NN * OUTD / 4; i += 256) dst[i] = src[i];
    __syncthreads();
    int i0 = blockIdx.y * 64 + threadIdx.y * 4;
    int j0 = blockIdx.x * 64 + threadIdx.x * 4;
    float ai[4][8], aj[4][8];
    #pragma unroll
    for (int m = 0; m < 4; m++)
        #pragma unroll
        for (int o = 0; o < 8; o++) ai[m][o] = Msm[(i0 + m) * 8 + o];
    #pragma unroll
    for (int n = 0; n < 4; n++)
        #pragma unroll
        for (int o = 0; o < 8; o++) aj[n][o] = Msm[(j0 + n) * 8 + o];
    float* ob = out + (size_t)zz * NN * NN;
    #pragma unroll
    for (int m = 0; m < 4; m++) {
        float r[4];
        #pragma unroll
        for (int n = 0; n < 4; n++) {
            float x = 0.f;
            #pragma unroll
            for (int o = 0; o < 8; o++) x += ai[m][o] * aj[n][o];
            r[n] = __logf(1.0f + __expf(-fabsf(x))) + fmaxf(-x, 0.f);
        }
        *(float4*)(ob + (size_t)(i0 + m) * NN + j0) = make_float4(r[0], r[1], r[2], r[3]);
    }
}

// ---------------- host orchestration ----------------------------------------
extern "C" void kernel_launch(void* const* d_in, const int* in_sizes, int n_in,
                              void* d_out, int out_size) {
    const float* adj  = (const float*)d_in[0];
    const int*   task = (const int*)d_in[1];
    const float* w[2][4];
    const float* bia[2][4];
    int idx = 2;
    for (int s = 0; s < 2; s++)
        for (int l = 0; l < 4; l++) {
            w[s][l]   = (const float*)d_in[idx++];
            bia[s][l] = (const float*)d_in[idx++];
        }
    const float* wc = (const float*)d_in[18];
    float* out = (float*)d_out;

    float* base = nullptr;
    cudaGetSymbolAddress((void**)&base, g_scratch);
    uint32_t* adjb = nullptr;
    cudaGetSymbolAddress((void**)&adjb, g_adjb);
    uint32_t* zb16 = nullptr;
    cudaGetSymbolAddress((void**)&zb16, g_zb16);
    uint32_t* hb16 = nullptr;
    cudaGetSymbolAddress((void**)&hb16, g_hb16);
    float* p_d  = base + OFF_D;
    float* p_H4 = base + OFF_H4;
    float* p_WB = base + OFF_WB;
    float* p_CC = base + OFF_CC;

    // dynamic smem opt-ins (>48KB; idempotent)
    cudaFuncSetAttribute(
        (const void*)gcn_bf16_kernel<128, 64, 4, 2, true, 1>,
        cudaFuncAttributeMaxDynamicSharedMemorySize, GCN_SMEM(128, 64));
    cudaFuncSetAttribute(
        (const void*)plain_res_kernel<128, 64, 4, 2>,
        cudaFuncAttributeMaxDynamicSharedMemorySize, PLAIN_SMEM(128, 64));

    // 1) preprocess: degree factors + adj -> bf16
    prep_kernel<<<NZ * NN / 8, 256>>>(adj, p_d, adjb);

    // 2) layer 1: pack d∘w1, gcn -> Hb16 (H1, 64 w/row)
    pack1_kernel<<<NZ * (NN / 2) * H1 / 256, 256>>>(w[0][0], w[1][0], p_d, zb16);
    gcn_bf16_kernel<128, 64, 4, 2, true, 1>
        <<<dim3(4, 2, NZ), 256, GCN_SMEM(128, 64)>>>(
            adjb, zb16, p_d, bia[0][0], bia[1][0], nullptr, hb16, H1);

    // 3) layer 2: zb16 = packed d∘(H1b @ w2) ; gcn -> Hb16 (H2, 32 w/row)
    plain_res_kernel<128, 64, 4, 2>
        <<<dim3(BB * NN / 128, 1, 2), 256, PLAIN_SMEM(128, 64)>>>(
            hb16, w[0][1], w[1][1], p_d, zb16);
    gcn_bf16_kernel<128, 64, 4, 2, true, 1>
        <<<dim3(4, 1, NZ), 256, GCN_SMEM(128, 64)>>>(
            adjb, zb16, p_d, bia[0][1], bia[1][1], nullptr, hb16, H2);

    // 4) layer 3 -> Hb16 (H3, 16 w/row)
    plain_res_kernel<64, 32, 4, 1>
        <<<dim3(BB * NN / 128, 1, 2), 128, PLAIN_SMEM(64, 32)>>>(
            hb16, w[0][2], w[1][2], p_d, zb16);
    gcn_bf16_kernel<128, 32, 4, 1, true, 1>
        <<<dim3(4, 1, NZ), 128, GCN_SMEM(128, 32)>>>(
            adjb, zb16, p_d, bia[0][2], bia[1][2], nullptr, hb16, H3);

    // 5) layer 4 (no act) -> H4 fp32
    plain_res_kernel<32, 8, 4, 1>
        <<<dim3(BB * NN / 128, 1, 2), 128, PLAIN_SMEM(32, 8)>>>(
            hb16, w[0][3], w[1][3], p_d, zb16);
    gcn_bf16_kernel<128, 8, 4, 1, false, 0>
        <<<dim3(4, 1, NZ), 128, GCN_SMEM(128, 8)>>>(
            adjb, zb16, p_d, bia[0][3], bia[1][3], p_H4, nullptr, OUTD);

    // 6) dynamic head params (conv3 = Hb16)
    dcl_params_kernel<<<NZ, 256>>>(task, wc, hb16, p_WB);

    // 7) logits + interleave into cc
    cc_kernel<<<NZ, 256>>>(p_H4, p_WB, p_CC);

    // 8) final gram + softplus
    final_kernel<<<dim3(8, 8, NZ), dim3(16, 16)>>>(p_CC, out);

    (void)in_sizes; (void)n_in; (void)out_size;
}

// round 17
// speedup vs baseline: 9.0126x; 1.0168x over previous
#include <cuda_runtime.h>
#include <cuda_bf16.h>
#include <math.h>
#include <stdint.h>

#define NN 512
#define BB 64
#define NZ 128            // B*2 branch instances
#define H1 128
#define H2 64
#define H3 32
#define OUTD 8
#define CLS 16
#define PDIM 72           // OUT*OUT + OUT
#define CDIM 48           // H3 + CLS

// ---------------- scratch (static device buffers, no allocs) ----------------
static const size_t OFF_D   = 0;
static const size_t OFF_H4  = OFF_D  + (size_t)NZ*NN;
static const size_t OFF_WB  = OFF_H4 + (size_t)NZ*NN*OUTD;
static const size_t OFF_CC  = OFF_WB + (size_t)NZ*PDIM;
static const size_t TOTAL_SCRATCH = OFF_CC + (size_t)BB*2*NN*OUTD;

__device__ float g_scratch[TOTAL_SCRATCH];
// adj as packed bf16x2 (k-pairs): [b2][512][256] uint32
__device__ __align__(128) uint32_t g_adjb[(size_t)NZ * NN * (NN / 2)];
// packed bf16 (d∘Z): [z][k-pair][n], max 128*256*128
__device__ __align__(128) uint32_t g_zb16[(size_t)NZ * (NN / 2) * H1];
// packed bf16 H (k-pairs along columns): [z][row][colpair], max 128*512*64
__device__ __align__(128) uint32_t g_hb16[(size_t)NZ * NN * (H1 / 2)];

// ---------------- bf16 helpers ------------------------------------------------
__device__ __forceinline__ uint32_t pack_bf16(float a, float b) {
    __nv_bfloat162 t = __floats2bfloat162_rn(a, b);
    return *reinterpret_cast<uint32_t*>(&t);
}
__device__ __forceinline__ float bf16_get(uint32_t w, int comp) {
    __nv_bfloat162 t = *reinterpret_cast<__nv_bfloat162*>(&w);
    return comp ? __bfloat162float(t.y) : __bfloat162float(t.x);
}
__device__ __forceinline__ uint32_t smem_u32(const void* p) {
    uint32_t a;
    asm("{ .reg .u64 t; cvta.to.shared.u64 t, %1; cvt.u32.u64 %0, t; }" : "=r"(a) : "l"(p));
    return a;
}

__device__ __forceinline__ void mma_bf16(float c[4],
    uint32_t a0, uint32_t a1, uint32_t a2, uint32_t a3,
    uint32_t b0, uint32_t b1) {
    asm volatile(
        "mma.sync.aligned.m16n8k16.row.col.f32.bf16.bf16.f32 "
        "{%0,%1,%2,%3}, {%4,%5,%6,%7}, {%8,%9}, {%0,%1,%2,%3};"
        : "+f"(c[0]), "+f"(c[1]), "+f"(c[2]), "+f"(c[3])
        : "r"(a0), "r"(a1), "r"(a2), "r"(a3), "r"(b0), "r"(b1));
}

// ---------------- preprocess: rowsum (d) + adj -> packed bf16 -----------------
__global__ void prep_kernel(const float* __restrict__ adj,
                            float* __restrict__ dout,
                            uint32_t* __restrict__ adjb) {
    int gw   = (blockIdx.x * blockDim.x + threadIdx.x) >> 5;
    int lane = threadIdx.x & 31;
    int b2  = gw >> 9;
    int row = gw & 511;
    const float4* r4 = (const float4*)(adj + (size_t)b2 * NN * NN + (size_t)row * NN);
    uint2* w2 = (uint2*)(adjb + (size_t)b2 * NN * (NN / 2) + (size_t)row * (NN / 2));
    float ssum = 0.f;
    #pragma unroll
    for (int j = lane; j < NN / 4; j += 32) {
        float4 v = r4[j];
        ssum += (v.x + v.y) + (v.z + v.w);
        uint2 p;
        p.x = pack_bf16(v.x, v.y);
        p.y = pack_bf16(v.z, v.w);
        w2[j] = p;
    }
    #pragma unroll
    for (int o = 16; o; o >>= 1) ssum += __shfl_xor_sync(0xffffffffu, ssum, o);
    if (lane == 0) {
        int s = b2 & 1, b = b2 >> 1;
        dout[(size_t)(s * BB + b) * NN + row] = rsqrtf(ssum + 1.0f);
    }
}

// ---------------- pack layer-1 B: Zb[z][p][n] = bf16x2(d∘w1) ------------------
__global__ void pack1_kernel(const float* __restrict__ w0,
                             const float* __restrict__ w1,
                             const float* __restrict__ dbase,
                             uint32_t* __restrict__ Zb) {
    size_t idx = (size_t)blockIdx.x * 256 + threadIdx.x;
    int n = idx & (H1 - 1);
    int p = (idx >> 7) & 255;
    int z = (int)(idx >> 15);
    const float* w = (z >= BB) ? w1 : w0;
    const float* dz = dbase + (size_t)z * NN;
    float v0 = dz[2 * p]     * w[(size_t)(2 * p) * H1 + n];
    float v1 = dz[2 * p + 1] * w[(size_t)(2 * p + 1) * H1 + n];
    Zb[idx] = pack_bf16(v0, v1);
}

#define BNP_OF(BN) (((BN) == 128) ? 136 : (((BN) == 64) ? 72 : (((BN) == 32) ? 40 : 8)))

// ---------------- GCN layer: bf16 MMA, BK=64, all-cp.async --------------------
// OUTBF=1: write H packed bf16 (k-pairs along columns) into Hout16
// OUTBF=0: write H fp32 into Cbase
template<int BM, int BN, int WGM, int WGN, bool ACT, int OUTBF>
__global__ void __launch_bounds__(WGM*WGN*32,
    (BN == 128) ? 2 : ((WGM*WGN*32 == 256) ? 3 : 4))
gcn_bf16_kernel(const uint32_t* __restrict__ Adjb,
                const uint32_t* __restrict__ Zb16,
                const float* __restrict__ dbase,
                const float* __restrict__ bias0,
                const float* __restrict__ bias1,
                float* __restrict__ Cbase,
                uint32_t* __restrict__ Hout16,
                int Ncols)
{
    constexpr int BK = 64;
    constexpr int KP = BK / 2;
    constexpr int KKS = BK / 16;
    constexpr int WM = BM / WGM, WN = BN / WGN;
    constexpr int MT = WM / 16, NT = WN / 8;
    constexpr int NTHREADS = WGM * WGN * 32;
    constexpr int ASTR = KP + 4;
    constexpr int BNP = BNP_OF(BN);
    constexpr int A_CH = BM * (KP / 4) / NTHREADS;
    constexpr int B_TOT = KP * BN / 4;
    constexpr int NTILES = NN / BK;
    constexpr int A_WORDS = 2 * BM * ASTR;

    extern __shared__ uint32_t smg[];
    uint32_t* Bb = smg + A_WORDS;

    const int z = blockIdx.z;
    const int s = z >> 6, b = z & 63;
    const int n0 = blockIdx.y * BN;
    const uint32_t* A  = Adjb + (size_t)(b * 2 + s) * NN * (NN / 2);
    const uint32_t* zb = Zb16 + (size_t)z * (NN / 2) * Ncols;
    const float* bias = s ? bias1 : bias0;
    const float* dz   = dbase + (size_t)z * NN;

    const int m0 = blockIdx.x * BM;
    const int tid = threadIdx.x;
    const int w = tid >> 5, lane = tid & 31;
    const int g = lane >> 2, tig = lane & 3;
    const int wm = (w / WGN) * WM;
    const int wn = (w % WGN) * WN;

    float acc[MT][NT][4] = {};

    auto cpasync_tile = [&](int c, int buf) {
        #pragma unroll
        for (int i = 0; i < A_CH; i++) {
            int idx = tid + i * NTHREADS;
            int r = idx / (KP / 4), q = idx % (KP / 4);
            uint32_t dst = smem_u32(&smg[buf * BM * ASTR + r * ASTR + q * 4]);
            const uint32_t* src = &A[(size_t)(m0 + r) * (NN / 2) + c * KP + q * 4];
            asm volatile("cp.async.cg.shared.global [%0], [%1], 16;"
                         :: "r"(dst), "l"(src));
        }
        #pragma unroll
        for (int i = 0; i < (B_TOT + NTHREADS - 1) / NTHREADS; i++) {
            int e = tid + i * NTHREADS;
            if (B_TOT % NTHREADS == 0 || e < B_TOT) {
                int p = e / (BN / 4), n4 = (e % (BN / 4)) * 4;
                uint32_t dst = smem_u32(&Bb[buf * KP * BNP + p * BNP + n4]);
                const uint32_t* src = &zb[(size_t)(c * KP + p) * Ncols + n0 + n4];
                asm volatile("cp.async.cg.shared.global [%0], [%1], 16;"
                             :: "r"(dst), "l"(src));
            }
        }
        asm volatile("cp.async.commit_group;");
    };

    cpasync_tile(0, 0);
    asm volatile("cp.async.wait_group 0;");
    __syncthreads();

    for (int c = 0; c < NTILES; c++) {
        const int cur = c & 1, nxt = cur ^ 1;
        if (c + 1 < NTILES) cpasync_tile(c + 1, nxt);

        const uint32_t* Ac = &smg[cur * BM * ASTR];
        const uint32_t* Bc = &Bb[cur * KP * BNP];
        #pragma unroll
        for (int kk = 0; kk < KKS; kk++) {
            uint32_t a0[MT], a1[MT], a2[MT], a3[MT];
            uint32_t b0[NT], b1[NT];
            #pragma unroll
            for (int mt = 0; mt < MT; mt++) {
                int r0 = wm + mt * 16 + g;
                const uint32_t* ar0 = Ac + r0 * ASTR;
                const uint32_t* ar1 = ar0 + 8 * ASTR;
                a0[mt] = ar0[kk * 8 + tig];
                a2[mt] = ar0[kk * 8 + 4 + tig];
                a1[mt] = ar1[kk * 8 + tig];
                a3[mt] = ar1[kk * 8 + 4 + tig];
            }
            #pragma unroll
            for (int nt = 0; nt < NT; nt++) {
                int cb = wn + nt * 8 + g;
                b0[nt] = Bc[(kk * 8 + tig) * BNP + cb];
                b1[nt] = Bc[(kk * 8 + 4 + tig) * BNP + cb];
            }
            #pragma unroll
            for (int mt = 0; mt < MT; mt++)
                #pragma unroll
                for (int nt = 0; nt < NT; nt++)
                    mma_bf16(acc[mt][nt], a0[mt], a1[mt], a2[mt], a3[mt],
                             b0[nt], b1[nt]);
        }

        if (c + 1 < NTILES) asm volatile("cp.async.wait_group 0;");
        __syncthreads();
    }

    // epilogue: v = d_i * (acc + packedZ_i) + bias (+leaky)
    const int comp = g & 1;
    const int NW = Ncols >> 1;
    #pragma unroll
    for (int mt = 0; mt < MT; mt++) {
        int r0 = m0 + wm + mt * 16 + g;
        int r1 = r0 + 8;
        float d0 = dz[r0], d1 = dz[r1];
        #pragma unroll
        for (int nt = 0; nt < NT; nt++) {
            int c = n0 + wn + nt * 8 + tig * 2;
            uint2 w0 = *(const uint2*)&zb[(size_t)(r0 >> 1) * Ncols + c];
            uint2 w1v = *(const uint2*)&zb[(size_t)(r1 >> 1) * Ncols + c];
            float bc0 = bias[c], bc1 = bias[c + 1];
            float v00 = d0 * (acc[mt][nt][0] + bf16_get(w0.x, comp)) + bc0;
            float v01 = d0 * (acc[mt][nt][1] + bf16_get(w0.y, comp)) + bc1;
            float v10 = d1 * (acc[mt][nt][2] + bf16_get(w1v.x, comp)) + bc0;
            float v11 = d1 * (acc[mt][nt][3] + bf16_get(w1v.y, comp)) + bc1;
            if (ACT) {
                v00 = (v00 >= 0.f) ? v00 : 0.2f * v00;
                v01 = (v01 >= 0.f) ? v01 : 0.2f * v01;
                v10 = (v10 >= 0.f) ? v10 : 0.2f * v10;
                v11 = (v11 >= 0.f) ? v11 : 0.2f * v11;
            }
            if (OUTBF) {
                Hout16[(size_t)z * NN * NW + (size_t)r0 * NW + (c >> 1)] = pack_bf16(v00, v01);
                Hout16[(size_t)z * NN * NW + (size_t)r1 * NW + (c >> 1)] = pack_bf16(v10, v11);
            } else {
                float* C = Cbase + (size_t)z * NN * Ncols;
                *(float2*)&C[(size_t)r0 * Ncols + c] = make_float2(v00, v01);
                *(float2*)&C[(size_t)r1 * Ncols + c] = make_float2(v10, v11);
            }
        }
    }
}

#define GCN_SMEM(BM, BN) ((2 * (BM) * 36 + 2 * 32 * BNP_OF(BN)) * 4)

// ---------------- plain resident GEMM: zb16 = packed d∘(Hb16 @ W) -------------
// Entire K resident. BM=64 for occupancy (MT=1, ~60 regs, 4 CTAs/SM).
template<int K, int BN, int BM, int WGM, int WGN>
__global__ void __launch_bounds__(WGM*WGN*32, 4)
plain_res_kernel(const uint32_t* __restrict__ Hb,
                 const float* __restrict__ W0,
                 const float* __restrict__ W1,
                 const float* __restrict__ dbase,
                 uint32_t* __restrict__ Zb)
{
    constexpr int KW = K / 2;
    constexpr int KKS = K / 16;
    constexpr int ASTR = KW + 4;
    constexpr int BNP = BNP_OF(BN);
    constexpr int WM = BM / WGM, WN = BN / WGN;
    constexpr int MT = WM / 16, NT = WN / 8;
    constexpr int NTHREADS = WGM * WGN * 32;
    constexpr int A_CH = BM * (KW / 4) / NTHREADS;
    constexpr int B_TOTP = KW * BN;

    extern __shared__ uint32_t psm[];
    uint32_t* As = psm;
    uint32_t* Bh = psm + BM * ASTR;

    const int z = blockIdx.z;   // s
    const uint32_t* A = Hb + (size_t)z * BB * NN * KW;
    const float* W = z ? W1 : W0;
    const float* d_s = dbase + (size_t)z * BB * NN;
    const size_t zoff = (size_t)z * BB * (NN / 2);

    const int m0 = blockIdx.x * BM;
    const int tid = threadIdx.x;
    const int w = tid >> 5, lane = tid & 31;
    const int g = lane >> 2, tig = lane & 3;
    const int wm = (w / WGN) * WM;
    const int wn = (w % WGN) * WN;

    #pragma unroll
    for (int i = 0; i < A_CH; i++) {
        int idx = tid + i * NTHREADS;
        int r = idx / (KW / 4), q = idx % (KW / 4);
        uint32_t dst = smem_u32(&As[r * ASTR + q * 4]);
        const uint32_t* src = &A[(size_t)(m0 + r) * KW + q * 4];
        asm volatile("cp.async.cg.shared.global [%0], [%1], 16;"
                     :: "r"(dst), "l"(src));
    }
    asm volatile("cp.async.commit_group;");
    #pragma unroll
    for (int i = 0; i < (B_TOTP + NTHREADS - 1) / NTHREADS; i++) {
        int e = tid + i * NTHREADS;
        if (B_TOTP % NTHREADS == 0 || e < B_TOTP) {
            int p = e / BN, n = e % BN;
            float f0 = W[(size_t)(2 * p) * BN + n];
            float f1 = W[(size_t)(2 * p + 1) * BN + n];
            Bh[p * BNP + n] = pack_bf16(f0, f1);
        }
    }
    asm volatile("cp.async.wait_group 0;");
    __syncthreads();

    float acc[MT][NT][4] = {};
    #pragma unroll
    for (int kk = 0; kk < KKS; kk++) {
        uint32_t a0[MT], a1[MT], a2[MT], a3[MT];
        uint32_t b0[NT], b1[NT];
        #pragma unroll
        for (int mt = 0; mt < MT; mt++) {
            int r0 = wm + mt * 16 + g;
            const uint32_t* ar0 = As + r0 * ASTR;
            const uint32_t* ar1 = ar0 + 8 * ASTR;
            a0[mt] = ar0[kk * 8 + tig];
            a2[mt] = ar0[kk * 8 + 4 + tig];
            a1[mt] = ar1[kk * 8 + tig];
            a3[mt] = ar1[kk * 8 + 4 + tig];
        }
        #pragma unroll
        for (int nt = 0; nt < NT; nt++) {
            int cb = wn + nt * 8 + g;
            b0[nt] = Bh[(kk * 8 + tig) * BNP + cb];
            b1[nt] = Bh[(kk * 8 + 4 + tig) * BNP + cb];
        }
        #pragma unroll
        for (int mt = 0; mt < MT; mt++)
            #pragma unroll
            for (int nt = 0; nt < NT; nt++)
                mma_bf16(acc[mt][nt], a0[mt], a1[mt], a2[mt], a3[mt],
                         b0[nt], b1[nt]);
    }
    __syncthreads();

    // epilogue: route tile through smem, pair rows, scale by d, write packed bf16
    float* Ct = reinterpret_cast<float*>(psm);
    #pragma unroll
    for (int mt = 0; mt < MT; mt++) {
        int rr0 = wm + mt * 16 + g;
        #pragma unroll
        for (int nt = 0; nt < NT; nt++) {
            int n = wn + nt * 8 + tig * 2;
            Ct[rr0 * (BN + 1) + n]       = acc[mt][nt][0];
            Ct[rr0 * (BN + 1) + n + 1]   = acc[mt][nt][1];
            Ct[(rr0 + 8) * (BN + 1) + n]     = acc[mt][nt][2];
            Ct[(rr0 + 8) * (BN + 1) + n + 1] = acc[mt][nt][3];
        }
    }
    __syncthreads();
    for (int e = tid; e < BM / 2 * BN; e += NTHREADS) {
        int pr = e / BN, n = e % BN;
        float f0 = Ct[(2 * pr) * (BN + 1) + n];
        float f1 = Ct[(2 * pr + 1) * (BN + 1) + n];
        int gr = m0 + 2 * pr;
        Zb[(zoff + (gr >> 1)) * BN + n] = pack_bf16(d_s[gr] * f0, d_s[gr + 1] * f1);
    }
}

#define PLAIN_SMW(K, BN, BM) \
    ((((BM) * ((K)/2 + 4) + ((K)/2) * BNP_OF(BN)) > ((BM) * ((BN)+1))) ? \
     ((BM) * ((K)/2 + 4) + ((K)/2) * BNP_OF(BN)) : ((BM) * ((BN)+1)))
#define PLAIN_SMEM(K, BN, BM) (PLAIN_SMW(K, BN, BM) * 4)

// ---------------- dynamic head params (conv3 = Hb16, stride 16 words) ---------
__global__ void dcl_params_kernel(const int* __restrict__ task,
                                  const float* __restrict__ wc,
                                  const uint32_t* __restrict__ H3b,
                                  float* __restrict__ wb) {
    int z = blockIdx.x;
    int b = z & 63;
    const uint32_t* conv3 = H3b + (size_t)z * NN * (H3 / 2);
    __shared__ float partial[256];
    __shared__ float xc[CDIM];
    int tid = threadIdx.x;
    int col = tid & 31, g = tid >> 5;
    int wofs = col >> 1, comp = col & 1;
    float p = 0.f;
    for (int r = g; r < NN; r += 8)
        p += bf16_get(conv3[(size_t)r * (H3 / 2) + wofs], comp);
    partial[tid] = p;
    __syncthreads();
    if (tid < H3) {
        float sum = 0.f;
        #pragma unroll
        for (int gg = 0; gg < 8; gg++) sum += partial[gg * 32 + tid];
        xc[tid] = sum * (1.0f / (float)NN);
    }
    if (tid >= H3 && tid < CDIM) {
        xc[tid] = (task[b] == tid - H3) ? 1.f : 0.f;
    }
    __syncthreads();
    if (tid < PDIM) {
        float acc = 0.f;
        #pragma unroll
        for (int c = 0; c < CDIM; c++) acc += wc[tid * CDIM + c] * xc[c];
        wb[(size_t)z * PDIM + tid] = acc;
    }
}

// ---------------- cc kernel: logits + interleave scatter --------------------
__global__ void cc_kernel(const float* __restrict__ H4b,
                          const float* __restrict__ wb,
                          float* __restrict__ cc) {
    int z = blockIdx.x;
    int q = z >> 6, b = z & 63;
    __shared__ float flat[NN * OUTD];
    __shared__ float wm[64];
    __shared__ float bv[8];
    int tid = threadIdx.x;
    const float4* src4 = (const float4*)(H4b + (size_t)z * NN * OUTD);
    float4* dst4 = (float4*)flat;
    for (int i = tid; i < NN * OUTD / 4; i += 256) dst4[i] = src4[i];
    if (tid < 64) wm[tid] = wb[(size_t)z * PDIM + tid];
    if (tid < 8)  bv[tid] = wb[(size_t)z * PDIM + 64 + tid];
    __syncthreads();
    for (int f = tid; f < NN * OUTD; f += 256) {
        int r = f >> 9, c = f & 511;
        float v = bv[r];
        #pragma unroll
        for (int i = 0; i < 8; i++) v += wm[r * 8 + i] * flat[i * NN + c];
        int n = f >> 3, o = f & 7;
        int scc = n >> 8;
        int n2 = ((n & 255) << 1) | q;
        cc[(((size_t)(b * 2 + scc) * NN + n2) << 3) + o] = v;
    }
}

// ---------------- final: out = softplus(-(cc @ cc^T)) -----------------------
__global__ void final_kernel(const float* __restrict__ cc, float* __restrict__ out) {
    int zz = blockIdx.z;
    __shared__ float Msm[NN * OUTD];
    int tid = threadIdx.y * 16 + threadIdx.x;
    const float4* src = (const float4*)(cc + (size_t)zz * NN * OUTD);
    float4* dst = (float4*)Msm;
    for (int i = tid; i < NN * OUTD / 4; i += 256) dst[i] = src[i];
    __syncthreads();
    int i0 = blockIdx.y * 64 + threadIdx.y * 4;
    int j0 = blockIdx.x * 64 + threadIdx.x * 4;
    float ai[4][8], aj[4][8];
    #pragma unroll
    for (int m = 0; m < 4; m++)
        #pragma unroll
        for (int o = 0; o < 8; o++) ai[m][o] = Msm[(i0 + m) * 8 + o];
    #pragma unroll
    for (int n = 0; n < 4; n++)
        #pragma unroll
        for (int o = 0; o < 8; o++) aj[n][o] = Msm[(j0 + n) * 8 + o];
    float* ob = out + (size_t)zz * NN * NN;
    #pragma unroll
    for (int m = 0; m < 4; m++) {
        float r[4];
        #pragma unroll
        for (int n = 0; n < 4; n++) {
            float x = 0.f;
            #pragma unroll
            for (int o = 0; o < 8; o++) x += ai[m][o] * aj[n][o];
            r[n] = __logf(1.0f + __expf(-fabsf(x))) + fmaxf(-x, 0.f);
        }
        *(float4*)(ob + (size_t)(i0 + m) * NN + j0) = make_float4(r[0], r[1], r[2], r[3]);
    }
}

// ---------------- host orchestration ----------------------------------------
extern "C" void kernel_launch(void* const* d_in, const int* in_sizes, int n_in,
                              void* d_out, int out_size) {
    const float* adj  = (const float*)d_in[0];
    const int*   task = (const int*)d_in[1];
    const float* w[2][4];
    const float* bia[2][4];
    int idx = 2;
    for (int s = 0; s < 2; s++)
        for (int l = 0; l < 4; l++) {
            w[s][l]   = (const float*)d_in[idx++];
            bia[s][l] = (const float*)d_in[idx++];
        }
    const float* wc = (const float*)d_in[18];
    float* out = (float*)d_out;

    float* base = nullptr;
    cudaGetSymbolAddress((void**)&base, g_scratch);
    uint32_t* adjb = nullptr;
    cudaGetSymbolAddress((void**)&adjb, g_adjb);
    uint32_t* zb16 = nullptr;
    cudaGetSymbolAddress((void**)&zb16, g_zb16);
    uint32_t* hb16 = nullptr;
    cudaGetSymbolAddress((void**)&hb16, g_hb16);
    float* p_d  = base + OFF_D;
    float* p_H4 = base + OFF_H4;
    float* p_WB = base + OFF_WB;
    float* p_CC = base + OFF_CC;

    // dynamic smem opt-ins (>48KB; idempotent)
    cudaFuncSetAttribute(
        (const void*)gcn_bf16_kernel<128, 128, 4, 2, true, 1>,
        cudaFuncAttributeMaxDynamicSharedMemorySize, GCN_SMEM(128, 128));
    cudaFuncSetAttribute(
        (const void*)gcn_bf16_kernel<128, 64, 4, 2, true, 1>,
        cudaFuncAttributeMaxDynamicSharedMemorySize, GCN_SMEM(128, 64));

    // 1) preprocess: degree factors + adj -> bf16
    prep_kernel<<<NZ * NN / 8, 256>>>(adj, p_d, adjb);

    // 2) layer 1: pack d∘w1, gcn (single n-pass, BN=128) -> Hb16 (H1, 64 w/row)
    pack1_kernel<<<NZ * (NN / 2) * H1 / 256, 256>>>(w[0][0], w[1][0], p_d, zb16);
    gcn_bf16_kernel<128, 128, 4, 2, true, 1>
        <<<dim3(4, 1, NZ), 256, GCN_SMEM(128, 128)>>>(
            adjb, zb16, p_d, bia[0][0], bia[1][0], nullptr, hb16, H1);

    // 3) layer 2: zb16 = packed d∘(H1b @ w2) ; gcn -> Hb16 (H2, 32 w/row)
    plain_res_kernel<128, 64, 64, 4, 2>
        <<<dim3(BB * NN / 64, 1, 2), 256, PLAIN_SMEM(128, 64, 64)>>>(
            hb16, w[0][1], w[1][1], p_d, zb16);
    gcn_bf16_kernel<128, 64, 4, 2, true, 1>
        <<<dim3(4, 1, NZ), 256, GCN_SMEM(128, 64)>>>(
            adjb, zb16, p_d, bia[0][1], bia[1][1], nullptr, hb16, H2);

    // 4) layer 3 -> Hb16 (H3, 16 w/row)
    plain_res_kernel<64, 32, 64, 4, 1>
        <<<dim3(BB * NN / 64, 1, 2), 128, PLAIN_SMEM(64, 32, 64)>>>(
            hb16, w[0][2], w[1][2], p_d, zb16);
    gcn_bf16_kernel<128, 32, 4, 1, true, 1>
        <<<dim3(4, 1, NZ), 128, GCN_SMEM(128, 32)>>>(
            adjb, zb16, p_d, bia[0][2], bia[1][2], nullptr, hb16, H3);

    // 5) layer 4 (no act) -> H4 fp32
    plain_res_kernel<32, 8, 64, 4, 1>
        <<<dim3(BB * NN / 64, 1, 2), 128, PLAIN_SMEM(32, 8, 64)>>>(
            hb16, w[0][3], w[1][3], p_d, zb16);
    gcn_bf16_kernel<128, 8, 4, 1, false, 0>
        <<<dim3(4, 1, NZ), 128, GCN_SMEM(128, 8)>>>(
            adjb, zb16, p_d, bia[0][3], bia[1][3], p_H4, nullptr, OUTD);

    // 6) dynamic head params (conv3 = Hb16)
    dcl_params_kernel<<<NZ, 256>>>(task, wc, hb16, p_WB);

    // 7) logits + interleave into cc
    cc_kernel<<<NZ, 256>>>(p_H4, p_WB, p_CC);

    // 8) final gram + softplus
    final_kernel<<<dim3(8, 8, NZ), dim3(16, 16)>>>(p_CC, out);

    (void)in_sizes; (void)n_in; (void)out_size;
}